// round 8
// baseline (speedup 1.0000x reference)
#include <cuda_runtime.h>
#include <cstdint>

#define SEQ    1024
#define DM     1024
#define NH     16
#define HD     64
#define BATCH  4
#define FFN_D  4096
#define NREL   64
#define BHN    (BATCH*NH)      // 64
#define ROWS   (BATCH*SEQ)     // 4096

// ---------------- scratch (device globals; no runtime allocation) ----------
__device__ float g_q [BHN*SEQ*HD];            // 16 MB  [bh][s][64]
__device__ float g_k [BHN*SEQ*HD];            // 16 MB
__device__ float g_v [BHN*SEQ*HD];            // 16 MB
__device__ float g_qe[BHN*SEQ*NREL];          // 16 MB  [bh][s][64]
__device__ float g_sc[67108864];              // 256 MB [bh][q][k]; reused as FFN hidden (64 MB)
__device__ float g_ctx[ROWS*DM];              // 16 MB  [b*s][d]
__device__ float g_t  [ROWS*DM];              // 16 MB  pre-LN residual sums
__device__ float g_ffin[ROWS*DM];             // 16 MB  ff_in (kept for 2nd residual)

// ---------------- helpers ---------------------------------------------------
__device__ __forceinline__ int rc_of(int t4, int i) {
    return (i < 4) ? (t4 * 4 + i) : (64 + t4 * 4 + i - 4);
}

__device__ __forceinline__ float warpSum(float v) {
    #pragma unroll
    for (int o = 16; o; o >>= 1) v += __shfl_xor_sync(0xffffffffu, v, o);
    return v;
}
__device__ __forceinline__ float warpMax(float v) {
    #pragma unroll
    for (int o = 16; o; o >>= 1) v = fmaxf(v, __shfl_xor_sync(0xffffffffu, v, o));
    return v;
}

// 128x128 tile NN SGEMM body: A[M,K] row-major, B[K,N] row-major.
// 256 threads, 8x8 per thread (4+4 split), BK=16.
__device__ __forceinline__ void gemm128_nn(const float* __restrict__ A,
                                           const float* __restrict__ B,
                                           int K, int N, int m0, int n0,
                                           float (&acc)[8][8])
{
    __shared__ float As[16][132];   // padded: conflict-free transpose stores
    __shared__ float Bs[16][128];
    const int tid = threadIdx.x;
    const int tx  = tid & 15, ty = tid >> 4;
    const int ar  = tid >> 2,  ac = (tid & 3) * 4;    // A tile: 128 rows x 16 cols
    const int br  = tid >> 5,  bc = (tid & 31) * 4;   // B tile: 16 rows x 128 cols

    for (int k0 = 0; k0 < K; k0 += 16) {
        #pragma unroll
        for (int i = 0; i < 2; i++) {
            float4 va = *(const float4*)(A + (size_t)(m0 + ar + i*64) * K + k0 + ac);
            As[ac+0][ar+i*64] = va.x;
            As[ac+1][ar+i*64] = va.y;
            As[ac+2][ar+i*64] = va.z;
            As[ac+3][ar+i*64] = va.w;
        }
        #pragma unroll
        for (int i = 0; i < 2; i++) {
            *(float4*)&Bs[br + i*8][bc] =
                *(const float4*)(B + (size_t)(k0 + br + i*8) * N + n0 + bc);
        }
        __syncthreads();
        #pragma unroll
        for (int k = 0; k < 16; k++) {
            float4 a0 = *(const float4*)&As[k][ty*4];
            float4 a1 = *(const float4*)&As[k][64 + ty*4];
            float4 b0 = *(const float4*)&Bs[k][tx*4];
            float4 b1 = *(const float4*)&Bs[k][64 + tx*4];
            float af[8] = {a0.x,a0.y,a0.z,a0.w,a1.x,a1.y,a1.z,a1.w};
            float bf[8] = {b0.x,b0.y,b0.z,b0.w,b1.x,b1.y,b1.z,b1.w};
            #pragma unroll
            for (int i = 0; i < 8; i++)
                #pragma unroll
                for (int j = 0; j < 8; j++)
                    acc[i][j] = fmaf(af[i], bf[j], acc[i][j]);
        }
        __syncthreads();
    }
}

// ---------------- QKV projection (fused over blockIdx.z) -------------------
// out[b,h,s,d] = (x @ W + bias)[b*S+s, h*64+d]
__global__ void __launch_bounds__(256, 2)
proj_kernel(const float* __restrict__ x,
            const float* __restrict__ Wq, const float* __restrict__ Wk, const float* __restrict__ Wv,
            const float* __restrict__ bq, const float* __restrict__ bk, const float* __restrict__ bv)
{
    const float* B; const float* bias; float* O;
    if      (blockIdx.z == 0) { B = Wq; bias = bq; O = g_q; }
    else if (blockIdx.z == 1) { B = Wk; bias = bk; O = g_k; }
    else                      { B = Wv; bias = bv; O = g_v; }

    float acc[8][8] = {};
    const int m0 = blockIdx.y * 128, n0 = blockIdx.x * 128;
    gemm128_nn(x, B, DM, DM, m0, n0, acc);

    const int tx = threadIdx.x & 15, ty = threadIdx.x >> 4;
    #pragma unroll
    for (int i = 0; i < 8; i++) {
        int row = m0 + rc_of(ty, i);
        int b = row >> 10, s = row & 1023;
        #pragma unroll
        for (int j = 0; j < 8; j++) {
            int col = n0 + rc_of(tx, j);
            int h = col >> 6, d = col & 63;
            O[((size_t)(b*NH + h) * SEQ + s) * HD + d] = acc[i][j] + bias[col];
        }
    }
}

// ---------------- generic GEMM + epilogue -----------------------------------
// EPI==2: relu(A@B + bias); EPI==3: A@B + bias + R  (row-major C[M,N])
template<int EPI>
__global__ void __launch_bounds__(256, 2)
sgemm_epi(const float* __restrict__ A, const float* __restrict__ B,
          const float* __restrict__ bias, const float* __restrict__ R,
          float* __restrict__ C, int K, int N)
{
    float acc[8][8] = {};
    const int m0 = blockIdx.y * 128, n0 = blockIdx.x * 128;
    gemm128_nn(A, B, K, N, m0, n0, acc);

    const int tx = threadIdx.x & 15, ty = threadIdx.x >> 4;
    #pragma unroll
    for (int i = 0; i < 8; i++) {
        int row = m0 + rc_of(ty, i);
        #pragma unroll
        for (int j = 0; j < 8; j++) {
            int col = n0 + rc_of(tx, j);
            float v = acc[i][j] + bias[col];
            if (EPI == 2) v = fmaxf(v, 0.0f);
            if (EPI == 3) v += R[(size_t)row * N + col];
            C[(size_t)row * N + col] = v;
        }
    }
}

// ---------------- qE = Q @ Ek^T  ([BH*S,64] x [64,64]) ----------------------
__global__ void __launch_bounds__(256)
qe_kernel(const float* __restrict__ Ek)
{
    __shared__ float sQ [64][65];
    __shared__ float sEk[64][65];
    const int tid = threadIdx.x;
    const size_t row0 = (size_t)blockIdx.x * 64;

    for (int i = tid; i < 64*64; i += 256) {
        sQ [i >> 6][i & 63] = g_q[row0 * 64 + i];
        sEk[i >> 6][i & 63] = Ek[i];
    }
    __syncthreads();

    const int r  = tid >> 2;
    const int nb = (tid & 3) * 16;
    float acc[16] = {};
    #pragma unroll
    for (int d = 0; d < 64; d++) {
        float qv = sQ[r][d];
        #pragma unroll
        for (int j = 0; j < 16; j++)
            acc[j] = fmaf(qv, sEk[nb + j][d], acc[j]);
    }
    #pragma unroll
    for (int j = 0; j < 16; j++)
        g_qe[(row0 + r) * 64 + nb + j] = acc[j];
}

// ---------------- scores: batched TN GEMM + rel gathers + scale -------------
// S[bh,q,k] = (Q[bh,q,:]·K[bh,k,:] + qE[bh,q,rid[q,k]] + Eb[rid[q,k],h]) / 8
__global__ void __launch_bounds__(256, 2)
scores_kernel(const float* __restrict__ Eb, const int* __restrict__ rid)
{
    __shared__ float As[16][132];
    __shared__ float Bs[16][132];
    const int tid = threadIdx.x;
    const int bh  = blockIdx.z;
    const int m0  = blockIdx.y * 128, n0 = blockIdx.x * 128;
    const float* A = g_q + (size_t)bh * SEQ * HD;
    const float* B = g_k + (size_t)bh * SEQ * HD;
    const int tx = tid & 15, ty = tid >> 4;
    const int lr = tid >> 2, lc = (tid & 3) * 4;

    float acc[8][8] = {};
    for (int k0 = 0; k0 < HD; k0 += 16) {
        #pragma unroll
        for (int i = 0; i < 2; i++) {
            float4 va = *(const float4*)(A + (size_t)(m0 + lr + i*64) * HD + k0 + lc);
            As[lc+0][lr+i*64] = va.x; As[lc+1][lr+i*64] = va.y;
            As[lc+2][lr+i*64] = va.z; As[lc+3][lr+i*64] = va.w;
            float4 vb = *(const float4*)(B + (size_t)(n0 + lr + i*64) * HD + k0 + lc);
            Bs[lc+0][lr+i*64] = vb.x; Bs[lc+1][lr+i*64] = vb.y;
            Bs[lc+2][lr+i*64] = vb.z; Bs[lc+3][lr+i*64] = vb.w;
        }
        __syncthreads();
        #pragma unroll
        for (int k = 0; k < 16; k++) {
            float4 a0 = *(const float4*)&As[k][ty*4];
            float4 a1 = *(const float4*)&As[k][64 + ty*4];
            float4 b0 = *(const float4*)&Bs[k][tx*4];
            float4 b1 = *(const float4*)&Bs[k][64 + tx*4];
            float af[8] = {a0.x,a0.y,a0.z,a0.w,a1.x,a1.y,a1.z,a1.w};
            float bf[8] = {b0.x,b0.y,b0.z,b0.w,b1.x,b1.y,b1.z,b1.w};
            #pragma unroll
            for (int i = 0; i < 8; i++)
                #pragma unroll
                for (int j = 0; j < 8; j++)
                    acc[i][j] = fmaf(af[i], bf[j], acc[i][j]);
        }
        __syncthreads();
    }

    const int h = bh & 15;
    const float* qeb = g_qe + (size_t)bh * SEQ * NREL;
    #pragma unroll
    for (int i = 0; i < 8; i++) {
        int row = m0 + rc_of(ty, i);
        size_t so = ((size_t)bh * SEQ + row) * SEQ;
        #pragma unroll
        for (int j = 0; j < 8; j++) {
            int col = n0 + rc_of(tx, j);
            int rd = rid[row * SEQ + col];
            g_sc[so + col] = (acc[i][j] + qeb[(size_t)row * NREL + rd]
                              + Eb[rd * NH + h]) * 0.125f;
        }
    }
}

// ---------------- row softmax (width 1024, 256 threads/row) ------------------
__global__ void __launch_bounds__(256)
softmax_kernel()
{
    __shared__ float red[8];
    float4* p = (float4*)(g_sc + ((size_t)blockIdx.x << 10));
    const int tid = threadIdx.x;
    float4 v = p[tid];

    float m = fmaxf(fmaxf(v.x, v.y), fmaxf(v.z, v.w));
    m = warpMax(m);
    if ((tid & 31) == 0) red[tid >> 5] = m;
    __syncthreads();
    float M = red[0];
    #pragma unroll
    for (int i = 1; i < 8; i++) M = fmaxf(M, red[i]);
    __syncthreads();

    v.x = __expf(v.x - M); v.y = __expf(v.y - M);
    v.z = __expf(v.z - M); v.w = __expf(v.w - M);
    float s = v.x + v.y + v.z + v.w;
    s = warpSum(s);
    if ((tid & 31) == 0) red[tid >> 5] = s;
    __syncthreads();
    float S = 0.f;
    #pragma unroll
    for (int i = 0; i < 8; i++) S += red[i];
    float inv = __fdividef(1.0f, S);
    v.x *= inv; v.y *= inv; v.z *= inv; v.w *= inv;
    p[tid] = v;
}

// ---------------- ctx = attn @ V (batched NN, N=64), write merged layout -----
__global__ void __launch_bounds__(256, 2)
ctx_kernel()
{
    __shared__ float As[16][132];
    __shared__ float Bs[16][64];
    const int tid = threadIdx.x;
    const int bh  = blockIdx.y;
    const int m0  = blockIdx.x * 128;
    const float* A  = g_sc + (size_t)bh * SEQ * SEQ;
    const float* Bv = g_v  + (size_t)bh * SEQ * HD;
    const int tx = tid & 15, ty = tid >> 4;
    const int lr = tid >> 2, lc = (tid & 3) * 4;
    const int br = tid >> 4, bc = (tid & 15) * 4;

    float acc[8][4] = {};
    for (int k0 = 0; k0 < SEQ; k0 += 16) {
        #pragma unroll
        for (int i = 0; i < 2; i++) {
            float4 va = *(const float4*)(A + (size_t)(m0 + lr + i*64) * SEQ + k0 + lc);
            As[lc+0][lr+i*64] = va.x; As[lc+1][lr+i*64] = va.y;
            As[lc+2][lr+i*64] = va.z; As[lc+3][lr+i*64] = va.w;
        }
        *(float4*)&Bs[br][bc] = *(const float4*)(Bv + (size_t)(k0 + br) * HD + bc);
        __syncthreads();
        #pragma unroll
        for (int k = 0; k < 16; k++) {
            float4 a0 = *(const float4*)&As[k][ty*4];
            float4 a1 = *(const float4*)&As[k][64 + ty*4];
            float4 b  = *(const float4*)&Bs[k][tx*4];
            float af[8] = {a0.x,a0.y,a0.z,a0.w,a1.x,a1.y,a1.z,a1.w};
            float bf[4] = {b.x,b.y,b.z,b.w};
            #pragma unroll
            for (int i = 0; i < 8; i++)
                #pragma unroll
                for (int j = 0; j < 4; j++)
                    acc[i][j] = fmaf(af[i], bf[j], acc[i][j]);
        }
        __syncthreads();
    }

    const int b = bh >> 4, h = bh & 15;
    #pragma unroll
    for (int i = 0; i < 8; i++) {
        int row = m0 + rc_of(ty, i);
        float4 o = make_float4(acc[i][0], acc[i][1], acc[i][2], acc[i][3]);
        *(float4*)&g_ctx[(size_t)(b * SEQ + row) * DM + h * HD + tx * 4] = o;
    }
}

// ---------------- layernorm (width 1024, 256 threads/row) --------------------
__global__ void __launch_bounds__(256)
ln_kernel(const float* __restrict__ X, const float* __restrict__ g,
          const float* __restrict__ bb, float* __restrict__ Y)
{
    __shared__ float red[16];
    const int tid = threadIdx.x;
    const size_t off = (size_t)blockIdx.x << 10;
    float4 v = ((const float4*)(X + off))[tid];

    float s  = v.x + v.y + v.z + v.w;
    float s2 = v.x*v.x + v.y*v.y + v.z*v.z + v.w*v.w;
    s = warpSum(s); s2 = warpSum(s2);
    if ((tid & 31) == 0) { red[tid >> 5] = s; red[8 + (tid >> 5)] = s2; }
    __syncthreads();
    float S = 0.f, S2 = 0.f;
    #pragma unroll
    for (int i = 0; i < 8; i++) { S += red[i]; S2 += red[8 + i]; }
    float mu  = S * (1.0f / 1024.0f);
    float var = S2 * (1.0f / 1024.0f) - mu * mu;
    float rs  = rsqrtf(var + 1e-6f);

    float4 gv = ((const float4*)g)[tid];
    float4 bv = ((const float4*)bb)[tid];
    float4 o;
    o.x = (v.x - mu) * rs * gv.x + bv.x;
    o.y = (v.y - mu) * rs * gv.y + bv.y;
    o.z = (v.z - mu) * rs * gv.z + bv.z;
    o.w = (v.w - mu) * rs * gv.w + bv.w;
    ((float4*)(Y + off))[tid] = o;
}

// ---------------- launch -----------------------------------------------------
extern "C" void kernel_launch(void* const* d_in, const int* in_sizes, int n_in,
                              void* d_out, int out_size)
{
    const float* x   = (const float*)d_in[0];
    const int*   rid = (const int*)  d_in[1];
    const float* Wq  = (const float*)d_in[2];
    const float* bq  = (const float*)d_in[3];
    const float* Wk  = (const float*)d_in[4];
    const float* bk  = (const float*)d_in[5];
    const float* Wv  = (const float*)d_in[6];
    const float* bv  = (const float*)d_in[7];
    const float* Wo  = (const float*)d_in[8];
    const float* bo  = (const float*)d_in[9];
    const float* Ek  = (const float*)d_in[10];
    const float* Eb  = (const float*)d_in[11];
    const float* g1  = (const float*)d_in[12];
    const float* b1  = (const float*)d_in[13];
    const float* g2  = (const float*)d_in[14];
    const float* b2  = (const float*)d_in[15];
    const float* W1  = (const float*)d_in[16];
    const float* bf1 = (const float*)d_in[17];
    const float* W2  = (const float*)d_in[18];
    const float* bf2 = (const float*)d_in[19];
    float* out = (float*)d_out;

    float *p_ctx, *p_t, *p_ffin, *p_sc;
    cudaGetSymbolAddress((void**)&p_ctx,  g_ctx);
    cudaGetSymbolAddress((void**)&p_t,    g_t);
    cudaGetSymbolAddress((void**)&p_ffin, g_ffin);
    cudaGetSymbolAddress((void**)&p_sc,   g_sc);
    float* p_h1 = p_sc;   // reuse scores buffer for FFN hidden (16M floats << 64M)

    const dim3 blk(256);

    // 1. QKV projections (fused launch; 768 blocks)
    proj_kernel<<<dim3(DM/128, ROWS/128, 3), blk>>>(x, Wq, Wk, Wv, bq, bk, bv);

    // 2. qE = Q @ Ek^T
    qe_kernel<<<BHN * SEQ / 64, blk>>>(Ek);

    // 3. scores (+rel-e gather, +rel-b, scale)
    scores_kernel<<<dim3(SEQ/128, SEQ/128, BHN), blk>>>(Eb, rid);

    // 4. softmax over keys
    softmax_kernel<<<BHN * SEQ, blk>>>();

    // 5. ctx = attn @ V  -> [B,S,D]
    ctx_kernel<<<dim3(SEQ/128, BHN), blk>>>();

    // 6. t = x + ctx @ Wo + bo
    sgemm_epi<3><<<dim3(DM/128, ROWS/128), blk>>>(p_ctx, Wo, bo, x, p_t, DM, DM);

    // 7. ff_in = LN1(t)
    ln_kernel<<<ROWS, blk>>>(p_t, g1, b1, p_ffin);

    // 8. h1 = relu(ff_in @ W1 + bf1)
    sgemm_epi<2><<<dim3(FFN_D/128, ROWS/128), blk>>>(p_ffin, W1, bf1, nullptr, p_h1, DM, FFN_D);

    // 9. t = ff_in + h1 @ W2 + bf2
    sgemm_epi<3><<<dim3(DM/128, ROWS/128), blk>>>(p_h1, W2, bf2, p_ffin, p_t, FFN_D, DM);

    // 10. out = LN2(t)
    ln_kernel<<<ROWS, blk>>>(p_t, g2, b2, out);
}

// round 9
// speedup vs baseline: 1.9975x; 1.9975x over previous
#include <cuda_runtime.h>
#include <cstdint>

#define SEQ    1024
#define DM     1024
#define NH     16
#define HD     64
#define BATCH  4
#define FFN_D  4096
#define NREL   64
#define BHN    (BATCH*NH)      // 64
#define ROWS   (BATCH*SEQ)     // 4096

// ---------------- scratch (device globals; no runtime allocation) ----------
__device__ float g_q [BHN*SEQ*HD];            // 16 MB  [bh][s][64]
__device__ float g_k [BHN*SEQ*HD];            // 16 MB
__device__ float g_v [BHN*SEQ*HD];            // 16 MB
__device__ float g_qe[BHN*SEQ*NREL];          // 16 MB  [bh][s][64]
__device__ float g_sc[67108864];              // 256 MB [bh][q][k]; reused as FFN hidden
__device__ float g_ctx[ROWS*DM];              // 16 MB
__device__ float g_t  [ROWS*DM];              // 16 MB
__device__ float g_ffin[ROWS*DM];             // 16 MB

// ---------------- helpers ---------------------------------------------------
__device__ __forceinline__ float warpSum(float v) {
    #pragma unroll
    for (int o = 16; o; o >>= 1) v += __shfl_xor_sync(0xffffffffu, v, o);
    return v;
}
__device__ __forceinline__ float warpMax(float v) {
    #pragma unroll
    for (int o = 16; o; o >>= 1) v = fmaxf(v, __shfl_xor_sync(0xffffffffu, v, o));
    return v;
}

// round-to-nearest f32 -> tf32 (kept in a float slot, low mantissa zeroed)
__device__ __forceinline__ float f2tf(float f) {
    uint32_t u;
    asm("cvt.rna.tf32.f32 %0, %1;" : "=r"(u) : "f"(f));
    return __uint_as_float(u);
}
__device__ __forceinline__ float4 f2tf4(float4 v) {
    v.x = f2tf(v.x); v.y = f2tf(v.y); v.z = f2tf(v.z); v.w = f2tf(v.w);
    return v;
}

// one m16n8k8 tf32 mma, D += A*B
__device__ __forceinline__ void mma8(float* d, const uint32_t* a, const uint32_t* b) {
    asm volatile(
        "mma.sync.aligned.m16n8k8.row.col.f32.tf32.tf32.f32 "
        "{%0,%1,%2,%3}, {%4,%5,%6,%7}, {%8,%9}, {%0,%1,%2,%3};\n"
        : "+f"(d[0]), "+f"(d[1]), "+f"(d[2]), "+f"(d[3])
        : "r"(a[0]), "r"(a[1]), "r"(a[2]), "r"(a[3]), "r"(b[0]), "r"(b[1]));
}

// ============================================================================
// Core 128x128 tf32 GEMM body. A[M,K], B[K,N] row-major, BK=32, 8 warps 2x4.
// Warp tile 64x32 -> acc[4 m-tiles][4 n-tiles][4].
// As[128][36]: frag-load bank = (4*gid + tig) % 32, conflict-free.
// Bs[32][136]: frag-load bank = (8*tig + gid) % 32, conflict-free.
// ============================================================================
#define MM_PROLOG()                                                         \
    const int tid  = threadIdx.x;                                           \
    const int warp = tid >> 5, lane = tid & 31;                             \
    const int wm   = (warp >> 2) * 64, wn = (warp & 3) * 32;                \
    const int gid  = lane >> 2, tig = lane & 3;

#define MM_COMPUTE_STEP(ACC)                                                \
    _Pragma("unroll")                                                       \
    for (int ks = 0; ks < 4; ks++) {                                        \
        const int kk = ks * 8;                                              \
        uint32_t af[4][4], bf[4][2];                                        \
        _Pragma("unroll")                                                   \
        for (int mi = 0; mi < 4; mi++) {                                    \
            const float* p = &As[wm + mi*16 + gid][kk + tig];               \
            af[mi][0] = __float_as_uint(p[0]);                              \
            af[mi][1] = __float_as_uint(p[8*36]);                           \
            af[mi][2] = __float_as_uint(p[4]);                              \
            af[mi][3] = __float_as_uint(p[8*36 + 4]);                       \
        }                                                                   \
        _Pragma("unroll")                                                   \
        for (int ni = 0; ni < 4; ni++) {                                    \
            bf[ni][0] = __float_as_uint(Bs[kk + tig    ][wn + ni*8 + gid]); \
            bf[ni][1] = __float_as_uint(Bs[kk + tig + 4][wn + ni*8 + gid]); \
        }                                                                   \
        _Pragma("unroll")                                                   \
        for (int mi = 0; mi < 4; mi++)                                      \
            _Pragma("unroll")                                               \
            for (int ni = 0; ni < 4; ni++)                                  \
                mma8(ACC[mi][ni], af[mi], bf[ni]);                          \
    }

// ---------------- generic GEMM + epilogues ----------------------------------
// EPI==2: relu(A@B + bias); EPI==3: A@B + bias + R
template<int EPI>
__global__ void __launch_bounds__(256)
mm_tf32(const float* __restrict__ A, const float* __restrict__ B,
        const float* __restrict__ bias, const float* __restrict__ R,
        float* __restrict__ C, int K, int N)
{
    __shared__ float As[128][36];
    __shared__ float Bs[32][136];
    MM_PROLOG();
    const int m0 = blockIdx.y * 128, n0 = blockIdx.x * 128;

    float acc[4][4][4] = {};
    for (int k0 = 0; k0 < K; k0 += 32) {
        #pragma unroll
        for (int i = 0; i < 4; i++) {
            int idx = i * 256 + tid;
            int ar = idx >> 3, ac = (idx & 7) << 2;
            *(float4*)&As[ar][ac] =
                f2tf4(*(const float4*)(A + (size_t)(m0 + ar) * K + k0 + ac));
            int br = idx >> 5, bc = (idx & 31) << 2;
            *(float4*)&Bs[br][bc] =
                f2tf4(*(const float4*)(B + (size_t)(k0 + br) * N + n0 + bc));
        }
        __syncthreads();
        MM_COMPUTE_STEP(acc);
        __syncthreads();
    }

    #pragma unroll
    for (int mi = 0; mi < 4; mi++) {
        int r0 = m0 + wm + mi * 16 + gid;
        #pragma unroll
        for (int ni = 0; ni < 4; ni++) {
            int c = n0 + wn + ni * 8 + tig * 2;
            float b0 = bias[c], b1 = bias[c + 1];
            float v00 = acc[mi][ni][0] + b0, v01 = acc[mi][ni][1] + b1;
            float v10 = acc[mi][ni][2] + b0, v11 = acc[mi][ni][3] + b1;
            if (EPI == 2) {
                v00 = fmaxf(v00, 0.f); v01 = fmaxf(v01, 0.f);
                v10 = fmaxf(v10, 0.f); v11 = fmaxf(v11, 0.f);
            }
            if (EPI == 3) {
                float2 ra = *(const float2*)(R + (size_t)r0 * N + c);
                float2 rb = *(const float2*)(R + (size_t)(r0 + 8) * N + c);
                v00 += ra.x; v01 += ra.y; v10 += rb.x; v11 += rb.y;
            }
            *(float2*)(C + (size_t)r0 * N + c)       = make_float2(v00, v01);
            *(float2*)(C + (size_t)(r0 + 8) * N + c) = make_float2(v10, v11);
        }
    }
}

// ---------------- QKV projection (fused over blockIdx.z), split-head out ----
__global__ void __launch_bounds__(256)
proj_tf32(const float* __restrict__ x,
          const float* __restrict__ Wq, const float* __restrict__ Wk, const float* __restrict__ Wv,
          const float* __restrict__ bq, const float* __restrict__ bk, const float* __restrict__ bv)
{
    const float* B; const float* bias; float* O;
    if      (blockIdx.z == 0) { B = Wq; bias = bq; O = g_q; }
    else if (blockIdx.z == 1) { B = Wk; bias = bk; O = g_k; }
    else                      { B = Wv; bias = bv; O = g_v; }

    __shared__ float As[128][36];
    __shared__ float Bs[32][136];
    MM_PROLOG();
    const int m0 = blockIdx.y * 128, n0 = blockIdx.x * 128;

    float acc[4][4][4] = {};
    for (int k0 = 0; k0 < DM; k0 += 32) {
        #pragma unroll
        for (int i = 0; i < 4; i++) {
            int idx = i * 256 + tid;
            int ar = idx >> 3, ac = (idx & 7) << 2;
            *(float4*)&As[ar][ac] =
                f2tf4(*(const float4*)(x + (size_t)(m0 + ar) * DM + k0 + ac));
            int br = idx >> 5, bc = (idx & 31) << 2;
            *(float4*)&Bs[br][bc] =
                f2tf4(*(const float4*)(B + (size_t)(k0 + br) * DM + n0 + bc));
        }
        __syncthreads();
        MM_COMPUTE_STEP(acc);
        __syncthreads();
    }

    #pragma unroll
    for (int mi = 0; mi < 4; mi++) {
        int r0 = m0 + wm + mi * 16 + gid;
        #pragma unroll
        for (int ni = 0; ni < 4; ni++) {
            int c = n0 + wn + ni * 8 + tig * 2;
            int h = c >> 6, d = c & 63;
            float b0 = bias[c], b1 = bias[c + 1];
            #pragma unroll
            for (int rr = 0; rr < 2; rr++) {
                int row = r0 + rr * 8;
                int b = row >> 10, s = row & 1023;
                float2 o = make_float2(acc[mi][ni][rr*2+0] + b0,
                                       acc[mi][ni][rr*2+1] + b1);
                *(float2*)&O[((size_t)(b*NH + h) * SEQ + s) * HD + d] = o;
            }
        }
    }
}

// ---------------- qE = Q @ Ek^T  ([BH*S,64] x [64,64]) ----------------------
__global__ void __launch_bounds__(256)
qe_kernel(const float* __restrict__ Ek)
{
    __shared__ float sQ [64][65];
    __shared__ float sEk[64][65];
    const int tid = threadIdx.x;
    const size_t row0 = (size_t)blockIdx.x * 64;

    for (int i = tid; i < 64*64; i += 256) {
        sQ [i >> 6][i & 63] = g_q[row0 * 64 + i];
        sEk[i >> 6][i & 63] = Ek[i];
    }
    __syncthreads();

    const int r  = tid >> 2;
    const int nb = (tid & 3) * 16;
    float acc[16] = {};
    #pragma unroll
    for (int d = 0; d < 64; d++) {
        float qv = sQ[r][d];
        #pragma unroll
        for (int j = 0; j < 16; j++)
            acc[j] = fmaf(qv, sEk[nb + j][d], acc[j]);
    }
    #pragma unroll
    for (int j = 0; j < 16; j++)
        g_qe[(row0 + r) * 64 + nb + j] = acc[j];
}

// ---------------- scores: batched TN GEMM + rel gathers + scale -------------
__global__ void __launch_bounds__(256)
scores_tf32(const float* __restrict__ Eb, const int* __restrict__ rid)
{
    __shared__ float As[128][36];
    __shared__ float Bs[32][136];
    MM_PROLOG();
    const int bh = blockIdx.z;
    const int m0 = blockIdx.y * 128, n0 = blockIdx.x * 128;
    const float* A  = g_q + (size_t)bh * SEQ * HD;
    const float* Bk = g_k + (size_t)bh * SEQ * HD;

    float acc[4][4][4] = {};
    for (int k0 = 0; k0 < HD; k0 += 32) {
        #pragma unroll
        for (int i = 0; i < 4; i++) {
            int idx = i * 256 + tid;
            int ar = idx >> 3, ac = (idx & 7) << 2;
            *(float4*)&As[ar][ac] =
                f2tf4(*(const float4*)(A + (size_t)(m0 + ar) * HD + k0 + ac));
            // B: transpose K rows (n) into Bs[k][n]
            float4 v = f2tf4(*(const float4*)(Bk + (size_t)(n0 + ar) * HD + k0 + ac));
            Bs[ac + 0][ar] = v.x; Bs[ac + 1][ar] = v.y;
            Bs[ac + 2][ar] = v.z; Bs[ac + 3][ar] = v.w;
        }
        __syncthreads();
        MM_COMPUTE_STEP(acc);
        __syncthreads();
    }

    const int h = bh & 15;
    const float* qeb = g_qe + (size_t)bh * SEQ * NREL;
    #pragma unroll
    for (int mi = 0; mi < 4; mi++) {
        int r0 = m0 + wm + mi * 16 + gid;
        #pragma unroll
        for (int ni = 0; ni < 4; ni++) {
            int c = n0 + wn + ni * 8 + tig * 2;
            #pragma unroll
            for (int rr = 0; rr < 2; rr++) {
                int row = r0 + rr * 8;
                size_t so = ((size_t)bh * SEQ + row) * SEQ;
                const float* qer = qeb + (size_t)row * NREL;
                int rd0 = rid[row * SEQ + c];
                int rd1 = rid[row * SEQ + c + 1];
                float2 o;
                o.x = (acc[mi][ni][rr*2+0] + qer[rd0] + Eb[rd0 * NH + h]) * 0.125f;
                o.y = (acc[mi][ni][rr*2+1] + qer[rd1] + Eb[rd1 * NH + h]) * 0.125f;
                *(float2*)&g_sc[so + c] = o;
            }
        }
    }
}

// ---------------- row softmax (width 1024, 256 threads/row) ------------------
__global__ void __launch_bounds__(256)
softmax_kernel()
{
    __shared__ float red[8];
    float4* p = (float4*)(g_sc + ((size_t)blockIdx.x << 10));
    const int tid = threadIdx.x;
    float4 v = p[tid];

    float m = fmaxf(fmaxf(v.x, v.y), fmaxf(v.z, v.w));
    m = warpMax(m);
    if ((tid & 31) == 0) red[tid >> 5] = m;
    __syncthreads();
    float M = red[0];
    #pragma unroll
    for (int i = 1; i < 8; i++) M = fmaxf(M, red[i]);
    __syncthreads();

    v.x = __expf(v.x - M); v.y = __expf(v.y - M);
    v.z = __expf(v.z - M); v.w = __expf(v.w - M);
    float s = v.x + v.y + v.z + v.w;
    s = warpSum(s);
    if ((tid & 31) == 0) red[tid >> 5] = s;
    __syncthreads();
    float S = 0.f;
    #pragma unroll
    for (int i = 0; i < 8; i++) S += red[i];
    float inv = __fdividef(1.0f, S);
    v.x *= inv; v.y *= inv; v.z *= inv; v.w *= inv;
    p[tid] = v;
}

// ---------------- ctx = attn @ V (128x64 tile), merged-layout output ---------
// 8 warps 4(M) x 2(N): warp tile 32x32 -> acc[2][4][4].
__global__ void __launch_bounds__(256)
ctx_tf32()
{
    __shared__ float As[128][36];
    __shared__ float Bs[32][72];   // stride 72: bank = (8*tig + gid) % 32, CF
    const int tid  = threadIdx.x;
    const int warp = tid >> 5, lane = tid & 31;
    const int wm   = (warp >> 1) * 32, wn = (warp & 1) * 32;
    const int gid  = lane >> 2, tig = lane & 3;
    const int bh   = blockIdx.y;
    const int m0   = blockIdx.x * 128;
    const float* A = g_sc + (size_t)bh * SEQ * SEQ;
    const float* V = g_v  + (size_t)bh * SEQ * HD;

    float acc[2][4][4] = {};
    for (int k0 = 0; k0 < SEQ; k0 += 32) {
        #pragma unroll
        for (int i = 0; i < 4; i++) {
            int idx = i * 256 + tid;
            int ar = idx >> 3, ac = (idx & 7) << 2;
            *(float4*)&As[ar][ac] =
                f2tf4(*(const float4*)(A + (size_t)(m0 + ar) * SEQ + k0 + ac));
        }
        #pragma unroll
        for (int i = 0; i < 2; i++) {
            int idx = i * 256 + tid;
            int br = idx >> 4, bc = (idx & 15) << 2;
            *(float4*)&Bs[br][bc] =
                f2tf4(*(const float4*)(V + (size_t)(k0 + br) * HD + bc));
        }
        __syncthreads();
        #pragma unroll
        for (int ks = 0; ks < 4; ks++) {
            const int kk = ks * 8;
            uint32_t af[2][4], bf[4][2];
            #pragma unroll
            for (int mi = 0; mi < 2; mi++) {
                const float* p = &As[wm + mi*16 + gid][kk + tig];
                af[mi][0] = __float_as_uint(p[0]);
                af[mi][1] = __float_as_uint(p[8*36]);
                af[mi][2] = __float_as_uint(p[4]);
                af[mi][3] = __float_as_uint(p[8*36 + 4]);
            }
            #pragma unroll
            for (int ni = 0; ni < 4; ni++) {
                bf[ni][0] = __float_as_uint(Bs[kk + tig    ][wn + ni*8 + gid]);
                bf[ni][1] = __float_as_uint(Bs[kk + tig + 4][wn + ni*8 + gid]);
            }
            #pragma unroll
            for (int mi = 0; mi < 2; mi++)
                #pragma unroll
                for (int ni = 0; ni < 4; ni++)
                    mma8(acc[mi][ni], af[mi], bf[ni]);
        }
        __syncthreads();
    }

    const int b = bh >> 4, h = bh & 15;
    #pragma unroll
    for (int mi = 0; mi < 2; mi++) {
        int r0 = m0 + wm + mi * 16 + gid;
        #pragma unroll
        for (int ni = 0; ni < 4; ni++) {
            int c = wn + ni * 8 + tig * 2;
            #pragma unroll
            for (int rr = 0; rr < 2; rr++) {
                int row = r0 + rr * 8;
                float2 o = make_float2(acc[mi][ni][rr*2+0], acc[mi][ni][rr*2+1]);
                *(float2*)&g_ctx[(size_t)(b * SEQ + row) * DM + h * HD + c] = o;
            }
        }
    }
}

// ---------------- layernorm (width 1024, 256 threads/row) --------------------
__global__ void __launch_bounds__(256)
ln_kernel(const float* __restrict__ X, const float* __restrict__ g,
          const float* __restrict__ bb, float* __restrict__ Y)
{
    __shared__ float red[16];
    const int tid = threadIdx.x;
    const size_t off = (size_t)blockIdx.x << 10;
    float4 v = ((const float4*)(X + off))[tid];

    float s  = v.x + v.y + v.z + v.w;
    float s2 = v.x*v.x + v.y*v.y + v.z*v.z + v.w*v.w;
    s = warpSum(s); s2 = warpSum(s2);
    if ((tid & 31) == 0) { red[tid >> 5] = s; red[8 + (tid >> 5)] = s2; }
    __syncthreads();
    float S = 0.f, S2 = 0.f;
    #pragma unroll
    for (int i = 0; i < 8; i++) { S += red[i]; S2 += red[8 + i]; }
    float mu  = S * (1.0f / 1024.0f);
    float var = S2 * (1.0f / 1024.0f) - mu * mu;
    float rs  = rsqrtf(var + 1e-6f);

    float4 gv = ((const float4*)g)[tid];
    float4 bv = ((const float4*)bb)[tid];
    float4 o;
    o.x = (v.x - mu) * rs * gv.x + bv.x;
    o.y = (v.y - mu) * rs * gv.y + bv.y;
    o.z = (v.z - mu) * rs * gv.z + bv.z;
    o.w = (v.w - mu) * rs * gv.w + bv.w;
    ((float4*)(Y + off))[tid] = o;
}

// ---------------- launch -----------------------------------------------------
extern "C" void kernel_launch(void* const* d_in, const int* in_sizes, int n_in,
                              void* d_out, int out_size)
{
    const float* x   = (const float*)d_in[0];
    const int*   rid = (const int*)  d_in[1];
    const float* Wq  = (const float*)d_in[2];
    const float* bq  = (const float*)d_in[3];
    const float* Wk  = (const float*)d_in[4];
    const float* bk  = (const float*)d_in[5];
    const float* Wv  = (const float*)d_in[6];
    const float* bv  = (const float*)d_in[7];
    const float* Wo  = (const float*)d_in[8];
    const float* bo  = (const float*)d_in[9];
    const float* Ek  = (const float*)d_in[10];
    const float* Eb  = (const float*)d_in[11];
    const float* g1  = (const float*)d_in[12];
    const float* b1  = (const float*)d_in[13];
    const float* g2  = (const float*)d_in[14];
    const float* b2  = (const float*)d_in[15];
    const float* W1  = (const float*)d_in[16];
    const float* bf1 = (const float*)d_in[17];
    const float* W2  = (const float*)d_in[18];
    const float* bf2 = (const float*)d_in[19];
    float* out = (float*)d_out;

    float *p_ctx, *p_t, *p_ffin, *p_sc;
    cudaGetSymbolAddress((void**)&p_ctx,  g_ctx);
    cudaGetSymbolAddress((void**)&p_t,    g_t);
    cudaGetSymbolAddress((void**)&p_ffin, g_ffin);
    cudaGetSymbolAddress((void**)&p_sc,   g_sc);
    float* p_h1 = p_sc;   // reuse scores buffer for FFN hidden

    const dim3 blk(256);

    // 1. QKV projections (tensor-core tf32)
    proj_tf32<<<dim3(DM/128, ROWS/128, 3), blk>>>(x, Wq, Wk, Wv, bq, bk, bv);

    // 2. qE = Q @ Ek^T
    qe_kernel<<<BHN * SEQ / 64, blk>>>(Ek);

    // 3. scores (+rel-e gather, +rel-b, scale)
    scores_tf32<<<dim3(SEQ/128, SEQ/128, BHN), blk>>>(Eb, rid);

    // 4. softmax over keys
    softmax_kernel<<<BHN * SEQ, blk>>>();

    // 5. ctx = attn @ V  -> [B,S,D]
    ctx_tf32<<<dim3(SEQ/128, BHN), blk>>>();

    // 6. t = x + ctx @ Wo + bo
    mm_tf32<3><<<dim3(DM/128, ROWS/128), blk>>>(p_ctx, Wo, bo, x, p_t, DM, DM);

    // 7. ff_in = LN1(t)
    ln_kernel<<<ROWS, blk>>>(p_t, g1, b1, p_ffin);

    // 8. h1 = relu(ff_in @ W1 + bf1)
    mm_tf32<2><<<dim3(FFN_D/128, ROWS/128), blk>>>(p_ffin, W1, bf1, nullptr, p_h1, DM, FFN_D);

    // 9. t = ff_in + h1 @ W2 + bf2
    mm_tf32<3><<<dim3(DM/128, ROWS/128), blk>>>(p_h1, W2, bf2, p_ffin, p_t, FFN_D, DM);

    // 10. out = LN2(t)
    ln_kernel<<<ROWS, blk>>>(p_t, g2, b2, out);
}

// round 10
// speedup vs baseline: 3.1763x; 1.5902x over previous
#include <cuda_runtime.h>
#include <cuda_fp16.h>
#include <cstdint>

#define SEQ    1024
#define DM     1024
#define NH     16
#define HD     64
#define BATCH  4
#define FFN_D  4096
#define NREL   64
#define BHN    (BATCH*NH)      // 64
#define ROWS   (BATCH*SEQ)     // 4096

// ---------------- scratch (device globals; no runtime allocation) ----------
__device__ __half g_qh  [BHN*SEQ*HD];        // 8 MB  [bh][s][d]
__device__ __half g_kh  [BHN*SEQ*HD];        // 8 MB  [bh][s][d]
__device__ __half g_vt  [BHN*HD*SEQ];        // 8 MB  [bh][d][s]  (transposed V)
__device__ float  g_sc  [BHN*SEQ*SEQ];       // 256 MB raw scores
__device__ __half g_sch [BHN*SEQ*SEQ];       // 128 MB softmax probs (half)
__device__ float  g_qe  [BHN*SEQ*NREL];      // 16 MB
__device__ __half g_ctxh[ROWS*DM];           // 8 MB
__device__ float  g_t   [ROWS*DM];           // 16 MB
__device__ float  g_ffin[ROWS*DM];           // 16 MB (residual for step 9)
__device__ __half g_ffinh[ROWS*DM];          // 8 MB
__device__ __half g_h1h [ROWS*FFN_D];        // 32 MB
__device__ __half g_wT  [4*DM*DM + 2*DM*FFN_D];  // 24 MB: WqT,WkT,WvT,WoT,W1T,W2T

// ---------------- helpers ---------------------------------------------------
__device__ __forceinline__ float warpSum(float v) {
    #pragma unroll
    for (int o = 16; o; o >>= 1) v += __shfl_xor_sync(0xffffffffu, v, o);
    return v;
}
__device__ __forceinline__ float warpMax(float v) {
    #pragma unroll
    for (int o = 16; o; o >>= 1) v = fmaxf(v, __shfl_xor_sync(0xffffffffu, v, o));
    return v;
}

__device__ __forceinline__ void cpa16(void* dst, const void* src) {
    uint32_t d = (uint32_t)__cvta_generic_to_shared(dst);
    asm volatile("cp.async.cg.shared.global [%0], [%1], 16;\n" :: "r"(d), "l"(src));
}
#define CPA_COMMIT() asm volatile("cp.async.commit_group;\n" ::: "memory")
#define CPA_WAIT0()  asm volatile("cp.async.wait_group 0;\n" ::: "memory")

// one m16n8k16 f16 mma, f32 accum
__device__ __forceinline__ void mma16(float* d, const uint32_t* a, const uint32_t* b) {
    asm volatile(
        "mma.sync.aligned.m16n8k16.row.col.f32.f16.f16.f32 "
        "{%0,%1,%2,%3}, {%4,%5,%6,%7}, {%8,%9}, {%0,%1,%2,%3};\n"
        : "+f"(d[0]), "+f"(d[1]), "+f"(d[2]), "+f"(d[3])
        : "r"(a[0]), "r"(a[1]), "r"(a[2]), "r"(a[3]), "r"(b[0]), "r"(b[1]));
}

// Compute one BK=32 step from smem tiles As[M][40], Bs[N][40] (k-contiguous).
// Fragment LDS bank = 20*row + tig : conflict-free for stride 40 halves.
template<int MI, int NI>
__device__ __forceinline__ void hstep(const __half (*As)[40], const __half (*Bs)[40],
                                      int wm, int wn, int gid, int tig,
                                      float (&acc)[MI][NI][4])
{
    #pragma unroll
    for (int ks = 0; ks < 2; ks++) {
        const int kk = ks * 16;
        uint32_t af[MI][4], bf[NI][2];
        #pragma unroll
        for (int mi = 0; mi < MI; mi++) {
            const __half* p0 = &As[wm + mi*16 + gid    ][kk + 2*tig];
            const __half* p1 = &As[wm + mi*16 + gid + 8][kk + 2*tig];
            af[mi][0] = *(const uint32_t*)p0;
            af[mi][1] = *(const uint32_t*)p1;
            af[mi][2] = *(const uint32_t*)(p0 + 8);
            af[mi][3] = *(const uint32_t*)(p1 + 8);
        }
        #pragma unroll
        for (int ni = 0; ni < NI; ni++) {
            const __half* q = &Bs[wn + ni*8 + gid][kk + 2*tig];
            bf[ni][0] = *(const uint32_t*)q;
            bf[ni][1] = *(const uint32_t*)(q + 8);
        }
        #pragma unroll
        for (int mi = 0; mi < MI; mi++)
            #pragma unroll
            for (int ni = 0; ni < NI; ni++)
                mma16(acc[mi][ni], af[mi], bf[ni]);
    }
}

// async-load a 128row x 32half tile (row stride ldk halves in gmem)
__device__ __forceinline__ void load128(__half (*S)[40], const __half* G,
                                        size_t ldk, int k0, int tid)
{
    #pragma unroll
    for (int i = 0; i < 2; i++) {
        int idx = i * 256 + tid;
        int r = idx >> 2, s = (idx & 3) * 8;
        cpa16(&S[r][s], G + (size_t)r * ldk + k0 + s);
    }
}

// ---------------- weight transpose: f32 [K][N] -> half [N][K] ----------------
__global__ void __launch_bounds__(256)
wtrans_kernel(const float* __restrict__ S, __half* __restrict__ D, int K, int N)
{
    __shared__ float t[32][33];
    const int k0 = blockIdx.y * 32, n0 = blockIdx.x * 32;
    const int tx = threadIdx.x & 31, ty = threadIdx.x >> 5;
    #pragma unroll
    for (int i = 0; i < 32; i += 8)
        t[ty + i][tx] = S[(size_t)(k0 + ty + i) * N + n0 + tx];
    __syncthreads();
    #pragma unroll
    for (int i = 0; i < 32; i += 8)
        D[(size_t)(n0 + ty + i) * K + k0 + tx] = __float2half(t[tx][ty + i]);
}

// ---------------- QKV projection (half TN gemm, fused over blockIdx.z) -------
__global__ void __launch_bounds__(256)
proj_h(const __half* __restrict__ xh,
       const float* __restrict__ bq, const float* __restrict__ bk, const float* __restrict__ bv)
{
    __shared__ __half As[2][128][40];
    __shared__ __half Bs[2][128][40];
    const int tid = threadIdx.x, warp = tid >> 5, lane = tid & 31;
    const int wm = (warp >> 2) * 64, wn = (warp & 3) * 32;
    const int gid = lane >> 2, tig = lane & 3;
    const int z = blockIdx.z;
    const int m0 = blockIdx.y * 128, n0 = blockIdx.x * 128;
    const __half* Ag = xh + (size_t)m0 * DM;
    const __half* Bg = g_wT + (size_t)z * DM * DM + (size_t)n0 * DM;
    const float* bias = (z == 0) ? bq : (z == 1) ? bk : bv;

    load128(As[0], Ag, DM, 0, tid);
    load128(Bs[0], Bg, DM, 0, tid);
    CPA_COMMIT();

    float acc[4][4][4] = {};
    const int nt = DM >> 5;
    for (int t = 0; t < nt; t++) {
        CPA_WAIT0();
        __syncthreads();
        if (t + 1 < nt) {
            load128(As[(t+1)&1], Ag, DM, (t+1) << 5, tid);
            load128(Bs[(t+1)&1], Bg, DM, (t+1) << 5, tid);
            CPA_COMMIT();
        }
        hstep<4,4>(As[t&1], Bs[t&1], wm, wn, gid, tig, acc);
        __syncthreads();
    }

    #pragma unroll
    for (int mi = 0; mi < 4; mi++) {
        int r0 = m0 + wm + mi * 16 + gid;
        #pragma unroll
        for (int ni = 0; ni < 4; ni++) {
            int c = n0 + wn + ni * 8 + tig * 2;
            int h = c >> 6, d = c & 63;
            float b0 = bias[c], b1 = bias[c + 1];
            #pragma unroll
            for (int rr = 0; rr < 2; rr++) {
                int row = r0 + rr * 8;
                int b = row >> 10, s = row & 1023;
                float v0 = acc[mi][ni][rr*2+0] + b0;
                float v1 = acc[mi][ni][rr*2+1] + b1;
                if (z < 2) {
                    __half* O = (z == 0) ? g_qh : g_kh;
                    *(__half2*)&O[((size_t)(b*NH + h) * SEQ + s) * HD + d] =
                        __floats2half2_rn(v0, v1);
                } else {
                    size_t vb = (size_t)(b*NH + h) * HD;
                    g_vt[(vb + d    ) * SEQ + s] = __float2half(v0);
                    g_vt[(vb + d + 1) * SEQ + s] = __float2half(v1);
                }
            }
        }
    }
}

// ---------------- generic half TN GEMM + epilogues ---------------------------
// EPI==2: relu(A@Bt^T + bias) -> half C ;  EPI==3: A@Bt^T + bias + R -> float C
template<int EPI>
__global__ void __launch_bounds__(256)
hgemm(const __half* __restrict__ A, const __half* __restrict__ Bt,
      const float* __restrict__ bias, const float* __restrict__ R,
      void* __restrict__ Cout, int K, int N)
{
    __shared__ __half As[2][128][40];
    __shared__ __half Bs[2][128][40];
    const int tid = threadIdx.x, warp = tid >> 5, lane = tid & 31;
    const int wm = (warp >> 2) * 64, wn = (warp & 3) * 32;
    const int gid = lane >> 2, tig = lane & 3;
    const int m0 = blockIdx.y * 128, n0 = blockIdx.x * 128;
    const __half* Ag = A  + (size_t)m0 * K;
    const __half* Bg = Bt + (size_t)n0 * K;

    load128(As[0], Ag, K, 0, tid);
    load128(Bs[0], Bg, K, 0, tid);
    CPA_COMMIT();

    float acc[4][4][4] = {};
    const int nt = K >> 5;
    for (int t = 0; t < nt; t++) {
        CPA_WAIT0();
        __syncthreads();
        if (t + 1 < nt) {
            load128(As[(t+1)&1], Ag, K, (t+1) << 5, tid);
            load128(Bs[(t+1)&1], Bg, K, (t+1) << 5, tid);
            CPA_COMMIT();
        }
        hstep<4,4>(As[t&1], Bs[t&1], wm, wn, gid, tig, acc);
        __syncthreads();
    }

    #pragma unroll
    for (int mi = 0; mi < 4; mi++) {
        int r0 = m0 + wm + mi * 16 + gid;
        #pragma unroll
        for (int ni = 0; ni < 4; ni++) {
            int c = n0 + wn + ni * 8 + tig * 2;
            float b0 = bias[c], b1 = bias[c + 1];
            float v00 = acc[mi][ni][0] + b0, v01 = acc[mi][ni][1] + b1;
            float v10 = acc[mi][ni][2] + b0, v11 = acc[mi][ni][3] + b1;
            if (EPI == 2) {
                v00 = fmaxf(v00, 0.f); v01 = fmaxf(v01, 0.f);
                v10 = fmaxf(v10, 0.f); v11 = fmaxf(v11, 0.f);
                __half* C = (__half*)Cout;
                *(__half2*)(C + (size_t)r0 * N + c)       = __floats2half2_rn(v00, v01);
                *(__half2*)(C + (size_t)(r0 + 8) * N + c) = __floats2half2_rn(v10, v11);
            } else {
                float2 ra = *(const float2*)(R + (size_t)r0 * N + c);
                float2 rb = *(const float2*)(R + (size_t)(r0 + 8) * N + c);
                float* C = (float*)Cout;
                *(float2*)(C + (size_t)r0 * N + c)       = make_float2(v00 + ra.x, v01 + ra.y);
                *(float2*)(C + (size_t)(r0 + 8) * N + c) = make_float2(v10 + rb.x, v11 + rb.y);
            }
        }
    }
}

// ---------------- qE = Q @ Ek^T  ([BH*S,64] x [64,64]) -----------------------
__global__ void __launch_bounds__(256)
qe_kernel(const float* __restrict__ Ek)
{
    __shared__ float sQ [64][65];
    __shared__ float sEk[64][65];
    const int tid = threadIdx.x;
    const size_t row0 = (size_t)blockIdx.x * 64;

    for (int i = tid; i < 64*64; i += 256) {
        sQ [i >> 6][i & 63] = __half2float(g_qh[row0 * 64 + i]);
        sEk[i >> 6][i & 63] = Ek[i];
    }
    __syncthreads();

    const int r  = tid >> 2;
    const int nb = (tid & 3) * 16;
    float acc[16] = {};
    #pragma unroll
    for (int d = 0; d < 64; d++) {
        float qv = sQ[r][d];
        #pragma unroll
        for (int j = 0; j < 16; j++)
            acc[j] = fmaf(qv, sEk[nb + j][d], acc[j]);
    }
    #pragma unroll
    for (int j = 0; j < 16; j++)
        g_qe[(row0 + r) * 64 + nb + j] = acc[j];
}

// ---------------- scores: batched TN half GEMM + rel gathers + scale ---------
__global__ void __launch_bounds__(256)
scores_h(const float* __restrict__ Eb, const int* __restrict__ rid)
{
    __shared__ __half As[2][128][40];
    __shared__ __half Bs[2][128][40];
    const int tid = threadIdx.x, warp = tid >> 5, lane = tid & 31;
    const int wm = (warp >> 2) * 64, wn = (warp & 3) * 32;
    const int gid = lane >> 2, tig = lane & 3;
    const int bh = blockIdx.z;
    const int m0 = blockIdx.y * 128, n0 = blockIdx.x * 128;
    const __half* Ag = g_qh + (size_t)bh * SEQ * HD + (size_t)m0 * HD;
    const __half* Bg = g_kh + (size_t)bh * SEQ * HD + (size_t)n0 * HD;

    load128(As[0], Ag, HD, 0, tid);
    load128(Bs[0], Bg, HD, 0, tid);
    CPA_COMMIT();

    float acc[4][4][4] = {};
    for (int t = 0; t < 2; t++) {
        CPA_WAIT0();
        __syncthreads();
        if (t == 0) {
            load128(As[1], Ag, HD, 32, tid);
            load128(Bs[1], Bg, HD, 32, tid);
            CPA_COMMIT();
        }
        hstep<4,4>(As[t], Bs[t], wm, wn, gid, tig, acc);
        __syncthreads();
    }

    const int h = bh & 15;
    const float* qeb = g_qe + (size_t)bh * SEQ * NREL;
    #pragma unroll
    for (int mi = 0; mi < 4; mi++) {
        int r0 = m0 + wm + mi * 16 + gid;
        #pragma unroll
        for (int ni = 0; ni < 4; ni++) {
            int c = n0 + wn + ni * 8 + tig * 2;
            #pragma unroll
            for (int rr = 0; rr < 2; rr++) {
                int row = r0 + rr * 8;
                size_t so = ((size_t)bh * SEQ + row) * SEQ;
                const float* qer = qeb + (size_t)row * NREL;
                int rd0 = rid[row * SEQ + c];
                int rd1 = rid[row * SEQ + c + 1];
                float2 o;
                o.x = (acc[mi][ni][rr*2+0] + qer[rd0] + Eb[rd0 * NH + h]) * 0.125f;
                o.y = (acc[mi][ni][rr*2+1] + qer[rd1] + Eb[rd1 * NH + h]) * 0.125f;
                *(float2*)&g_sc[so + c] = o;
            }
        }
    }
}

// ---------------- row softmax: f32 in -> half probs out ----------------------
__global__ void __launch_bounds__(256)
softmax_kernel()
{
    __shared__ float red[8];
    const float4* p = (const float4*)(g_sc + ((size_t)blockIdx.x << 10));
    __half2* po = (__half2*)(g_sch + ((size_t)blockIdx.x << 10));
    const int tid = threadIdx.x;
    float4 v = p[tid];

    float m = fmaxf(fmaxf(v.x, v.y), fmaxf(v.z, v.w));
    m = warpMax(m);
    if ((tid & 31) == 0) red[tid >> 5] = m;
    __syncthreads();
    float M = red[0];
    #pragma unroll
    for (int i = 1; i < 8; i++) M = fmaxf(M, red[i]);
    __syncthreads();

    v.x = __expf(v.x - M); v.y = __expf(v.y - M);
    v.z = __expf(v.z - M); v.w = __expf(v.w - M);
    float s = v.x + v.y + v.z + v.w;
    s = warpSum(s);
    if ((tid & 31) == 0) red[tid >> 5] = s;
    __syncthreads();
    float S = 0.f;
    #pragma unroll
    for (int i = 0; i < 8; i++) S += red[i];
    float inv = __fdividef(1.0f, S);
    po[tid*2+0] = __floats2half2_rn(v.x * inv, v.y * inv);
    po[tid*2+1] = __floats2half2_rn(v.z * inv, v.w * inv);
}

// ---------------- ctx = attn @ V : BM=128, BN=64, K=1024 ---------------------
// 8 warps 4(M) x 2(N), warp tile 32x32: MI=2, NI=4.
__global__ void __launch_bounds__(256)
ctx_h()
{
    __shared__ __half As[2][128][40];
    __shared__ __half Bs[2][64][40];
    const int tid = threadIdx.x, warp = tid >> 5, lane = tid & 31;
    const int wm = (warp >> 1) * 32, wn = (warp & 1) * 32;
    const int gid = lane >> 2, tig = lane & 3;
    const int bh = blockIdx.y;
    const int m0 = blockIdx.x * 128;
    const __half* Ag = g_sch + (size_t)bh * SEQ * SEQ + (size_t)m0 * SEQ;
    const __half* Vg = g_vt  + (size_t)bh * HD * SEQ;

    load128(As[0], Ag, SEQ, 0, tid);
    { int r = tid >> 2, s = (tid & 3) * 8;
      cpa16(&Bs[0][r][s], Vg + (size_t)r * SEQ + s); }
    CPA_COMMIT();

    float acc[2][4][4] = {};
    const int nt = SEQ >> 5;
    for (int t = 0; t < nt; t++) {
        CPA_WAIT0();
        __syncthreads();
        if (t + 1 < nt) {
            int k0 = (t + 1) << 5;
            load128(As[(t+1)&1], Ag, SEQ, k0, tid);
            int r = tid >> 2, s = (tid & 3) * 8;
            cpa16(&Bs[(t+1)&1][r][s], Vg + (size_t)r * SEQ + k0 + s);
            CPA_COMMIT();
        }
        hstep<2,4>(As[t&1], Bs[t&1], wm, wn, gid, tig, acc);
        __syncthreads();
    }

    const int b = bh >> 4, h = bh & 15;
    #pragma unroll
    for (int mi = 0; mi < 2; mi++) {
        int r0 = m0 + wm + mi * 16 + gid;
        #pragma unroll
        for (int ni = 0; ni < 4; ni++) {
            int c = wn + ni * 8 + tig * 2;
            #pragma unroll
            for (int rr = 0; rr < 2; rr++) {
                int row = r0 + rr * 8;
                *(__half2*)&g_ctxh[(size_t)(b * SEQ + row) * DM + h * HD + c] =
                    __floats2half2_rn(acc[mi][ni][rr*2+0], acc[mi][ni][rr*2+1]);
            }
        }
    }
}

// ---------------- layernorm; optional half copy of output --------------------
template<int HOUT>
__global__ void __launch_bounds__(256)
ln_kernel(const float* __restrict__ X, const float* __restrict__ g,
          const float* __restrict__ bb, float* __restrict__ Y, __half* __restrict__ Yh)
{
    __shared__ float red[16];
    const int tid = threadIdx.x;
    const size_t off = (size_t)blockIdx.x << 10;
    float4 v = ((const float4*)(X + off))[tid];

    float s  = v.x + v.y + v.z + v.w;
    float s2 = v.x*v.x + v.y*v.y + v.z*v.z + v.w*v.w;
    s = warpSum(s); s2 = warpSum(s2);
    if ((tid & 31) == 0) { red[tid >> 5] = s; red[8 + (tid >> 5)] = s2; }
    __syncthreads();
    float S = 0.f, S2 = 0.f;
    #pragma unroll
    for (int i = 0; i < 8; i++) { S += red[i]; S2 += red[8 + i]; }
    float mu  = S * (1.0f / 1024.0f);
    float var = S2 * (1.0f / 1024.0f) - mu * mu;
    float rs  = rsqrtf(var + 1e-6f);

    float4 gv = ((const float4*)g)[tid];
    float4 bv = ((const float4*)bb)[tid];
    float4 o;
    o.x = (v.x - mu) * rs * gv.x + bv.x;
    o.y = (v.y - mu) * rs * gv.y + bv.y;
    o.z = (v.z - mu) * rs * gv.z + bv.z;
    o.w = (v.w - mu) * rs * gv.w + bv.w;
    ((float4*)(Y + off))[tid] = o;
    if (HOUT) {
        __half2* ph = (__half2*)(Yh + off);
        ph[tid*2+0] = __floats2half2_rn(o.x, o.y);
        ph[tid*2+1] = __floats2half2_rn(o.z, o.w);
    }
}

// ---------------- f32 -> half straight copy (for x) --------------------------
__global__ void __launch_bounds__(256)
f2h_kernel(const float* __restrict__ S, __half* __restrict__ D)
{
    size_t i = (size_t)blockIdx.x * 1024 + threadIdx.x * 4;
    float4 v = *(const float4*)(S + i);
    ((__half2*)(D + i))[0] = __floats2half2_rn(v.x, v.y);
    ((__half2*)(D + i))[1] = __floats2half2_rn(v.z, v.w);
}

__device__ __half g_xh[ROWS*DM];   // half copy of input x

// ---------------- launch -----------------------------------------------------
extern "C" void kernel_launch(void* const* d_in, const int* in_sizes, int n_in,
                              void* d_out, int out_size)
{
    const float* x   = (const float*)d_in[0];
    const int*   rid = (const int*)  d_in[1];
    const float* Wq  = (const float*)d_in[2];
    const float* bq  = (const float*)d_in[3];
    const float* Wk  = (const float*)d_in[4];
    const float* bk  = (const float*)d_in[5];
    const float* Wv  = (const float*)d_in[6];
    const float* bv  = (const float*)d_in[7];
    const float* Wo  = (const float*)d_in[8];
    const float* bo  = (const float*)d_in[9];
    const float* Ek  = (const float*)d_in[10];
    const float* Eb  = (const float*)d_in[11];
    const float* g1  = (const float*)d_in[12];
    const float* b1  = (const float*)d_in[13];
    const float* g2  = (const float*)d_in[14];
    const float* b2  = (const float*)d_in[15];
    const float* W1  = (const float*)d_in[16];
    const float* bf1 = (const float*)d_in[17];
    const float* W2  = (const float*)d_in[18];
    const float* bf2 = (const float*)d_in[19];
    float* out = (float*)d_out;

    __half *p_wT, *p_xh, *p_ctxh, *p_ffinh, *p_h1h;
    float  *p_t, *p_ffin;
    cudaGetSymbolAddress((void**)&p_wT,    g_wT);
    cudaGetSymbolAddress((void**)&p_xh,    g_xh);
    cudaGetSymbolAddress((void**)&p_ctxh,  g_ctxh);
    cudaGetSymbolAddress((void**)&p_ffinh, g_ffinh);
    cudaGetSymbolAddress((void**)&p_h1h,   g_h1h);
    cudaGetSymbolAddress((void**)&p_t,     g_t);
    cudaGetSymbolAddress((void**)&p_ffin,  g_ffin);

    __half* WqT = p_wT;
    __half* WkT = p_wT + (size_t)DM*DM;
    __half* WvT = p_wT + (size_t)2*DM*DM;
    __half* WoT = p_wT + (size_t)3*DM*DM;
    __half* W1T = p_wT + (size_t)4*DM*DM;            // [FFN][DM]
    __half* W2T = p_wT + (size_t)4*DM*DM + DM*FFN_D; // [DM][FFN]

    const dim3 blk(256);

    // 0. operand conversion
    wtrans_kernel<<<dim3(DM/32,  DM/32),  blk>>>(Wq, WqT, DM, DM);
    wtrans_kernel<<<dim3(DM/32,  DM/32),  blk>>>(Wk, WkT, DM, DM);
    wtrans_kernel<<<dim3(DM/32,  DM/32),  blk>>>(Wv, WvT, DM, DM);
    wtrans_kernel<<<dim3(DM/32,  DM/32),  blk>>>(Wo, WoT, DM, DM);
    wtrans_kernel<<<dim3(FFN_D/32, DM/32),  blk>>>(W1, W1T, DM, FFN_D);
    wtrans_kernel<<<dim3(DM/32,  FFN_D/32), blk>>>(W2, W2T, FFN_D, DM);
    f2h_kernel<<<ROWS*DM/1024, blk>>>(x, p_xh);

    // 1. QKV projections
    proj_h<<<dim3(DM/128, ROWS/128, 3), blk>>>(p_xh, bq, bk, bv);

    // 2. qE = Q @ Ek^T
    qe_kernel<<<BHN * SEQ / 64, blk>>>(Ek);

    // 3. scores (+rel-e gather, +rel-b, scale) -> f32
    scores_h<<<dim3(SEQ/128, SEQ/128, BHN), blk>>>(Eb, rid);

    // 4. softmax -> half probs
    softmax_kernel<<<BHN * SEQ, blk>>>();

    // 5. ctx = attn @ V -> half merged layout
    ctx_h<<<dim3(SEQ/128, BHN), blk>>>();

    // 6. t = x + ctx @ Wo + bo
    hgemm<3><<<dim3(DM/128, ROWS/128), blk>>>(p_ctxh, WoT, bo, x, p_t, DM, DM);

    // 7. ff_in = LN1(t)  (f32 + half)
    ln_kernel<1><<<ROWS, blk>>>(p_t, g1, b1, p_ffin, p_ffinh);

    // 8. h1 = relu(ff_in @ W1 + bf1) -> half
    hgemm<2><<<dim3(FFN_D/128, ROWS/128), blk>>>(p_ffinh, W1T, bf1, nullptr, p_h1h, DM, FFN_D);

    // 9. t = ff_in + h1 @ W2 + bf2
    hgemm<3><<<dim3(DM/128, ROWS/128), blk>>>(p_h1h, W2T, bf2, p_ffin, p_t, FFN_D, DM);

    // 10. out = LN2(t)
    ln_kernel<0><<<ROWS, blk>>>(p_t, g2, b2, out, nullptr);
}

// round 13
// speedup vs baseline: 3.4151x; 1.0752x over previous
#include <cuda_runtime.h>
#include <cuda_fp16.h>
#include <cstdint>

#define SEQ    1024
#define DM     1024
#define NH     16
#define HD     64
#define BATCH  4
#define FFN_D  4096
#define NREL   64
#define BHN    (BATCH*NH)      // 64
#define ROWS   (BATCH*SEQ)     // 4096

// ---------------- scratch (device globals; no runtime allocation) ----------
__device__ __half g_qh  [BHN*SEQ*HD];        // 8 MB  [bh][s][d]
__device__ __half g_kh  [BHN*SEQ*HD];        // 8 MB  [bh][s][d]
__device__ __half g_vt  [BHN*HD*SEQ];        // 8 MB  [bh][d][s]  (transposed V)
__device__ float  g_qe  [BHN*SEQ*NREL];      // 16 MB
__device__ __half g_ctxh[ROWS*DM];           // 8 MB
__device__ float  g_t   [ROWS*DM];           // 16 MB
__device__ float  g_ffin[ROWS*DM];           // 16 MB
__device__ __half g_ffinh[ROWS*DM];          // 8 MB
__device__ __half g_h1h [ROWS*FFN_D];        // 32 MB
__device__ __half g_wT  [4*DM*DM + 2*DM*FFN_D];  // 24 MB
__device__ __half g_xh  [ROWS*DM];           // half copy of input x

// ---------------- helpers ---------------------------------------------------
__device__ __forceinline__ float warpSum(float v) {
    #pragma unroll
    for (int o = 16; o; o >>= 1) v += __shfl_xor_sync(0xffffffffu, v, o);
    return v;
}
__device__ __forceinline__ float warpMax(float v) {
    #pragma unroll
    for (int o = 16; o; o >>= 1) v = fmaxf(v, __shfl_xor_sync(0xffffffffu, v, o));
    return v;
}
__device__ __forceinline__ void cpa16(void* dst, const void* src) {
    uint32_t d = (uint32_t)__cvta_generic_to_shared(dst);
    asm volatile("cp.async.cg.shared.global [%0], [%1], 16;\n" :: "r"(d), "l"(src));
}
#define CPA_COMMIT() asm volatile("cp.async.commit_group;\n" ::: "memory")
#define CPA_WAIT0()  asm volatile("cp.async.wait_group 0;\n" ::: "memory")
#define CPA_WAIT1()  asm volatile("cp.async.wait_group 1;\n" ::: "memory")

__device__ __forceinline__ void mma16(float* d, const uint32_t* a, const uint32_t* b) {
    asm volatile(
        "mma.sync.aligned.m16n8k16.row.col.f32.f16.f16.f32 "
        "{%0,%1,%2,%3}, {%4,%5,%6,%7}, {%8,%9}, {%0,%1,%2,%3};\n"
        : "+f"(d[0]), "+f"(d[1]), "+f"(d[2]), "+f"(d[3])
        : "r"(a[0]), "r"(a[1]), "r"(a[2]), "r"(a[3]), "r"(b[0]), "r"(b[1]));
}

template<int MI, int NI>
__device__ __forceinline__ void hstep(const __half (*As)[40], const __half (*Bs)[40],
                                      int wm, int wn, int gid, int tig,
                                      float (&acc)[MI][NI][4])
{
    #pragma unroll
    for (int ks = 0; ks < 2; ks++) {
        const int kk = ks * 16;
        uint32_t af[MI][4], bf[NI][2];
        #pragma unroll
        for (int mi = 0; mi < MI; mi++) {
            const __half* p0 = &As[wm + mi*16 + gid    ][kk + 2*tig];
            const __half* p1 = &As[wm + mi*16 + gid + 8][kk + 2*tig];
            af[mi][0] = *(const uint32_t*)p0;
            af[mi][1] = *(const uint32_t*)p1;
            af[mi][2] = *(const uint32_t*)(p0 + 8);
            af[mi][3] = *(const uint32_t*)(p1 + 8);
        }
        #pragma unroll
        for (int ni = 0; ni < NI; ni++) {
            const __half* q = &Bs[wn + ni*8 + gid][kk + 2*tig];
            bf[ni][0] = *(const uint32_t*)q;
            bf[ni][1] = *(const uint32_t*)(q + 8);
        }
        #pragma unroll
        for (int mi = 0; mi < MI; mi++)
            #pragma unroll
            for (int ni = 0; ni < NI; ni++)
                mma16(acc[mi][ni], af[mi], bf[ni]);
    }
}
__device__ __forceinline__ void load128(__half (*S)[40], const __half* G,
                                        size_t ldk, int k0, int tid)
{
    #pragma unroll
    for (int i = 0; i < 2; i++) {
        int idx = i * 256 + tid;
        int r = idx >> 2, s = (idx & 3) * 8;
        cpa16(&S[r][s], G + (size_t)r * ldk + k0 + s);
    }
}

// ---------------- QKV projection (half TN gemm, fused over blockIdx.z) -------
__global__ void __launch_bounds__(256)
proj_h(const __half* __restrict__ xh,
       const float* __restrict__ bq, const float* __restrict__ bk, const float* __restrict__ bv)
{
    __shared__ __half As[2][128][40];
    __shared__ __half Bs[2][128][40];
    const int tid = threadIdx.x, warp = tid >> 5, lane = tid & 31;
    const int wm = (warp >> 2) * 64, wn = (warp & 3) * 32;
    const int gid = lane >> 2, tig = lane & 3;
    const int z = blockIdx.z;
    const int m0 = blockIdx.y * 128, n0 = blockIdx.x * 128;
    const __half* Ag = xh + (size_t)m0 * DM;
    const __half* Bg = g_wT + (size_t)z * DM * DM + (size_t)n0 * DM;
    const float* bias = (z == 0) ? bq : (z == 1) ? bk : bv;

    load128(As[0], Ag, DM, 0, tid);
    load128(Bs[0], Bg, DM, 0, tid);
    CPA_COMMIT();

    float acc[4][4][4] = {};
    const int nt = DM >> 5;
    for (int t = 0; t < nt; t++) {
        CPA_WAIT0();
        __syncthreads();
        if (t + 1 < nt) {
            load128(As[(t+1)&1], Ag, DM, (t+1) << 5, tid);
            load128(Bs[(t+1)&1], Bg, DM, (t+1) << 5, tid);
            CPA_COMMIT();
        }
        hstep<4,4>(As[t&1], Bs[t&1], wm, wn, gid, tig, acc);
        __syncthreads();
    }

    #pragma unroll
    for (int mi = 0; mi < 4; mi++) {
        int r0 = m0 + wm + mi * 16 + gid;
        #pragma unroll
        for (int ni = 0; ni < 4; ni++) {
            int c = n0 + wn + ni * 8 + tig * 2;
            int h = c >> 6, d = c & 63;
            float b0 = bias[c], b1 = bias[c + 1];
            #pragma unroll
            for (int rr = 0; rr < 2; rr++) {
                int row = r0 + rr * 8;
                int b = row >> 10, s = row & 1023;
                float v0 = acc[mi][ni][rr*2+0] + b0;
                float v1 = acc[mi][ni][rr*2+1] + b1;
                if (z < 2) {
                    __half* O = (z == 0) ? g_qh : g_kh;
                    *(__half2*)&O[((size_t)(b*NH + h) * SEQ + s) * HD + d] =
                        __floats2half2_rn(v0, v1);
                } else {
                    size_t vb = (size_t)(b*NH + h) * HD;
                    g_vt[(vb + d    ) * SEQ + s] = __float2half(v0);
                    g_vt[(vb + d + 1) * SEQ + s] = __float2half(v1);
                }
            }
        }
    }
}

// ---------------- generic half TN GEMM + epilogues ---------------------------
template<int EPI>
__global__ void __launch_bounds__(256)
hgemm(const __half* __restrict__ A, const __half* __restrict__ Bt,
      const float* __restrict__ bias, const float* __restrict__ R,
      void* __restrict__ Cout, int K, int N)
{
    __shared__ __half As[2][128][40];
    __shared__ __half Bs[2][128][40];
    const int tid = threadIdx.x, warp = tid >> 5, lane = tid & 31;
    const int wm = (warp >> 2) * 64, wn = (warp & 3) * 32;
    const int gid = lane >> 2, tig = lane & 3;
    const int m0 = blockIdx.y * 128, n0 = blockIdx.x * 128;
    const __half* Ag = A  + (size_t)m0 * K;
    const __half* Bg = Bt + (size_t)n0 * K;

    load128(As[0], Ag, K, 0, tid);
    load128(Bs[0], Bg, K, 0, tid);
    CPA_COMMIT();

    float acc[4][4][4] = {};
    const int nt = K >> 5;
    for (int t = 0; t < nt; t++) {
        CPA_WAIT0();
        __syncthreads();
        if (t + 1 < nt) {
            load128(As[(t+1)&1], Ag, K, (t+1) << 5, tid);
            load128(Bs[(t+1)&1], Bg, K, (t+1) << 5, tid);
            CPA_COMMIT();
        }
        hstep<4,4>(As[t&1], Bs[t&1], wm, wn, gid, tig, acc);
        __syncthreads();
    }

    #pragma unroll
    for (int mi = 0; mi < 4; mi++) {
        int r0 = m0 + wm + mi * 16 + gid;
        #pragma unroll
        for (int ni = 0; ni < 4; ni++) {
            int c = n0 + wn + ni * 8 + tig * 2;
            float b0 = bias[c], b1 = bias[c + 1];
            float v00 = acc[mi][ni][0] + b0, v01 = acc[mi][ni][1] + b1;
            float v10 = acc[mi][ni][2] + b0, v11 = acc[mi][ni][3] + b1;
            if (EPI == 2) {
                v00 = fmaxf(v00, 0.f); v01 = fmaxf(v01, 0.f);
                v10 = fmaxf(v10, 0.f); v11 = fmaxf(v11, 0.f);
                __half* C = (__half*)Cout;
                *(__half2*)(C + (size_t)r0 * N + c)       = __floats2half2_rn(v00, v01);
                *(__half2*)(C + (size_t)(r0 + 8) * N + c) = __floats2half2_rn(v10, v11);
            } else {
                float2 ra = *(const float2*)(R + (size_t)r0 * N + c);
                float2 rb = *(const float2*)(R + (size_t)(r0 + 8) * N + c);
                float* C = (float*)Cout;
                *(float2*)(C + (size_t)r0 * N + c)       = make_float2(v00 + ra.x, v01 + ra.y);
                *(float2*)(C + (size_t)(r0 + 8) * N + c) = make_float2(v10 + rb.x, v11 + rb.y);
            }
        }
    }
}

// ---------------- qE = Q @ Ek^T  ---------------------------------------------
__global__ void __launch_bounds__(256)
qe_kernel(const float* __restrict__ Ek)
{
    __shared__ float sQ [64][65];
    __shared__ float sEk[64][65];
    const int tid = threadIdx.x;
    const size_t row0 = (size_t)blockIdx.x * 64;

    for (int i = tid; i < 64*64; i += 256) {
        sQ [i >> 6][i & 63] = __half2float(g_qh[row0 * 64 + i]);
        sEk[i >> 6][i & 63] = Ek[i];
    }
    __syncthreads();

    const int r  = tid >> 2;
    const int nb = (tid & 3) * 16;
    float acc[16] = {};
    #pragma unroll
    for (int d = 0; d < 64; d++) {
        float qv = sQ[r][d];
        #pragma unroll
        for (int j = 0; j < 16; j++)
            acc[j] = fmaf(qv, sEk[nb + j][d], acc[j]);
    }
    #pragma unroll
    for (int j = 0; j < 16; j++)
        g_qe[(row0 + r) * 64 + nb + j] = acc[j];
}

// ================= fused attention ===========================================
// One CTA: 32 query rows x one (b,h). Scores row-block lives in SMEM; K then V
// streamed in double-buffered cp.async tiles; softmax in regs; probs half
// in-place; only the 32x64 ctx tile is written out.
#define AT_SMEM  182016
#define AOFF_S   0                       // float  [32][1032]   132096 B
#define AOFF_Q   132096                  // half   [32][72]       4608 B
#define AOFF_KV  136704                  // 2 x 18432 B (K tile 128x72h / V tile 64x136h)
#define AOFF_QE  173568                  // float  [32][64]       8192 B
#define AOFF_EB  181760                  // float  [64]            256 B

__global__ void __launch_bounds__(256)
attn_fused(const float* __restrict__ Eb, const int* __restrict__ rid)
{
    extern __shared__ char sm[];
    float*  Ssc = (float*) (sm + AOFF_S);    // row stride 1032 f32 (2064 half)
    __half* Qs  = (__half*)(sm + AOFF_Q);    // row stride 72
    float*  QE  = (float*) (sm + AOFF_QE);   // row stride 64
    float*  EBc = (float*) (sm + AOFF_EB);
    __half* KV0 = (__half*)(sm + AOFF_KV);
    __half* KV1 = (__half*)(sm + AOFF_KV + 18432);

    const int tid = threadIdx.x, warp = tid >> 5, lane = tid & 31;
    const int gid = lane >> 2, tig = lane & 3;
    const int bh = blockIdx.y, h = bh & 15;
    const int m0 = blockIdx.x * 32;

    // ---- stage Q (32x64), qE rows (32x64 f32), Eb column ----
    {
        int r = tid >> 3, c = (tid & 7) * 8;
        cpa16(Qs + r*72 + c, g_qh + (size_t)bh*SEQ*HD + (size_t)(m0 + r)*HD + c);
    }
    #pragma unroll
    for (int i = 0; i < 2; i++) {
        int idx = i*256 + tid;
        int r = idx >> 4, c = (idx & 15) * 4;
        cpa16(QE + r*64 + c, g_qe + ((size_t)bh*SEQ + m0 + r)*NREL + c);
    }
    if (tid < 64) EBc[tid] = Eb[tid*NH + h];

    const __half* Kg = g_kh + (size_t)bh*SEQ*HD;
    // K tile 0
    #pragma unroll
    for (int i = 0; i < 4; i++) {
        int idx = i*256 + tid;
        int r = idx >> 3, c = (idx & 7) * 8;
        cpa16(KV0 + r*72 + c, Kg + (size_t)r*HD + c);
    }
    CPA_COMMIT();

    // ---- phase 1: scores = QK^T + qE-gather + Eb, scaled, into SMEM ----
    const int wn = warp * 16;
    for (int kt = 0; kt < 8; kt++) {
        __half* cur = (kt & 1) ? KV1 : KV0;
        if (kt + 1 < 8) {
            __half* nxt = (kt & 1) ? KV0 : KV1;
            #pragma unroll
            for (int i = 0; i < 4; i++) {
                int idx = i*256 + tid;
                int r = idx >> 3, c = (idx & 7) * 8;
                cpa16(nxt + r*72 + c, Kg + (size_t)(kt+1)*128*HD + (size_t)r*HD + c);
            }
            CPA_COMMIT();
            CPA_WAIT1();
        } else CPA_WAIT0();
        __syncthreads();

        float acc[2][2][4] = {};
        #pragma unroll
        for (int ks = 0; ks < 4; ks++) {
            const int kk = ks * 16;
            uint32_t af[2][4], bf[2][2];
            #pragma unroll
            for (int mi = 0; mi < 2; mi++) {
                const __half* p0 = Qs + (mi*16 + gid)*72 + kk + 2*tig;
                const __half* p1 = p0 + 8*72;
                af[mi][0] = *(const uint32_t*)p0;
                af[mi][1] = *(const uint32_t*)p1;
                af[mi][2] = *(const uint32_t*)(p0 + 8);
                af[mi][3] = *(const uint32_t*)(p1 + 8);
            }
            #pragma unroll
            for (int ni = 0; ni < 2; ni++) {
                const __half* q = cur + (wn + ni*8 + gid)*72 + kk + 2*tig;
                bf[ni][0] = *(const uint32_t*)q;
                bf[ni][1] = *(const uint32_t*)(q + 8);
            }
            #pragma unroll
            for (int mi = 0; mi < 2; mi++)
                #pragma unroll
                for (int ni = 0; ni < 2; ni++)
                    mma16(acc[mi][ni], af[mi], bf[ni]);
        }
        #pragma unroll
        for (int mi = 0; mi < 2; mi++) {
            #pragma unroll
            for (int ni = 0; ni < 2; ni++) {
                #pragma unroll
                for (int rr = 0; rr < 2; rr++) {
                    int row = mi*16 + gid + rr*8;
                    int col = kt*128 + wn + ni*8 + tig*2;
                    const int* rp = rid + (size_t)(m0 + row)*SEQ + col;
                    int rd0 = rp[0], rd1 = rp[1];
                    float2 o;
                    o.x = (acc[mi][ni][rr*2+0] + QE[row*64 + rd0] + EBc[rd0]) * 0.125f;
                    o.y = (acc[mi][ni][rr*2+1] + QE[row*64 + rd1] + EBc[rd1]) * 0.125f;
                    *(float2*)&Ssc[row*1032 + col] = o;
                }
            }
        }
        __syncthreads();
    }

    // ---- prefetch V tile 0 (overlaps softmax) ----
    const __half* Vg = g_vt + (size_t)bh*HD*SEQ;
    #pragma unroll
    for (int i = 0; i < 4; i++) {
        int idx = i*256 + tid;
        int r = idx >> 4, c = (idx & 15) * 8;
        cpa16(KV0 + r*136 + c, Vg + (size_t)r*SEQ + c);
    }
    CPA_COMMIT();

    // ---- phase 2: row softmax, probs to half in place ----
    #pragma unroll
    for (int rr = 0; rr < 4; rr++) {
        const int row = warp*4 + rr;
        float* base = Ssc + row*1032;
        float v[32];
        #pragma unroll
        for (int i = 0; i < 32; i++) v[i] = base[lane + 32*i];
        float m = v[0];
        #pragma unroll
        for (int i = 1; i < 32; i++) m = fmaxf(m, v[i]);
        m = warpMax(m);
        float s = 0.f;
        #pragma unroll
        for (int i = 0; i < 32; i++) { v[i] = __expf(v[i] - m); s += v[i]; }
        s = warpSum(s);
        float inv = __fdividef(1.0f, s);
        __syncwarp();
        __half* hb = (__half*)base;
        #pragma unroll
        for (int i = 0; i < 32; i++) hb[lane + 32*i] = __float2half(v[i] * inv);
    }
    __syncthreads();

    // ---- phase 3: ctx = probs @ V ----
    const int wn3 = warp * 8;
    float acc3[2][4] = {};
    for (int vt = 0; vt < 8; vt++) {
        const __half* cur = (vt & 1) ? KV1 : KV0;
        if (vt + 1 < 8) {
            __half* nxt = (vt & 1) ? KV0 : KV1;
            #pragma unroll
            for (int i = 0; i < 4; i++) {
                int idx = i*256 + tid;
                int r = idx >> 4, c = (idx & 15) * 8;
                cpa16(nxt + r*136 + c, Vg + (size_t)r*SEQ + (vt+1)*128 + c);
            }
            CPA_COMMIT();
            CPA_WAIT1();
        } else CPA_WAIT0();
        __syncthreads();

        const __half* Ph = (const __half*)Ssc;   // row stride 2064 halves
        #pragma unroll
        for (int ks = 0; ks < 8; ks++) {
            const int kk = ks * 16;
            uint32_t af[2][4], bf[2];
            #pragma unroll
            for (int mi = 0; mi < 2; mi++) {
                const __half* p0 = Ph + (mi*16 + gid)*2064 + vt*128 + kk + 2*tig;
                const __half* p1 = p0 + 8*2064;
                af[mi][0] = *(const uint32_t*)p0;
                af[mi][1] = *(const uint32_t*)p1;
                af[mi][2] = *(const uint32_t*)(p0 + 8);
                af[mi][3] = *(const uint32_t*)(p1 + 8);
            }
            const __half* q = cur + (wn3 + gid)*136 + kk + 2*tig;
            bf[0] = *(const uint32_t*)q;
            bf[1] = *(const uint32_t*)(q + 8);
            mma16(acc3[0], af[0], bf);
            mma16(acc3[1], af[1], bf);
        }
        __syncthreads();
    }

    const int b = bh >> 4;
    #pragma unroll
    for (int mi = 0; mi < 2; mi++)
        #pragma unroll
        for (int rr = 0; rr < 2; rr++) {
            int row = mi*16 + gid + rr*8;
            int tok = b*SEQ + m0 + row;
            *(__half2*)&g_ctxh[(size_t)tok*DM + h*HD + wn3 + tig*2] =
                __floats2half2_rn(acc3[mi][rr*2+0], acc3[mi][rr*2+1]);
        }
}

// ---------------- small kernels ---------------------------------------------
__global__ void __launch_bounds__(256)
wtrans_kernel(const float* __restrict__ S, __half* __restrict__ D, int K, int N)
{
    __shared__ float t[32][33];
    const int k0 = blockIdx.y * 32, n0 = blockIdx.x * 32;
    const int tx = threadIdx.x & 31, ty = threadIdx.x >> 5;
    #pragma unroll
    for (int i = 0; i < 32; i += 8)
        t[ty + i][tx] = S[(size_t)(k0 + ty + i) * N + n0 + tx];
    __syncthreads();
    #pragma unroll
    for (int i = 0; i < 32; i += 8)
        D[(size_t)(n0 + ty + i) * K + k0 + tx] = __float2half(t[tx][ty + i]);
}

template<int HOUT>
__global__ void __launch_bounds__(256)
ln_kernel(const float* __restrict__ X, const float* __restrict__ g,
          const float* __restrict__ bb, float* __restrict__ Y, __half* __restrict__ Yh)
{
    __shared__ float red[16];
    const int tid = threadIdx.x;
    const size_t off = (size_t)blockIdx.x << 10;
    float4 v = ((const float4*)(X + off))[tid];

    float s  = v.x + v.y + v.z + v.w;
    float s2 = v.x*v.x + v.y*v.y + v.z*v.z + v.w*v.w;
    s = warpSum(s); s2 = warpSum(s2);
    if ((tid & 31) == 0) { red[tid >> 5] = s; red[8 + (tid >> 5)] = s2; }
    __syncthreads();
    float S = 0.f, S2 = 0.f;
    #pragma unroll
    for (int i = 0; i < 8; i++) { S += red[i]; S2 += red[8 + i]; }
    float mu  = S * (1.0f / 1024.0f);
    float var = S2 * (1.0f / 1024.0f) - mu * mu;
    float rs  = rsqrtf(var + 1e-6f);

    float4 gv = ((const float4*)g)[tid];
    float4 bv = ((const float4*)bb)[tid];
    float4 o;
    o.x = (v.x - mu) * rs * gv.x + bv.x;
    o.y = (v.y - mu) * rs * gv.y + bv.y;
    o.z = (v.z - mu) * rs * gv.z + bv.z;
    o.w = (v.w - mu) * rs * gv.w + bv.w;
    ((float4*)(Y + off))[tid] = o;
    if (HOUT) {
        __half2* ph = (__half2*)(Yh + off);
        ph[tid*2+0] = __floats2half2_rn(o.x, o.y);
        ph[tid*2+1] = __floats2half2_rn(o.z, o.w);
    }
}

__global__ void __launch_bounds__(256)
f2h_kernel(const float* __restrict__ S, __half* __restrict__ D)
{
    size_t i = (size_t)blockIdx.x * 1024 + threadIdx.x * 4;
    float4 v = *(const float4*)(S + i);
    ((__half2*)(D + i))[0] = __floats2half2_rn(v.x, v.y);
    ((__half2*)(D + i))[1] = __floats2half2_rn(v.z, v.w);
}

// ---------------- launch -----------------------------------------------------
extern "C" void kernel_launch(void* const* d_in, const int* in_sizes, int n_in,
                              void* d_out, int out_size)
{
    const float* x   = (const float*)d_in[0];
    const int*   rid = (const int*)  d_in[1];
    const float* Wq  = (const float*)d_in[2];
    const float* bq  = (const float*)d_in[3];
    const float* Wk  = (const float*)d_in[4];
    const float* bk  = (const float*)d_in[5];
    const float* Wv  = (const float*)d_in[6];
    const float* bv  = (const float*)d_in[7];
    const float* Wo  = (const float*)d_in[8];
    const float* bo  = (const float*)d_in[9];
    const float* Ek  = (const float*)d_in[10];
    const float* Eb  = (const float*)d_in[11];
    const float* g1  = (const float*)d_in[12];
    const float* b1  = (const float*)d_in[13];
    const float* g2  = (const float*)d_in[14];
    const float* b2  = (const float*)d_in[15];
    const float* W1  = (const float*)d_in[16];
    const float* bf1 = (const float*)d_in[17];
    const float* W2  = (const float*)d_in[18];
    const float* bf2 = (const float*)d_in[19];
    float* out = (float*)d_out;

    __half *p_wT, *p_xh, *p_ctxh, *p_ffinh, *p_h1h;
    float  *p_t, *p_ffin;
    cudaGetSymbolAddress((void**)&p_wT,    g_wT);
    cudaGetSymbolAddress((void**)&p_xh,    g_xh);
    cudaGetSymbolAddress((void**)&p_ctxh,  g_ctxh);
    cudaGetSymbolAddress((void**)&p_ffinh, g_ffinh);
    cudaGetSymbolAddress((void**)&p_h1h,   g_h1h);
    cudaGetSymbolAddress((void**)&p_t,     g_t);
    cudaGetSymbolAddress((void**)&p_ffin,  g_ffin);

    __half* WoT = p_wT + (size_t)3*DM*DM;
    __half* W1T = p_wT + (size_t)4*DM*DM;            // [FFN][DM]
    __half* W2T = p_wT + (size_t)4*DM*DM + DM*FFN_D; // [DM][FFN]

    static int smem_set = 0;
    if (!smem_set) {
        cudaFuncSetAttribute(attn_fused, cudaFuncAttributeMaxDynamicSharedMemorySize, AT_SMEM);
        smem_set = 1;
    }

    const dim3 blk(256);

    // 0. operand conversion
    wtrans_kernel<<<dim3(DM/32,  DM/32),  blk>>>(Wq, p_wT,                       DM, DM);
    wtrans_kernel<<<dim3(DM/32,  DM/32),  blk>>>(Wk, p_wT + (size_t)DM*DM,       DM, DM);
    wtrans_kernel<<<dim3(DM/32,  DM/32),  blk>>>(Wv, p_wT + (size_t)2*DM*DM,     DM, DM);
    wtrans_kernel<<<dim3(DM/32,  DM/32),  blk>>>(Wo, WoT, DM, DM);
    wtrans_kernel<<<dim3(FFN_D/32, DM/32),  blk>>>(W1, W1T, DM, FFN_D);
    wtrans_kernel<<<dim3(DM/32,  FFN_D/32), blk>>>(W2, W2T, FFN_D, DM);
    f2h_kernel<<<ROWS*DM/1024, blk>>>(x, p_xh);

    // 1. QKV projections
    proj_h<<<dim3(DM/128, ROWS/128, 3), blk>>>(p_xh, bq, bk, bv);

    // 2. qE = Q @ Ek^T
    qe_kernel<<<BHN * SEQ / 64, blk>>>(Ek);

    // 3-5. fused scores + softmax + ctx
    attn_fused<<<dim3(SEQ/32, BHN), blk, AT_SMEM>>>(Eb, rid);

    // 6. t = x + ctx @ Wo + bo
    hgemm<3><<<dim3(DM/128, ROWS/128), blk>>>(p_ctxh, WoT, bo, x, p_t, DM, DM);

    // 7. ff_in = LN1(t)
    ln_kernel<1><<<ROWS, blk>>>(p_t, g1, b1, p_ffin, p_ffinh);

    // 8. h1 = relu(ff_in @ W1 + bf1) -> half
    hgemm<2><<<dim3(FFN_D/128, ROWS/128), blk>>>(p_ffinh, W1T, bf1, nullptr, p_h1h, DM, FFN_D);

    // 9. t = ff_in + h1 @ W2 + bf2
    hgemm<3><<<dim3(DM/128, ROWS/128), blk>>>(p_h1h, W2T, bf2, p_ffin, p_t, FFN_D, DM);

    // 10. out = LN2(t)
    ln_kernel<0><<<ROWS, blk>>>(p_t, g2, b2, out, nullptr);
}

// round 14
// speedup vs baseline: 3.9888x; 1.1680x over previous
#include <cuda_runtime.h>
#include <cuda_fp16.h>
#include <cstdint>

#define SEQ    1024
#define DM     1024
#define NH     16
#define HD     64
#define BATCH  4
#define FFN_D  4096
#define NREL   64
#define BHN    (BATCH*NH)      // 64
#define ROWS   (BATCH*SEQ)     // 4096

// ---------------- scratch (device globals; no runtime allocation) ----------
__device__ __half g_qh  [BHN*SEQ*HD];        // 8 MB  [bh][s][d]
__device__ __half g_kh  [BHN*SEQ*HD];        // 8 MB  [bh][s][d]
__device__ __half g_vt  [BHN*HD*SEQ];        // 8 MB  [bh][d][s]  (transposed V)
__device__ float  g_qe  [BHN*SEQ*NREL];      // 16 MB
__device__ __half g_ctxh[ROWS*DM];           // 8 MB
__device__ float  g_t   [ROWS*DM];           // 16 MB
__device__ float  g_ffin[ROWS*DM];           // 16 MB
__device__ __half g_ffinh[ROWS*DM];          // 8 MB
__device__ __half g_h1h [ROWS*FFN_D];        // 32 MB
__device__ __half g_wT  [4*DM*DM + 2*DM*FFN_D];  // 24 MB
__device__ __half g_xh  [ROWS*DM];           // half copy of input x

// ---------------- helpers ---------------------------------------------------
__device__ __forceinline__ float warpSum(float v) {
    #pragma unroll
    for (int o = 16; o; o >>= 1) v += __shfl_xor_sync(0xffffffffu, v, o);
    return v;
}
__device__ __forceinline__ void cpa16(void* dst, const void* src) {
    uint32_t d = (uint32_t)__cvta_generic_to_shared(dst);
    asm volatile("cp.async.cg.shared.global [%0], [%1], 16;\n" :: "r"(d), "l"(src));
}
#define CPA_COMMIT() asm volatile("cp.async.commit_group;\n" ::: "memory")
#define CPA_WAIT0()  asm volatile("cp.async.wait_group 0;\n" ::: "memory")
#define CPA_WAIT1()  asm volatile("cp.async.wait_group 1;\n" ::: "memory")

__device__ __forceinline__ void mma16(float* d, const uint32_t* a, const uint32_t* b) {
    asm volatile(
        "mma.sync.aligned.m16n8k16.row.col.f32.f16.f16.f32 "
        "{%0,%1,%2,%3}, {%4,%5,%6,%7}, {%8,%9}, {%0,%1,%2,%3};\n"
        : "+f"(d[0]), "+f"(d[1]), "+f"(d[2]), "+f"(d[3])
        : "r"(a[0]), "r"(a[1]), "r"(a[2]), "r"(a[3]), "r"(b[0]), "r"(b[1]));
}
__device__ __forceinline__ uint32_t pack2(float a, float b) {
    __half2 h = __floats2half2_rn(a, b);
    return *(uint32_t*)&h;
}

template<int MI, int NI>
__device__ __forceinline__ void hstep(const __half (*As)[40], const __half (*Bs)[40],
                                      int wm, int wn, int gid, int tig,
                                      float (&acc)[MI][NI][4])
{
    #pragma unroll
    for (int ks = 0; ks < 2; ks++) {
        const int kk = ks * 16;
        uint32_t af[MI][4], bf[NI][2];
        #pragma unroll
        for (int mi = 0; mi < MI; mi++) {
            const __half* p0 = &As[wm + mi*16 + gid    ][kk + 2*tig];
            const __half* p1 = &As[wm + mi*16 + gid + 8][kk + 2*tig];
            af[mi][0] = *(const uint32_t*)p0;
            af[mi][1] = *(const uint32_t*)p1;
            af[mi][2] = *(const uint32_t*)(p0 + 8);
            af[mi][3] = *(const uint32_t*)(p1 + 8);
        }
        #pragma unroll
        for (int ni = 0; ni < NI; ni++) {
            const __half* q = &Bs[wn + ni*8 + gid][kk + 2*tig];
            bf[ni][0] = *(const uint32_t*)q;
            bf[ni][1] = *(const uint32_t*)(q + 8);
        }
        #pragma unroll
        for (int mi = 0; mi < MI; mi++)
            #pragma unroll
            for (int ni = 0; ni < NI; ni++)
                mma16(acc[mi][ni], af[mi], bf[ni]);
    }
}
__device__ __forceinline__ void load128(__half (*S)[40], const __half* G,
                                        size_t ldk, int k0, int tid)
{
    #pragma unroll
    for (int i = 0; i < 2; i++) {
        int idx = i * 256 + tid;
        int r = idx >> 2, s = (idx & 3) * 8;
        cpa16(&S[r][s], G + (size_t)r * ldk + k0 + s);
    }
}

// ---------------- QKV projection -------------------------------------------
__global__ void __launch_bounds__(256)
proj_h(const __half* __restrict__ xh,
       const float* __restrict__ bq, const float* __restrict__ bk, const float* __restrict__ bv)
{
    __shared__ __half As[2][128][40];
    __shared__ __half Bs[2][128][40];
    const int tid = threadIdx.x, warp = tid >> 5, lane = tid & 31;
    const int wm = (warp >> 2) * 64, wn = (warp & 3) * 32;
    const int gid = lane >> 2, tig = lane & 3;
    const int z = blockIdx.z;
    const int m0 = blockIdx.y * 128, n0 = blockIdx.x * 128;
    const __half* Ag = xh + (size_t)m0 * DM;
    const __half* Bg = g_wT + (size_t)z * DM * DM + (size_t)n0 * DM;
    const float* bias = (z == 0) ? bq : (z == 1) ? bk : bv;

    load128(As[0], Ag, DM, 0, tid);
    load128(Bs[0], Bg, DM, 0, tid);
    CPA_COMMIT();

    float acc[4][4][4] = {};
    const int nt = DM >> 5;
    for (int t = 0; t < nt; t++) {
        CPA_WAIT0();
        __syncthreads();
        if (t + 1 < nt) {
            load128(As[(t+1)&1], Ag, DM, (t+1) << 5, tid);
            load128(Bs[(t+1)&1], Bg, DM, (t+1) << 5, tid);
            CPA_COMMIT();
        }
        hstep<4,4>(As[t&1], Bs[t&1], wm, wn, gid, tig, acc);
        __syncthreads();
    }

    #pragma unroll
    for (int mi = 0; mi < 4; mi++) {
        int r0 = m0 + wm + mi * 16 + gid;
        #pragma unroll
        for (int ni = 0; ni < 4; ni++) {
            int c = n0 + wn + ni * 8 + tig * 2;
            int h = c >> 6, d = c & 63;
            float b0 = bias[c], b1 = bias[c + 1];
            #pragma unroll
            for (int rr = 0; rr < 2; rr++) {
                int row = r0 + rr * 8;
                int b = row >> 10, s = row & 1023;
                float v0 = acc[mi][ni][rr*2+0] + b0;
                float v1 = acc[mi][ni][rr*2+1] + b1;
                if (z < 2) {
                    __half* O = (z == 0) ? g_qh : g_kh;
                    *(__half2*)&O[((size_t)(b*NH + h) * SEQ + s) * HD + d] =
                        __floats2half2_rn(v0, v1);
                } else {
                    size_t vb = (size_t)(b*NH + h) * HD;
                    g_vt[(vb + d    ) * SEQ + s] = __float2half(v0);
                    g_vt[(vb + d + 1) * SEQ + s] = __float2half(v1);
                }
            }
        }
    }
}

// ---------------- generic half TN GEMM + epilogues ---------------------------
template<int EPI>
__global__ void __launch_bounds__(256)
hgemm(const __half* __restrict__ A, const __half* __restrict__ Bt,
      const float* __restrict__ bias, const float* __restrict__ R,
      void* __restrict__ Cout, int K, int N)
{
    __shared__ __half As[2][128][40];
    __shared__ __half Bs[2][128][40];
    const int tid = threadIdx.x, warp = tid >> 5, lane = tid & 31;
    const int wm = (warp >> 2) * 64, wn = (warp & 3) * 32;
    const int gid = lane >> 2, tig = lane & 3;
    const int m0 = blockIdx.y * 128, n0 = blockIdx.x * 128;
    const __half* Ag = A  + (size_t)m0 * K;
    const __half* Bg = Bt + (size_t)n0 * K;

    load128(As[0], Ag, K, 0, tid);
    load128(Bs[0], Bg, K, 0, tid);
    CPA_COMMIT();

    float acc[4][4][4] = {};
    const int nt = K >> 5;
    for (int t = 0; t < nt; t++) {
        CPA_WAIT0();
        __syncthreads();
        if (t + 1 < nt) {
            load128(As[(t+1)&1], Ag, K, (t+1) << 5, tid);
            load128(Bs[(t+1)&1], Bg, K, (t+1) << 5, tid);
            CPA_COMMIT();
        }
        hstep<4,4>(As[t&1], Bs[t&1], wm, wn, gid, tig, acc);
        __syncthreads();
    }

    #pragma unroll
    for (int mi = 0; mi < 4; mi++) {
        int r0 = m0 + wm + mi * 16 + gid;
        #pragma unroll
        for (int ni = 0; ni < 4; ni++) {
            int c = n0 + wn + ni * 8 + tig * 2;
            float b0 = bias[c], b1 = bias[c + 1];
            float v00 = acc[mi][ni][0] + b0, v01 = acc[mi][ni][1] + b1;
            float v10 = acc[mi][ni][2] + b0, v11 = acc[mi][ni][3] + b1;
            if (EPI == 2) {
                v00 = fmaxf(v00, 0.f); v01 = fmaxf(v01, 0.f);
                v10 = fmaxf(v10, 0.f); v11 = fmaxf(v11, 0.f);
                __half* C = (__half*)Cout;
                *(__half2*)(C + (size_t)r0 * N + c)       = __floats2half2_rn(v00, v01);
                *(__half2*)(C + (size_t)(r0 + 8) * N + c) = __floats2half2_rn(v10, v11);
            } else {
                float2 ra = *(const float2*)(R + (size_t)r0 * N + c);
                float2 rb = *(const float2*)(R + (size_t)(r0 + 8) * N + c);
                float* C = (float*)Cout;
                *(float2*)(C + (size_t)r0 * N + c)       = make_float2(v00 + ra.x, v01 + ra.y);
                *(float2*)(C + (size_t)(r0 + 8) * N + c) = make_float2(v10 + rb.x, v11 + rb.y);
            }
        }
    }
}

// ---------------- qE = Q @ Ek^T  ---------------------------------------------
__global__ void __launch_bounds__(256)
qe_kernel(const float* __restrict__ Ek)
{
    __shared__ float sQ [64][65];
    __shared__ float sEk[64][65];
    const int tid = threadIdx.x;
    const size_t row0 = (size_t)blockIdx.x * 64;

    for (int i = tid; i < 64*64; i += 256) {
        sQ [i >> 6][i & 63] = __half2float(g_qh[row0 * 64 + i]);
        sEk[i >> 6][i & 63] = Ek[i];
    }
    __syncthreads();

    const int r  = tid >> 2;
    const int nb = (tid & 3) * 16;
    float acc[16] = {};
    #pragma unroll
    for (int d = 0; d < 64; d++) {
        float qv = sQ[r][d];
        #pragma unroll
        for (int j = 0; j < 16; j++)
            acc[j] = fmaf(qv, sEk[nb + j][d], acc[j]);
    }
    #pragma unroll
    for (int j = 0; j < 16; j++)
        g_qe[(row0 + r) * 64 + nb + j] = acc[j];
}

// ================= flash attention (online softmax, scores stay in regs) =====
// CTA: 128 threads (4 warps), 64 q-rows of one (b,h). Warp w: rows w*16..+16.
// Per 128-key tile: S=QK^T in frags; qE/Eb gather + scale in frag epilogue;
// online max/sum via quad shuffles; P repacked in-register to A-frags; ctx+=P*V.
#define FA_SMEM 97536
#define FOFF_Q   0        // half [64][72]   9216 B
#define FOFF_QE  9216     // f32  [64][64]  16384 B
#define FOFF_EB  25600    // f32  [64]        256 B
#define FOFF_K   25856    // 2 x half[128][72] = 2x18432 B
#define FOFF_V   62720    // 2 x half[64][136] = 2x17408 B

__global__ void __launch_bounds__(128)
attn_flash(const float* __restrict__ Eb, const int* __restrict__ rid)
{
    extern __shared__ char sm[];
    __half* Qs  = (__half*)(sm + FOFF_Q);    // stride 72
    float*  QE  = (float*) (sm + FOFF_QE);   // stride 64
    float*  EBc = (float*) (sm + FOFF_EB);
    __half* Kb  = (__half*)(sm + FOFF_K);    // buffers of 9216 halves
    __half* Vb  = (__half*)(sm + FOFF_V);    // buffers of 8704 halves

    const int tid = threadIdx.x, warp = tid >> 5, lane = tid & 31;
    const int gid = lane >> 2, tig = lane & 3;
    const int bh = blockIdx.y, h = bh & 15, b = bh >> 4;
    const int m0 = blockIdx.x * 64;
    const int wr = warp * 16;

    const __half* Kg = g_kh + (size_t)bh * SEQ * HD;
    const __half* Vg = g_vt + (size_t)bh * HD * SEQ;

    // group 0: Q + QE + K0 + V0
    #pragma unroll
    for (int i = 0; i < 4; i++) {
        int idx = i*128 + tid; int r = idx >> 3, c = (idx & 7) * 8;
        cpa16(Qs + r*72 + c, g_qh + (size_t)bh*SEQ*HD + (size_t)(m0 + r)*HD + c);
    }
    #pragma unroll
    for (int i = 0; i < 8; i++) {
        int idx = i*128 + tid; int r = idx >> 4, c = (idx & 15) * 4;
        cpa16(QE + r*64 + c, g_qe + ((size_t)bh*SEQ + m0 + r)*NREL + c);
    }
    if (tid < 64) EBc[tid] = Eb[tid*NH + h];
    #pragma unroll
    for (int i = 0; i < 8; i++) {
        int idx = i*128 + tid; int r = idx >> 3, c = (idx & 7) * 8;
        cpa16(Kb + r*72 + c, Kg + (size_t)r*HD + c);
    }
    #pragma unroll
    for (int i = 0; i < 8; i++) {
        int idx = i*128 + tid; int r = idx >> 4, c = (idx & 15) * 8;
        cpa16(Vb + r*136 + c, Vg + (size_t)r*SEQ + c);
    }
    CPA_COMMIT();
    // group 1: K1 + V1
    #pragma unroll
    for (int i = 0; i < 8; i++) {
        int idx = i*128 + tid; int r = idx >> 3, c = (idx & 7) * 8;
        cpa16(Kb + 9216 + r*72 + c, Kg + (size_t)(128 + r)*HD + c);
    }
    #pragma unroll
    for (int i = 0; i < 8; i++) {
        int idx = i*128 + tid; int r = idx >> 4, c = (idx & 15) * 8;
        cpa16(Vb + 8704 + r*136 + c, Vg + (size_t)r*SEQ + 128 + c);
    }
    CPA_COMMIT();

    float m0r = -1e30f, m1r = -1e30f, l0 = 0.f, l1 = 0.f;
    float ctx[8][4] = {};

    for (int kt = 0; kt < 8; kt++) {
        if (kt < 7) CPA_WAIT1(); else CPA_WAIT0();
        __syncthreads();
        const __half* Kt = Kb + (kt & 1) * 9216;
        const __half* Vt = Vb + (kt & 1) * 8704;

        // ---- S = Q K^T (warp: 16 rows x 128 keys) ----
        float sacc[16][4] = {};
        #pragma unroll
        for (int ks = 0; ks < 4; ks++) {
            const int kk = ks * 16;
            uint32_t af[4];
            const __half* p0 = Qs + (wr + gid)*72 + kk + 2*tig;
            const __half* p1 = p0 + 8*72;
            af[0] = *(const uint32_t*)p0;
            af[1] = *(const uint32_t*)p1;
            af[2] = *(const uint32_t*)(p0 + 8);
            af[3] = *(const uint32_t*)(p1 + 8);
            #pragma unroll
            for (int ni = 0; ni < 16; ni++) {
                uint32_t bf[2];
                const __half* q = Kt + (ni*8 + gid)*72 + kk + 2*tig;
                bf[0] = *(const uint32_t*)q;
                bf[1] = *(const uint32_t*)(q + 8);
                mma16(sacc[ni], af, bf);
            }
        }

        // ---- rel gathers + scale + tile max ----
        const int row0 = m0 + wr + gid, row1 = row0 + 8;
        const float* qe0 = QE + (wr + gid) * 64;
        const float* qe1 = qe0 + 8 * 64;
        float mx0 = -1e30f, mx1 = -1e30f;
        #pragma unroll
        for (int ni = 0; ni < 16; ni++) {
            int col = kt*128 + ni*8 + tig*2;
            int2 rd0 = *(const int2*)(rid + (size_t)row0*SEQ + col);
            int2 rd1 = *(const int2*)(rid + (size_t)row1*SEQ + col);
            sacc[ni][0] = (sacc[ni][0] + qe0[rd0.x] + EBc[rd0.x]) * 0.125f;
            sacc[ni][1] = (sacc[ni][1] + qe0[rd0.y] + EBc[rd0.y]) * 0.125f;
            sacc[ni][2] = (sacc[ni][2] + qe1[rd1.x] + EBc[rd1.x]) * 0.125f;
            sacc[ni][3] = (sacc[ni][3] + qe1[rd1.y] + EBc[rd1.y]) * 0.125f;
            mx0 = fmaxf(mx0, fmaxf(sacc[ni][0], sacc[ni][1]));
            mx1 = fmaxf(mx1, fmaxf(sacc[ni][2], sacc[ni][3]));
        }
        mx0 = fmaxf(mx0, __shfl_xor_sync(0xffffffffu, mx0, 1));
        mx0 = fmaxf(mx0, __shfl_xor_sync(0xffffffffu, mx0, 2));
        mx1 = fmaxf(mx1, __shfl_xor_sync(0xffffffffu, mx1, 1));
        mx1 = fmaxf(mx1, __shfl_xor_sync(0xffffffffu, mx1, 2));

        // ---- online update ----
        float nm0 = fmaxf(m0r, mx0), nm1 = fmaxf(m1r, mx1);
        float f0 = __expf(m0r - nm0), f1 = __expf(m1r - nm1);
        m0r = nm0; m1r = nm1;
        float s0 = 0.f, s1 = 0.f;
        #pragma unroll
        for (int ni = 0; ni < 16; ni++) {
            sacc[ni][0] = __expf(sacc[ni][0] - nm0); s0 += sacc[ni][0];
            sacc[ni][1] = __expf(sacc[ni][1] - nm0); s0 += sacc[ni][1];
            sacc[ni][2] = __expf(sacc[ni][2] - nm1); s1 += sacc[ni][2];
            sacc[ni][3] = __expf(sacc[ni][3] - nm1); s1 += sacc[ni][3];
        }
        s0 += __shfl_xor_sync(0xffffffffu, s0, 1);
        s0 += __shfl_xor_sync(0xffffffffu, s0, 2);
        s1 += __shfl_xor_sync(0xffffffffu, s1, 1);
        s1 += __shfl_xor_sync(0xffffffffu, s1, 2);
        l0 = l0 * f0 + s0;
        l1 = l1 * f1 + s1;
        #pragma unroll
        for (int nj = 0; nj < 8; nj++) {
            ctx[nj][0] *= f0; ctx[nj][1] *= f0;
            ctx[nj][2] *= f1; ctx[nj][3] *= f1;
        }

        // ---- ctx += P * V  (P repacked in-register) ----
        #pragma unroll
        for (int kc = 0; kc < 8; kc++) {
            uint32_t a[4];
            a[0] = pack2(sacc[2*kc    ][0], sacc[2*kc    ][1]);
            a[1] = pack2(sacc[2*kc    ][2], sacc[2*kc    ][3]);
            a[2] = pack2(sacc[2*kc + 1][0], sacc[2*kc + 1][1]);
            a[3] = pack2(sacc[2*kc + 1][2], sacc[2*kc + 1][3]);
            #pragma unroll
            for (int nj = 0; nj < 8; nj++) {
                uint32_t bf[2];
                const __half* q = Vt + (nj*8 + gid)*136 + kc*16 + 2*tig;
                bf[0] = *(const uint32_t*)q;
                bf[1] = *(const uint32_t*)(q + 8);
                mma16(ctx[nj], a, bf);
            }
        }

        __syncthreads();
        if (kt + 2 < 8) {
            const int nk = kt + 2, buf = kt & 1;
            #pragma unroll
            for (int i = 0; i < 8; i++) {
                int idx = i*128 + tid; int r = idx >> 3, c = (idx & 7) * 8;
                cpa16(Kb + buf*9216 + r*72 + c, Kg + (size_t)(nk*128 + r)*HD + c);
            }
            #pragma unroll
            for (int i = 0; i < 8; i++) {
                int idx = i*128 + tid; int r = idx >> 4, c = (idx & 15) * 8;
                cpa16(Vb + buf*8704 + r*136 + c, Vg + (size_t)r*SEQ + nk*128 + c);
            }
            CPA_COMMIT();
        }
    }

    // ---- epilogue: normalize, write ctx tile ----
    const float i0 = __fdividef(1.0f, l0), i1 = __fdividef(1.0f, l1);
    const int tok0 = b*SEQ + m0 + wr + gid, tok1 = tok0 + 8;
    #pragma unroll
    for (int nj = 0; nj < 8; nj++) {
        int c = h*HD + nj*8 + tig*2;
        *(__half2*)&g_ctxh[(size_t)tok0*DM + c] =
            __floats2half2_rn(ctx[nj][0]*i0, ctx[nj][1]*i0);
        *(__half2*)&g_ctxh[(size_t)tok1*DM + c] =
            __floats2half2_rn(ctx[nj][2]*i1, ctx[nj][3]*i1);
    }
}

// ---------------- small kernels ---------------------------------------------
// z-fused transpose of the four DM x DM weights
__global__ void __launch_bounds__(256)
wtrans4_kernel(const float* __restrict__ Wq, const float* __restrict__ Wk,
               const float* __restrict__ Wv, const float* __restrict__ Wo)
{
    const float* S = (blockIdx.z == 0) ? Wq : (blockIdx.z == 1) ? Wk
                   : (blockIdx.z == 2) ? Wv : Wo;
    __half* D = g_wT + (size_t)blockIdx.z * DM * DM;
    __shared__ float t[32][33];
    const int k0 = blockIdx.y * 32, n0 = blockIdx.x * 32;
    const int tx = threadIdx.x & 31, ty = threadIdx.x >> 5;
    #pragma unroll
    for (int i = 0; i < 32; i += 8)
        t[ty + i][tx] = S[(size_t)(k0 + ty + i) * DM + n0 + tx];
    __syncthreads();
    #pragma unroll
    for (int i = 0; i < 32; i += 8)
        D[(size_t)(n0 + ty + i) * DM + k0 + tx] = __float2half(t[tx][ty + i]);
}

__global__ void __launch_bounds__(256)
wtrans_kernel(const float* __restrict__ S, __half* __restrict__ D, int K, int N)
{
    __shared__ float t[32][33];
    const int k0 = blockIdx.y * 32, n0 = blockIdx.x * 32;
    const int tx = threadIdx.x & 31, ty = threadIdx.x >> 5;
    #pragma unroll
    for (int i = 0; i < 32; i += 8)
        t[ty + i][tx] = S[(size_t)(k0 + ty + i) * N + n0 + tx];
    __syncthreads();
    #pragma unroll
    for (int i = 0; i < 32; i += 8)
        D[(size_t)(n0 + ty + i) * K + k0 + tx] = __float2half(t[tx][ty + i]);
}

template<int HOUT>
__global__ void __launch_bounds__(256)
ln_kernel(const float* __restrict__ X, const float* __restrict__ g,
          const float* __restrict__ bb, float* __restrict__ Y, __half* __restrict__ Yh)
{
    __shared__ float red[16];
    const int tid = threadIdx.x;
    const size_t off = (size_t)blockIdx.x << 10;
    float4 v = ((const float4*)(X + off))[tid];

    float s  = v.x + v.y + v.z + v.w;
    float s2 = v.x*v.x + v.y*v.y + v.z*v.z + v.w*v.w;
    s = warpSum(s); s2 = warpSum(s2);
    if ((tid & 31) == 0) { red[tid >> 5] = s; red[8 + (tid >> 5)] = s2; }
    __syncthreads();
    float S = 0.f, S2 = 0.f;
    #pragma unroll
    for (int i = 0; i < 8; i++) { S += red[i]; S2 += red[8 + i]; }
    float mu  = S * (1.0f / 1024.0f);
    float var = S2 * (1.0f / 1024.0f) - mu * mu;
    float rs  = rsqrtf(var + 1e-6f);

    float4 gv = ((const float4*)g)[tid];
    float4 bv = ((const float4*)bb)[tid];
    float4 o;
    o.x = (v.x - mu) * rs * gv.x + bv.x;
    o.y = (v.y - mu) * rs * gv.y + bv.y;
    o.z = (v.z - mu) * rs * gv.z + bv.z;
    o.w = (v.w - mu) * rs * gv.w + bv.w;
    ((float4*)(Y + off))[tid] = o;
    if (HOUT) {
        __half2* ph = (__half2*)(Yh + off);
        ph[tid*2+0] = __floats2half2_rn(o.x, o.y);
        ph[tid*2+1] = __floats2half2_rn(o.z, o.w);
    }
}

__global__ void __launch_bounds__(256)
f2h_kernel(const float* __restrict__ S, __half* __restrict__ D)
{
    size_t i = (size_t)blockIdx.x * 1024 + threadIdx.x * 4;
    float4 v = *(const float4*)(S + i);
    ((__half2*)(D + i))[0] = __floats2half2_rn(v.x, v.y);
    ((__half2*)(D + i))[1] = __floats2half2_rn(v.z, v.w);
}

// ---------------- launch -----------------------------------------------------
extern "C" void kernel_launch(void* const* d_in, const int* in_sizes, int n_in,
                              void* d_out, int out_size)
{
    const float* x   = (const float*)d_in[0];
    const int*   rid = (const int*)  d_in[1];
    const float* Wq  = (const float*)d_in[2];
    const float* bq  = (const float*)d_in[3];
    const float* Wk  = (const float*)d_in[4];
    const float* bk  = (const float*)d_in[5];
    const float* Wv  = (const float*)d_in[6];
    const float* bv  = (const float*)d_in[7];
    const float* Wo  = (const float*)d_in[8];
    const float* bo  = (const float*)d_in[9];
    const float* Ek  = (const float*)d_in[10];
    const float* Eb  = (const float*)d_in[11];
    const float* g1  = (const float*)d_in[12];
    const float* b1  = (const float*)d_in[13];
    const float* g2  = (const float*)d_in[14];
    const float* b2  = (const float*)d_in[15];
    const float* W1  = (const float*)d_in[16];
    const float* bf1 = (const float*)d_in[17];
    const float* W2  = (const float*)d_in[18];
    const float* bf2 = (const float*)d_in[19];
    float* out = (float*)d_out;

    __half *p_wT, *p_xh, *p_ctxh, *p_ffinh, *p_h1h;
    float  *p_t, *p_ffin;
    cudaGetSymbolAddress((void**)&p_wT,    g_wT);
    cudaGetSymbolAddress((void**)&p_xh,    g_xh);
    cudaGetSymbolAddress((void**)&p_ctxh,  g_ctxh);
    cudaGetSymbolAddress((void**)&p_ffinh, g_ffinh);
    cudaGetSymbolAddress((void**)&p_h1h,   g_h1h);
    cudaGetSymbolAddress((void**)&p_t,     g_t);
    cudaGetSymbolAddress((void**)&p_ffin,  g_ffin);

    __half* WoT = p_wT + (size_t)3*DM*DM;
    __half* W1T = p_wT + (size_t)4*DM*DM;            // [FFN][DM]
    __half* W2T = p_wT + (size_t)4*DM*DM + DM*FFN_D; // [DM][FFN]

    static int smem_set = 0;
    if (!smem_set) {
        cudaFuncSetAttribute(attn_flash, cudaFuncAttributeMaxDynamicSharedMemorySize, FA_SMEM);
        smem_set = 1;
    }

    const dim3 blk(256);

    // 0. operand conversion
    wtrans4_kernel<<<dim3(DM/32, DM/32, 4), blk>>>(Wq, Wk, Wv, Wo);
    wtrans_kernel<<<dim3(FFN_D/32, DM/32),  blk>>>(W1, W1T, DM, FFN_D);
    wtrans_kernel<<<dim3(DM/32,  FFN_D/32), blk>>>(W2, W2T, FFN_D, DM);
    f2h_kernel<<<ROWS*DM/1024, blk>>>(x, p_xh);

    // 1. QKV projections
    proj_h<<<dim3(DM/128, ROWS/128, 3), blk>>>(p_xh, bq, bk, bv);

    // 2. qE = Q @ Ek^T
    qe_kernel<<<BHN * SEQ / 64, blk>>>(Ek);

    // 3-5. flash attention (scores + rel terms + softmax + ctx, fused)
    attn_flash<<<dim3(SEQ/64, BHN), dim3(128), FA_SMEM>>>(Eb, rid);

    // 6. t = x + ctx @ Wo + bo
    hgemm<3><<<dim3(DM/128, ROWS/128), blk>>>(p_ctxh, WoT, bo, x, p_t, DM, DM);

    // 7. ff_in = LN1(t)
    ln_kernel<1><<<ROWS, blk>>>(p_t, g1, b1, p_ffin, p_ffinh);

    // 8. h1 = relu(ff_in @ W1 + bf1) -> half
    hgemm<2><<<dim3(FFN_D/128, ROWS/128), blk>>>(p_ffinh, W1T, bf1, nullptr, p_h1h, DM, FFN_D);

    // 9. t = ff_in + h1 @ W2 + bf2
    hgemm<3><<<dim3(DM/128, ROWS/128), blk>>>(p_h1h, W2T, bf2, p_ffin, p_t, FFN_D, DM);

    // 10. out = LN2(t)
    ln_kernel<0><<<ROWS, blk>>>(p_t, g2, b2, out, nullptr);
}

// round 15
// speedup vs baseline: 4.3379x; 1.0875x over previous
#include <cuda_runtime.h>
#include <cuda_fp16.h>
#include <cstdint>

#define SEQ    1024
#define DM     1024
#define NH     16
#define HD     64
#define BATCH  4
#define FFN_D  4096
#define NREL   64
#define BHN    (BATCH*NH)      // 64
#define ROWS   (BATCH*SEQ)     // 4096

// ---------------- scratch (device globals; no runtime allocation) ----------
__device__ __half g_qh  [BHN*SEQ*HD];        // 8 MB  [bh][s][d]
__device__ __half g_kh  [BHN*SEQ*HD];        // 8 MB  [bh][s][d]
__device__ __half g_vt  [BHN*HD*SEQ];        // 8 MB  [bh][d][s]  (transposed V)
__device__ float  g_qe  [BHN*SEQ*NREL];      // 16 MB
__device__ __half g_ctxh[ROWS*DM];           // 8 MB
__device__ float  g_t   [ROWS*DM];           // 16 MB
__device__ float  g_ffin[ROWS*DM];           // 16 MB
__device__ __half g_ffinh[ROWS*DM];          // 8 MB
__device__ __half g_h1h [ROWS*FFN_D];        // 32 MB
__device__ __half g_wT  [4*DM*DM + 2*DM*FFN_D];  // 24 MB
__device__ __half g_xh  [ROWS*DM];           // half copy of input x

// ---------------- helpers ---------------------------------------------------
__device__ __forceinline__ float warpSum(float v) {
    #pragma unroll
    for (int o = 16; o; o >>= 1) v += __shfl_xor_sync(0xffffffffu, v, o);
    return v;
}
__device__ __forceinline__ void cpa16(void* dst, const void* src) {
    uint32_t d = (uint32_t)__cvta_generic_to_shared(dst);
    asm volatile("cp.async.cg.shared.global [%0], [%1], 16;\n" :: "r"(d), "l"(src));
}
#define CPA_COMMIT() asm volatile("cp.async.commit_group;\n" ::: "memory")
#define CPA_WAIT0()  asm volatile("cp.async.wait_group 0;\n" ::: "memory")
#define CPA_WAIT1()  asm volatile("cp.async.wait_group 1;\n" ::: "memory")

__device__ __forceinline__ void mma16(float* d, const uint32_t* a, const uint32_t* b) {
    asm volatile(
        "mma.sync.aligned.m16n8k16.row.col.f32.f16.f16.f32 "
        "{%0,%1,%2,%3}, {%4,%5,%6,%7}, {%8,%9}, {%0,%1,%2,%3};\n"
        : "+f"(d[0]), "+f"(d[1]), "+f"(d[2]), "+f"(d[3])
        : "r"(a[0]), "r"(a[1]), "r"(a[2]), "r"(a[3]), "r"(b[0]), "r"(b[1]));
}
__device__ __forceinline__ void ldm4(uint32_t* r, uint32_t addr) {
    asm volatile("ldmatrix.sync.aligned.m8n8.x4.shared.b16 {%0,%1,%2,%3}, [%4];"
        : "=r"(r[0]), "=r"(r[1]), "=r"(r[2]), "=r"(r[3]) : "r"(addr));
}
__device__ __forceinline__ uint32_t pack2(float a, float b) {
    __half2 h = __floats2half2_rn(a, b);
    return *(uint32_t*)&h;
}

// ================= 3-stage ldmatrix TN GEMM core =============================
// Tile 128x128, BK=32, 8 warps (2M x 4N), warp tile 64x32.
// Stage layout: A[128][40]h then B[128][40]h -> 20480 B per stage, 3 stages.
#define G_STG   20480
#define G_SMEM  (3*G_STG)

__device__ __forceinline__ void ld_stage(char* smp, int st, const __half* Ag,
                                         const __half* Bg, int K, int k0, int tid)
{
    char* A = smp + st * G_STG;
    char* B = A + 10240;
    #pragma unroll
    for (int i = 0; i < 2; i++) {
        int idx = i * 256 + tid;
        int r = idx >> 2, c = (idx & 3) * 8;
        cpa16(A + (r*40 + c)*2, Ag + (size_t)r * K + k0 + c);
        cpa16(B + (r*40 + c)*2, Bg + (size_t)r * K + k0 + c);
    }
    CPA_COMMIT();
}

// compute one BK=32 stage via ldmatrix fragments
__device__ __forceinline__ void ldm_step(uint32_t su, int st, int wm, int wn,
                                         int lane, float (&acc)[4][4][4])
{
    const int grp = lane >> 3, lr = lane & 7;
    const uint32_t arow = (grp & 1) * 8 + lr, acol = (grp >> 1) * 8;
    const uint32_t brow = (grp >> 1) * 8 + lr, bcol = (grp & 1) * 8;
    const uint32_t sA = su + st * G_STG;
    const uint32_t sB = sA + 10240;

    #pragma unroll
    for (int ks = 0; ks < 2; ks++) {
        const int kk = ks * 16;
        uint32_t af[4][4], bf[4][2];
        #pragma unroll
        for (int mi = 0; mi < 4; mi++)
            ldm4(af[mi], sA + ((wm + mi*16 + arow)*40 + kk + acol)*2);
        #pragma unroll
        for (int p = 0; p < 2; p++) {
            uint32_t t4[4];
            ldm4(t4, sB + ((wn + p*16 + brow)*40 + kk + bcol)*2);
            bf[2*p  ][0] = t4[0]; bf[2*p  ][1] = t4[1];
            bf[2*p+1][0] = t4[2]; bf[2*p+1][1] = t4[3];
        }
        #pragma unroll
        for (int mi = 0; mi < 4; mi++)
            #pragma unroll
            for (int ni = 0; ni < 4; ni++)
                mma16(acc[mi][ni], af[mi], bf[ni]);
    }
}

__device__ __forceinline__ void mainloop3(char* smp, uint32_t su,
                                          const __half* Ag, const __half* Bg,
                                          int K, int wm, int wn, int lane, int tid,
                                          float (&acc)[4][4][4])
{
    const int nt = K >> 5;
    ld_stage(smp, 0, Ag, Bg, K, 0, tid);
    ld_stage(smp, 1, Ag, Bg, K, 32, tid);
    int cs = 0, ls = 2;
    for (int t = 0; t < nt; t++) {
        if (t + 1 < nt) CPA_WAIT1(); else CPA_WAIT0();
        __syncthreads();
        if (t + 2 < nt) {
            ld_stage(smp, ls, Ag, Bg, K, (t + 2) << 5, tid);
            ls = (ls == 2) ? 0 : ls + 1;
        }
        ldm_step(su, cs, wm, wn, lane, acc);
        cs = (cs == 2) ? 0 : cs + 1;
    }
}

// ---------------- QKV projection (z-fused) -----------------------------------
__global__ void __launch_bounds__(256, 2)
proj_h(const __half* __restrict__ xh,
       const float* __restrict__ bq, const float* __restrict__ bk, const float* __restrict__ bv)
{
    extern __shared__ char smp[];
    const uint32_t su = (uint32_t)__cvta_generic_to_shared(smp);
    const int tid = threadIdx.x, warp = tid >> 5, lane = tid & 31;
    const int wm = (warp >> 2) * 64, wn = (warp & 3) * 32;
    const int gid = lane >> 2, tig = lane & 3;
    const int z = blockIdx.z;
    const int m0 = blockIdx.y * 128, n0 = blockIdx.x * 128;
    const __half* Ag = xh + (size_t)m0 * DM;
    const __half* Bg = g_wT + (size_t)z * DM * DM + (size_t)n0 * DM;
    const float* bias = (z == 0) ? bq : (z == 1) ? bk : bv;

    float acc[4][4][4] = {};
    mainloop3(smp, su, Ag, Bg, DM, wm, wn, lane, tid, acc);

    #pragma unroll
    for (int mi = 0; mi < 4; mi++) {
        int r0 = m0 + wm + mi * 16 + gid;
        #pragma unroll
        for (int ni = 0; ni < 4; ni++) {
            int c = n0 + wn + ni * 8 + tig * 2;
            int h = c >> 6, d = c & 63;
            float b0 = bias[c], b1 = bias[c + 1];
            #pragma unroll
            for (int rr = 0; rr < 2; rr++) {
                int row = r0 + rr * 8;
                int b = row >> 10, s = row & 1023;
                float v0 = acc[mi][ni][rr*2+0] + b0;
                float v1 = acc[mi][ni][rr*2+1] + b1;
                if (z < 2) {
                    __half* O = (z == 0) ? g_qh : g_kh;
                    *(__half2*)&O[((size_t)(b*NH + h) * SEQ + s) * HD + d] =
                        __floats2half2_rn(v0, v1);
                } else {
                    size_t vb = (size_t)(b*NH + h) * HD;
                    g_vt[(vb + d    ) * SEQ + s] = __float2half(v0);
                    g_vt[(vb + d + 1) * SEQ + s] = __float2half(v1);
                }
            }
        }
    }
}

// ---------------- generic half TN GEMM + epilogues ---------------------------
// EPI==2: relu(A@Bt^T + bias) -> half C ;  EPI==3: A@Bt^T + bias + R -> float C
template<int EPI>
__global__ void __launch_bounds__(256, 2)
hgemm(const __half* __restrict__ A, const __half* __restrict__ Bt,
      const float* __restrict__ bias, const float* __restrict__ R,
      void* __restrict__ Cout, int K, int N)
{
    extern __shared__ char smp[];
    const uint32_t su = (uint32_t)__cvta_generic_to_shared(smp);
    const int tid = threadIdx.x, warp = tid >> 5, lane = tid & 31;
    const int wm = (warp >> 2) * 64, wn = (warp & 3) * 32;
    const int gid = lane >> 2, tig = lane & 3;
    const int m0 = blockIdx.y * 128, n0 = blockIdx.x * 128;

    float acc[4][4][4] = {};
    mainloop3(smp, su, A + (size_t)m0 * K, Bt + (size_t)n0 * K, K, wm, wn, lane, tid, acc);

    #pragma unroll
    for (int mi = 0; mi < 4; mi++) {
        int r0 = m0 + wm + mi * 16 + gid;
        #pragma unroll
        for (int ni = 0; ni < 4; ni++) {
            int c = n0 + wn + ni * 8 + tig * 2;
            float b0 = bias[c], b1 = bias[c + 1];
            float v00 = acc[mi][ni][0] + b0, v01 = acc[mi][ni][1] + b1;
            float v10 = acc[mi][ni][2] + b0, v11 = acc[mi][ni][3] + b1;
            if (EPI == 2) {
                v00 = fmaxf(v00, 0.f); v01 = fmaxf(v01, 0.f);
                v10 = fmaxf(v10, 0.f); v11 = fmaxf(v11, 0.f);
                __half* C = (__half*)Cout;
                *(__half2*)(C + (size_t)r0 * N + c)       = __floats2half2_rn(v00, v01);
                *(__half2*)(C + (size_t)(r0 + 8) * N + c) = __floats2half2_rn(v10, v11);
            } else {
                float2 ra = *(const float2*)(R + (size_t)r0 * N + c);
                float2 rb = *(const float2*)(R + (size_t)(r0 + 8) * N + c);
                float* C = (float*)Cout;
                *(float2*)(C + (size_t)r0 * N + c)       = make_float2(v00 + ra.x, v01 + ra.y);
                *(float2*)(C + (size_t)(r0 + 8) * N + c) = make_float2(v10 + rb.x, v11 + rb.y);
            }
        }
    }
}

// ---------------- qE = Q @ Ek^T  ---------------------------------------------
__global__ void __launch_bounds__(256)
qe_kernel(const float* __restrict__ Ek)
{
    __shared__ float sQ [64][65];
    __shared__ float sEk[64][65];
    const int tid = threadIdx.x;
    const size_t row0 = (size_t)blockIdx.x * 64;

    for (int i = tid; i < 64*64; i += 256) {
        sQ [i >> 6][i & 63] = __half2float(g_qh[row0 * 64 + i]);
        sEk[i >> 6][i & 63] = Ek[i];
    }
    __syncthreads();

    const int r  = tid >> 2;
    const int nb = (tid & 3) * 16;
    float acc[16] = {};
    #pragma unroll
    for (int d = 0; d < 64; d++) {
        float qv = sQ[r][d];
        #pragma unroll
        for (int j = 0; j < 16; j++)
            acc[j] = fmaf(qv, sEk[nb + j][d], acc[j]);
    }
    #pragma unroll
    for (int j = 0; j < 16; j++)
        g_qe[(row0 + r) * 64 + nb + j] = acc[j];
}

// ================= flash attention (online softmax) ==========================
#define FA_SMEM 97536
#define FOFF_Q   0        // half [64][72]   9216 B
#define FOFF_QE  9216     // f32  [64][64]  16384 B
#define FOFF_EB  25600    // f32  [64]        256 B
#define FOFF_K   25856    // 2 x half[128][72] = 2x18432 B
#define FOFF_V   62720    // 2 x half[64][136] = 2x17408 B

__global__ void __launch_bounds__(128)
attn_flash(const float* __restrict__ Eb, const int* __restrict__ rid)
{
    extern __shared__ char sm[];
    __half* Qs  = (__half*)(sm + FOFF_Q);    // stride 72
    float*  QE  = (float*) (sm + FOFF_QE);   // stride 64
    float*  EBc = (float*) (sm + FOFF_EB);
    __half* Kb  = (__half*)(sm + FOFF_K);    // buffers of 9216 halves
    __half* Vb  = (__half*)(sm + FOFF_V);    // buffers of 8704 halves

    const int tid = threadIdx.x, warp = tid >> 5, lane = tid & 31;
    const int gid = lane >> 2, tig = lane & 3;
    const int bh = blockIdx.y, h = bh & 15, b = bh >> 4;
    const int m0 = blockIdx.x * 64;
    const int wr = warp * 16;

    const __half* Kg = g_kh + (size_t)bh * SEQ * HD;
    const __half* Vg = g_vt + (size_t)bh * HD * SEQ;

    #pragma unroll
    for (int i = 0; i < 4; i++) {
        int idx = i*128 + tid; int r = idx >> 3, c = (idx & 7) * 8;
        cpa16(Qs + r*72 + c, g_qh + (size_t)bh*SEQ*HD + (size_t)(m0 + r)*HD + c);
    }
    #pragma unroll
    for (int i = 0; i < 8; i++) {
        int idx = i*128 + tid; int r = idx >> 4, c = (idx & 15) * 4;
        cpa16(QE + r*64 + c, g_qe + ((size_t)bh*SEQ + m0 + r)*NREL + c);
    }
    if (tid < 64) EBc[tid] = Eb[tid*NH + h];
    #pragma unroll
    for (int i = 0; i < 8; i++) {
        int idx = i*128 + tid; int r = idx >> 3, c = (idx & 7) * 8;
        cpa16(Kb + r*72 + c, Kg + (size_t)r*HD + c);
    }
    #pragma unroll
    for (int i = 0; i < 8; i++) {
        int idx = i*128 + tid; int r = idx >> 4, c = (idx & 15) * 8;
        cpa16(Vb + r*136 + c, Vg + (size_t)r*SEQ + c);
    }
    CPA_COMMIT();
    #pragma unroll
    for (int i = 0; i < 8; i++) {
        int idx = i*128 + tid; int r = idx >> 3, c = (idx & 7) * 8;
        cpa16(Kb + 9216 + r*72 + c, Kg + (size_t)(128 + r)*HD + c);
    }
    #pragma unroll
    for (int i = 0; i < 8; i++) {
        int idx = i*128 + tid; int r = idx >> 4, c = (idx & 15) * 8;
        cpa16(Vb + 8704 + r*136 + c, Vg + (size_t)r*SEQ + 128 + c);
    }
    CPA_COMMIT();

    float m0r = -1e30f, m1r = -1e30f, l0 = 0.f, l1 = 0.f;
    float ctx[8][4] = {};

    for (int kt = 0; kt < 8; kt++) {
        if (kt < 7) CPA_WAIT1(); else CPA_WAIT0();
        __syncthreads();
        const __half* Kt = Kb + (kt & 1) * 9216;
        const __half* Vt = Vb + (kt & 1) * 8704;

        float sacc[16][4] = {};
        #pragma unroll
        for (int ks = 0; ks < 4; ks++) {
            const int kk = ks * 16;
            uint32_t af[4];
            const __half* p0 = Qs + (wr + gid)*72 + kk + 2*tig;
            const __half* p1 = p0 + 8*72;
            af[0] = *(const uint32_t*)p0;
            af[1] = *(const uint32_t*)p1;
            af[2] = *(const uint32_t*)(p0 + 8);
            af[3] = *(const uint32_t*)(p1 + 8);
            #pragma unroll
            for (int ni = 0; ni < 16; ni++) {
                uint32_t bf[2];
                const __half* q = Kt + (ni*8 + gid)*72 + kk + 2*tig;
                bf[0] = *(const uint32_t*)q;
                bf[1] = *(const uint32_t*)(q + 8);
                mma16(sacc[ni], af, bf);
            }
        }

        const int row0 = m0 + wr + gid, row1 = row0 + 8;
        const float* qe0 = QE + (wr + gid) * 64;
        const float* qe1 = qe0 + 8 * 64;
        float mx0 = -1e30f, mx1 = -1e30f;
        #pragma unroll
        for (int ni = 0; ni < 16; ni++) {
            int col = kt*128 + ni*8 + tig*2;
            int2 rd0 = *(const int2*)(rid + (size_t)row0*SEQ + col);
            int2 rd1 = *(const int2*)(rid + (size_t)row1*SEQ + col);
            sacc[ni][0] = (sacc[ni][0] + qe0[rd0.x] + EBc[rd0.x]) * 0.125f;
            sacc[ni][1] = (sacc[ni][1] + qe0[rd0.y] + EBc[rd0.y]) * 0.125f;
            sacc[ni][2] = (sacc[ni][2] + qe1[rd1.x] + EBc[rd1.x]) * 0.125f;
            sacc[ni][3] = (sacc[ni][3] + qe1[rd1.y] + EBc[rd1.y]) * 0.125f;
            mx0 = fmaxf(mx0, fmaxf(sacc[ni][0], sacc[ni][1]));
            mx1 = fmaxf(mx1, fmaxf(sacc[ni][2], sacc[ni][3]));
        }
        mx0 = fmaxf(mx0, __shfl_xor_sync(0xffffffffu, mx0, 1));
        mx0 = fmaxf(mx0, __shfl_xor_sync(0xffffffffu, mx0, 2));
        mx1 = fmaxf(mx1, __shfl_xor_sync(0xffffffffu, mx1, 1));
        mx1 = fmaxf(mx1, __shfl_xor_sync(0xffffffffu, mx1, 2));

        float nm0 = fmaxf(m0r, mx0), nm1 = fmaxf(m1r, mx1);
        float f0 = __expf(m0r - nm0), f1 = __expf(m1r - nm1);
        m0r = nm0; m1r = nm1;
        float s0 = 0.f, s1 = 0.f;
        #pragma unroll
        for (int ni = 0; ni < 16; ni++) {
            sacc[ni][0] = __expf(sacc[ni][0] - nm0); s0 += sacc[ni][0];
            sacc[ni][1] = __expf(sacc[ni][1] - nm0); s0 += sacc[ni][1];
            sacc[ni][2] = __expf(sacc[ni][2] - nm1); s1 += sacc[ni][2];
            sacc[ni][3] = __expf(sacc[ni][3] - nm1); s1 += sacc[ni][3];
        }
        s0 += __shfl_xor_sync(0xffffffffu, s0, 1);
        s0 += __shfl_xor_sync(0xffffffffu, s0, 2);
        s1 += __shfl_xor_sync(0xffffffffu, s1, 1);
        s1 += __shfl_xor_sync(0xffffffffu, s1, 2);
        l0 = l0 * f0 + s0;
        l1 = l1 * f1 + s1;
        #pragma unroll
        for (int nj = 0; nj < 8; nj++) {
            ctx[nj][0] *= f0; ctx[nj][1] *= f0;
            ctx[nj][2] *= f1; ctx[nj][3] *= f1;
        }

        #pragma unroll
        for (int kc = 0; kc < 8; kc++) {
            uint32_t a[4];
            a[0] = pack2(sacc[2*kc    ][0], sacc[2*kc    ][1]);
            a[1] = pack2(sacc[2*kc    ][2], sacc[2*kc    ][3]);
            a[2] = pack2(sacc[2*kc + 1][0], sacc[2*kc + 1][1]);
            a[3] = pack2(sacc[2*kc + 1][2], sacc[2*kc + 1][3]);
            #pragma unroll
            for (int nj = 0; nj < 8; nj++) {
                uint32_t bf[2];
                const __half* q = Vt + (nj*8 + gid)*136 + kc*16 + 2*tig;
                bf[0] = *(const uint32_t*)q;
                bf[1] = *(const uint32_t*)(q + 8);
                mma16(ctx[nj], a, bf);
            }
        }

        __syncthreads();
        if (kt + 2 < 8) {
            const int nk = kt + 2, buf = kt & 1;
            #pragma unroll
            for (int i = 0; i < 8; i++) {
                int idx = i*128 + tid; int r = idx >> 3, c = (idx & 7) * 8;
                cpa16(Kb + buf*9216 + r*72 + c, Kg + (size_t)(nk*128 + r)*HD + c);
            }
            #pragma unroll
            for (int i = 0; i < 8; i++) {
                int idx = i*128 + tid; int r = idx >> 4, c = (idx & 15) * 8;
                cpa16(Vb + buf*8704 + r*136 + c, Vg + (size_t)r*SEQ + nk*128 + c);
            }
            CPA_COMMIT();
        }
    }

    const float i0 = __fdividef(1.0f, l0), i1 = __fdividef(1.0f, l1);
    const int tok0 = b*SEQ + m0 + wr + gid, tok1 = tok0 + 8;
    #pragma unroll
    for (int nj = 0; nj < 8; nj++) {
        int c = h*HD + nj*8 + tig*2;
        *(__half2*)&g_ctxh[(size_t)tok0*DM + c] =
            __floats2half2_rn(ctx[nj][0]*i0, ctx[nj][1]*i0);
        *(__half2*)&g_ctxh[(size_t)tok1*DM + c] =
            __floats2half2_rn(ctx[nj][2]*i1, ctx[nj][3]*i1);
    }
}

// ---------------- small kernels ---------------------------------------------
__global__ void __launch_bounds__(256)
wtrans4_kernel(const float* __restrict__ Wq, const float* __restrict__ Wk,
               const float* __restrict__ Wv, const float* __restrict__ Wo)
{
    const float* S = (blockIdx.z == 0) ? Wq : (blockIdx.z == 1) ? Wk
                   : (blockIdx.z == 2) ? Wv : Wo;
    __half* D = g_wT + (size_t)blockIdx.z * DM * DM;
    __shared__ float t[32][33];
    const int k0 = blockIdx.y * 32, n0 = blockIdx.x * 32;
    const int tx = threadIdx.x & 31, ty = threadIdx.x >> 5;
    #pragma unroll
    for (int i = 0; i < 32; i += 8)
        t[ty + i][tx] = S[(size_t)(k0 + ty + i) * DM + n0 + tx];
    __syncthreads();
    #pragma unroll
    for (int i = 0; i < 32; i += 8)
        D[(size_t)(n0 + ty + i) * DM + k0 + tx] = __float2half(t[tx][ty + i]);
}

__global__ void __launch_bounds__(256)
wtrans_kernel(const float* __restrict__ S, __half* __restrict__ D, int K, int N)
{
    __shared__ float t[32][33];
    const int k0 = blockIdx.y * 32, n0 = blockIdx.x * 32;
    const int tx = threadIdx.x & 31, ty = threadIdx.x >> 5;
    #pragma unroll
    for (int i = 0; i < 32; i += 8)
        t[ty + i][tx] = S[(size_t)(k0 + ty + i) * N + n0 + tx];
    __syncthreads();
    #pragma unroll
    for (int i = 0; i < 32; i += 8)
        D[(size_t)(n0 + ty + i) * K + k0 + tx] = __float2half(t[tx][ty + i]);
}

template<int HOUT>
__global__ void __launch_bounds__(256)
ln_kernel(const float* __restrict__ X, const float* __restrict__ g,
          const float* __restrict__ bb, float* __restrict__ Y, __half* __restrict__ Yh)
{
    __shared__ float red[16];
    const int tid = threadIdx.x;
    const size_t off = (size_t)blockIdx.x << 10;
    float4 v = ((const float4*)(X + off))[tid];

    float s  = v.x + v.y + v.z + v.w;
    float s2 = v.x*v.x + v.y*v.y + v.z*v.z + v.w*v.w;
    s = warpSum(s); s2 = warpSum(s2);
    if ((tid & 31) == 0) { red[tid >> 5] = s; red[8 + (tid >> 5)] = s2; }
    __syncthreads();
    float S = 0.f, S2 = 0.f;
    #pragma unroll
    for (int i = 0; i < 8; i++) { S += red[i]; S2 += red[8 + i]; }
    float mu  = S * (1.0f / 1024.0f);
    float var = S2 * (1.0f / 1024.0f) - mu * mu;
    float rs  = rsqrtf(var + 1e-6f);

    float4 gv = ((const float4*)g)[tid];
    float4 bv = ((const float4*)bb)[tid];
    float4 o;
    o.x = (v.x - mu) * rs * gv.x + bv.x;
    o.y = (v.y - mu) * rs * gv.y + bv.y;
    o.z = (v.z - mu) * rs * gv.z + bv.z;
    o.w = (v.w - mu) * rs * gv.w + bv.w;
    ((float4*)(Y + off))[tid] = o;
    if (HOUT) {
        __half2* ph = (__half2*)(Yh + off);
        ph[tid*2+0] = __floats2half2_rn(o.x, o.y);
        ph[tid*2+1] = __floats2half2_rn(o.z, o.w);
    }
}

__global__ void __launch_bounds__(256)
f2h_kernel(const float* __restrict__ S, __half* __restrict__ D)
{
    size_t i = (size_t)blockIdx.x * 1024 + threadIdx.x * 4;
    float4 v = *(const float4*)(S + i);
    ((__half2*)(D + i))[0] = __floats2half2_rn(v.x, v.y);
    ((__half2*)(D + i))[1] = __floats2half2_rn(v.z, v.w);
}

// ---------------- launch -----------------------------------------------------
extern "C" void kernel_launch(void* const* d_in, const int* in_sizes, int n_in,
                              void* d_out, int out_size)
{
    const float* x   = (const float*)d_in[0];
    const int*   rid = (const int*)  d_in[1];
    const float* Wq  = (const float*)d_in[2];
    const float* bq  = (const float*)d_in[3];
    const float* Wk  = (const float*)d_in[4];
    const float* bk  = (const float*)d_in[5];
    const float* Wv  = (const float*)d_in[6];
    const float* bv  = (const float*)d_in[7];
    const float* Wo  = (const float*)d_in[8];
    const float* bo  = (const float*)d_in[9];
    const float* Ek  = (const float*)d_in[10];
    const float* Eb  = (const float*)d_in[11];
    const float* g1  = (const float*)d_in[12];
    const float* b1  = (const float*)d_in[13];
    const float* g2  = (const float*)d_in[14];
    const float* b2  = (const float*)d_in[15];
    const float* W1  = (const float*)d_in[16];
    const float* bf1 = (const float*)d_in[17];
    const float* W2  = (const float*)d_in[18];
    const float* bf2 = (const float*)d_in[19];
    float* out = (float*)d_out;

    __half *p_wT, *p_xh, *p_ctxh, *p_ffinh, *p_h1h;
    float  *p_t, *p_ffin;
    cudaGetSymbolAddress((void**)&p_wT,    g_wT);
    cudaGetSymbolAddress((void**)&p_xh,    g_xh);
    cudaGetSymbolAddress((void**)&p_ctxh,  g_ctxh);
    cudaGetSymbolAddress((void**)&p_ffinh, g_ffinh);
    cudaGetSymbolAddress((void**)&p_h1h,   g_h1h);
    cudaGetSymbolAddress((void**)&p_t,     g_t);
    cudaGetSymbolAddress((void**)&p_ffin,  g_ffin);

    __half* WoT = p_wT + (size_t)3*DM*DM;
    __half* W1T = p_wT + (size_t)4*DM*DM;            // [FFN][DM]
    __half* W2T = p_wT + (size_t)4*DM*DM + DM*FFN_D; // [DM][FFN]

    static int smem_set = 0;
    if (!smem_set) {
        cudaFuncSetAttribute(attn_flash, cudaFuncAttributeMaxDynamicSharedMemorySize, FA_SMEM);
        cudaFuncSetAttribute(proj_h,     cudaFuncAttributeMaxDynamicSharedMemorySize, G_SMEM);
        cudaFuncSetAttribute(hgemm<2>,   cudaFuncAttributeMaxDynamicSharedMemorySize, G_SMEM);
        cudaFuncSetAttribute(hgemm<3>,   cudaFuncAttributeMaxDynamicSharedMemorySize, G_SMEM);
        smem_set = 1;
    }

    const dim3 blk(256);

    // 0. operand conversion
    wtrans4_kernel<<<dim3(DM/32, DM/32, 4), blk>>>(Wq, Wk, Wv, Wo);
    wtrans_kernel<<<dim3(FFN_D/32, DM/32),  blk>>>(W1, W1T, DM, FFN_D);
    wtrans_kernel<<<dim3(DM/32,  FFN_D/32), blk>>>(W2, W2T, FFN_D, DM);
    f2h_kernel<<<ROWS*DM/1024, blk>>>(x, p_xh);

    // 1. QKV projections
    proj_h<<<dim3(DM/128, ROWS/128, 3), blk, G_SMEM>>>(p_xh, bq, bk, bv);

    // 2. qE = Q @ Ek^T
    qe_kernel<<<BHN * SEQ / 64, blk>>>(Ek);

    // 3-5. flash attention
    attn_flash<<<dim3(SEQ/64, BHN), dim3(128), FA_SMEM>>>(Eb, rid);

    // 6. t = x + ctx @ Wo + bo
    hgemm<3><<<dim3(DM/128, ROWS/128), blk, G_SMEM>>>(p_ctxh, WoT, bo, x, p_t, DM, DM);

    // 7. ff_in = LN1(t)
    ln_kernel<1><<<ROWS, blk>>>(p_t, g1, b1, p_ffin, p_ffinh);

    // 8. h1 = relu(ff_in @ W1 + bf1) -> half
    hgemm<2><<<dim3(FFN_D/128, ROWS/128), blk, G_SMEM>>>(p_ffinh, W1T, bf1, nullptr, p_h1h, DM, FFN_D);

    // 9. t = ff_in + h1 @ W2 + bf2
    hgemm<3><<<dim3(DM/128, ROWS/128), blk, G_SMEM>>>(p_h1h, W2T, bf2, p_ffin, p_t, FFN_D, DM);

    // 10. out = LN2(t)
    ln_kernel<0><<<ROWS, blk>>>(p_t, g2, b2, out, nullptr);
}

// round 16
// speedup vs baseline: 4.7227x; 1.0887x over previous
#include <cuda_runtime.h>
#include <cuda_fp16.h>
#include <cstdint>

#define SEQ    1024
#define DM     1024
#define NH     16
#define HD     64
#define BATCH  4
#define FFN_D  4096
#define NREL   64
#define BHN    (BATCH*NH)      // 64
#define ROWS   (BATCH*SEQ)     // 4096

// ---------------- scratch (device globals; no runtime allocation) ----------
__device__ __half  g_qh  [BHN*SEQ*HD];       // 8 MB  [bh][s][d]
__device__ __half  g_kh  [BHN*SEQ*HD];       // 8 MB  [bh][s][d]
__device__ __half  g_vt  [BHN*HD*SEQ];       // 8 MB  [bh][d][s]
__device__ float   g_qe  [BHN*SEQ*NREL];     // 16 MB
__device__ __half  g_ctxh[ROWS*DM];          // 8 MB
__device__ float   g_t   [ROWS*DM];          // 16 MB
__device__ float   g_ffin[ROWS*DM];          // 16 MB
__device__ __half  g_ffinh[ROWS*DM];         // 8 MB
__device__ __half  g_h1h [ROWS*FFN_D];       // 32 MB
__device__ __half  g_wT  [4*DM*DM + 2*DM*FFN_D];  // 24 MB
__device__ __half  g_xh  [ROWS*DM];          // half copy of input x
__device__ uint8_t g_rid8[SEQ*SEQ];          // 1 MB  u8 copy of relative_ids

// ---------------- helpers ---------------------------------------------------
__device__ __forceinline__ float warpSum(float v) {
    #pragma unroll
    for (int o = 16; o; o >>= 1) v += __shfl_xor_sync(0xffffffffu, v, o);
    return v;
}
__device__ __forceinline__ void cpa16(void* dst, const void* src) {
    uint32_t d = (uint32_t)__cvta_generic_to_shared(dst);
    asm volatile("cp.async.cg.shared.global [%0], [%1], 16;\n" :: "r"(d), "l"(src));
}
#define CPA_COMMIT() asm volatile("cp.async.commit_group;\n" ::: "memory")
#define CPA_WAIT0()  asm volatile("cp.async.wait_group 0;\n" ::: "memory")
#define CPA_WAIT1()  asm volatile("cp.async.wait_group 1;\n" ::: "memory")
#define CPA_WAIT2()  asm volatile("cp.async.wait_group 2;\n" ::: "memory")

__device__ __forceinline__ void mma16(float* d, const uint32_t* a, const uint32_t* b) {
    asm volatile(
        "mma.sync.aligned.m16n8k16.row.col.f32.f16.f16.f32 "
        "{%0,%1,%2,%3}, {%4,%5,%6,%7}, {%8,%9}, {%0,%1,%2,%3};\n"
        : "+f"(d[0]), "+f"(d[1]), "+f"(d[2]), "+f"(d[3])
        : "r"(a[0]), "r"(a[1]), "r"(a[2]), "r"(a[3]), "r"(b[0]), "r"(b[1]));
}
__device__ __forceinline__ void ldm4(uint32_t* r, uint32_t addr) {
    asm volatile("ldmatrix.sync.aligned.m8n8.x4.shared.b16 {%0,%1,%2,%3}, [%4];"
        : "=r"(r[0]), "=r"(r[1]), "=r"(r[2]), "=r"(r[3]) : "r"(addr));
}
__device__ __forceinline__ uint32_t pack2(float a, float b) {
    __half2 h = __floats2half2_rn(a, b);
    return *(uint32_t*)&h;
}

// ================= 4-stage ldmatrix TN GEMM core =============================
// Tile 128x128, BK=32, 8 warps (2M x 4N), warp tile 64x32.
// Stage: A[128][40]h then B[128][40]h -> 20480 B, 4 stages.
#define G_STG   20480
#define G_SMEM  (4*G_STG)

__device__ __forceinline__ void ld_stage(char* smp, int st, const __half* Ag,
                                         const __half* Bg, int K, int k0, int tid)
{
    char* A = smp + st * G_STG;
    char* B = A + 10240;
    #pragma unroll
    for (int i = 0; i < 2; i++) {
        int idx = i * 256 + tid;
        int r = idx >> 2, c = (idx & 3) * 8;
        cpa16(A + (r*40 + c)*2, Ag + (size_t)r * K + k0 + c);
        cpa16(B + (r*40 + c)*2, Bg + (size_t)r * K + k0 + c);
    }
    CPA_COMMIT();
}

__device__ __forceinline__ void ldm_step(uint32_t su, int st, int wm, int wn,
                                         int lane, float (&acc)[4][4][4])
{
    const int grp = lane >> 3, lr = lane & 7;
    const uint32_t arow = (grp & 1) * 8 + lr, acol = (grp >> 1) * 8;
    const uint32_t brow = (grp >> 1) * 8 + lr, bcol = (grp & 1) * 8;
    const uint32_t sA = su + st * G_STG;
    const uint32_t sB = sA + 10240;

    #pragma unroll
    for (int ks = 0; ks < 2; ks++) {
        const int kk = ks * 16;
        uint32_t af[4][4], bf[4][2];
        #pragma unroll
        for (int mi = 0; mi < 4; mi++)
            ldm4(af[mi], sA + ((wm + mi*16 + arow)*40 + kk + acol)*2);
        #pragma unroll
        for (int p = 0; p < 2; p++) {
            uint32_t t4[4];
            ldm4(t4, sB + ((wn + p*16 + brow)*40 + kk + bcol)*2);
            bf[2*p  ][0] = t4[0]; bf[2*p  ][1] = t4[1];
            bf[2*p+1][0] = t4[2]; bf[2*p+1][1] = t4[3];
        }
        #pragma unroll
        for (int mi = 0; mi < 4; mi++)
            #pragma unroll
            for (int ni = 0; ni < 4; ni++)
                mma16(acc[mi][ni], af[mi], bf[ni]);
    }
}

__device__ __forceinline__ void mainloop4(char* smp, uint32_t su,
                                          const __half* Ag, const __half* Bg,
                                          int K, int wm, int wn, int lane, int tid,
                                          float (&acc)[4][4][4])
{
    const int nt = K >> 5;
    ld_stage(smp, 0, Ag, Bg, K, 0, tid);
    ld_stage(smp, 1, Ag, Bg, K, 32, tid);
    ld_stage(smp, 2, Ag, Bg, K, 64, tid);
    for (int t = 0; t < nt; t++) {
        if (t + 3 < nt)      CPA_WAIT2();
        else if (t + 2 < nt) CPA_WAIT1();
        else                 CPA_WAIT0();
        __syncthreads();
        if (t + 3 < nt)
            ld_stage(smp, (t + 3) & 3, Ag, Bg, K, (t + 3) << 5, tid);
        ldm_step(su, t & 3, wm, wn, lane, acc);
    }
}

// ---------------- QKV projection (z-fused) -----------------------------------
__global__ void __launch_bounds__(256, 2)
proj_h(const __half* __restrict__ xh,
       const float* __restrict__ bq, const float* __restrict__ bk, const float* __restrict__ bv)
{
    extern __shared__ char smp[];
    const uint32_t su = (uint32_t)__cvta_generic_to_shared(smp);
    const int tid = threadIdx.x, warp = tid >> 5, lane = tid & 31;
    const int wm = (warp >> 2) * 64, wn = (warp & 3) * 32;
    const int gid = lane >> 2, tig = lane & 3;
    const int z = blockIdx.z;
    const int m0 = blockIdx.y * 128, n0 = blockIdx.x * 128;
    const __half* Ag = xh + (size_t)m0 * DM;
    const __half* Bg = g_wT + (size_t)z * DM * DM + (size_t)n0 * DM;
    const float* bias = (z == 0) ? bq : (z == 1) ? bk : bv;

    float acc[4][4][4] = {};
    mainloop4(smp, su, Ag, Bg, DM, wm, wn, lane, tid, acc);

    #pragma unroll
    for (int mi = 0; mi < 4; mi++) {
        int r0 = m0 + wm + mi * 16 + gid;
        #pragma unroll
        for (int ni = 0; ni < 4; ni++) {
            int c = n0 + wn + ni * 8 + tig * 2;
            int h = c >> 6, d = c & 63;
            float b0 = bias[c], b1 = bias[c + 1];
            #pragma unroll
            for (int rr = 0; rr < 2; rr++) {
                int row = r0 + rr * 8;
                int b = row >> 10, s = row & 1023;
                float v0 = acc[mi][ni][rr*2+0] + b0;
                float v1 = acc[mi][ni][rr*2+1] + b1;
                if (z < 2) {
                    __half* O = (z == 0) ? g_qh : g_kh;
                    *(__half2*)&O[((size_t)(b*NH + h) * SEQ + s) * HD + d] =
                        __floats2half2_rn(v0, v1);
                } else {
                    size_t vb = (size_t)(b*NH + h) * HD;
                    g_vt[(vb + d    ) * SEQ + s] = __float2half(v0);
                    g_vt[(vb + d + 1) * SEQ + s] = __float2half(v1);
                }
            }
        }
    }
}

// ---------------- generic half TN GEMM + epilogues ---------------------------
template<int EPI>
__global__ void __launch_bounds__(256, 2)
hgemm(const __half* __restrict__ A, const __half* __restrict__ Bt,
      const float* __restrict__ bias, const float* __restrict__ R,
      void* __restrict__ Cout, int K, int N)
{
    extern __shared__ char smp[];
    const uint32_t su = (uint32_t)__cvta_generic_to_shared(smp);
    const int tid = threadIdx.x, warp = tid >> 5, lane = tid & 31;
    const int wm = (warp >> 2) * 64, wn = (warp & 3) * 32;
    const int gid = lane >> 2, tig = lane & 3;
    const int m0 = blockIdx.y * 128, n0 = blockIdx.x * 128;

    float acc[4][4][4] = {};
    mainloop4(smp, su, A + (size_t)m0 * K, Bt + (size_t)n0 * K, K, wm, wn, lane, tid, acc);

    #pragma unroll
    for (int mi = 0; mi < 4; mi++) {
        int r0 = m0 + wm + mi * 16 + gid;
        #pragma unroll
        for (int ni = 0; ni < 4; ni++) {
            int c = n0 + wn + ni * 8 + tig * 2;
            float b0 = bias[c], b1 = bias[c + 1];
            float v00 = acc[mi][ni][0] + b0, v01 = acc[mi][ni][1] + b1;
            float v10 = acc[mi][ni][2] + b0, v11 = acc[mi][ni][3] + b1;
            if (EPI == 2) {
                v00 = fmaxf(v00, 0.f); v01 = fmaxf(v01, 0.f);
                v10 = fmaxf(v10, 0.f); v11 = fmaxf(v11, 0.f);
                __half* C = (__half*)Cout;
                *(__half2*)(C + (size_t)r0 * N + c)       = __floats2half2_rn(v00, v01);
                *(__half2*)(C + (size_t)(r0 + 8) * N + c) = __floats2half2_rn(v10, v11);
            } else {
                float2 ra = *(const float2*)(R + (size_t)r0 * N + c);
                float2 rb = *(const float2*)(R + (size_t)(r0 + 8) * N + c);
                float* C = (float*)Cout;
                *(float2*)(C + (size_t)r0 * N + c)       = make_float2(v00 + ra.x, v01 + ra.y);
                *(float2*)(C + (size_t)(r0 + 8) * N + c) = make_float2(v10 + rb.x, v11 + rb.y);
            }
        }
    }
}

// ---------------- qE = Q @ Ek^T  ---------------------------------------------
__global__ void __launch_bounds__(256)
qe_kernel(const float* __restrict__ Ek)
{
    __shared__ float sQ [64][65];
    __shared__ float sEk[64][65];
    const int tid = threadIdx.x;
    const size_t row0 = (size_t)blockIdx.x * 64;

    for (int i = tid; i < 64*64; i += 256) {
        sQ [i >> 6][i & 63] = __half2float(g_qh[row0 * 64 + i]);
        sEk[i >> 6][i & 63] = Ek[i];
    }
    __syncthreads();

    const int r  = tid >> 2;
    const int nb = (tid & 3) * 16;
    float acc[16] = {};
    #pragma unroll
    for (int d = 0; d < 64; d++) {
        float qv = sQ[r][d];
        #pragma unroll
        for (int j = 0; j < 16; j++)
            acc[j] = fmaf(qv, sEk[nb + j][d], acc[j]);
    }
    #pragma unroll
    for (int j = 0; j < 16; j++)
        g_qe[(row0 + r) * 64 + nb + j] = acc[j];
}

// ================= flash attention (online softmax, ldmatrix frags) ==========
#define FA_SMEM 97536
#define FOFF_Q   0        // half [64][72]   9216 B
#define FOFF_QE  9216     // f32  [64][64]  16384 B
#define FOFF_EB  25600    // f32  [64]        256 B
#define FOFF_K   25856    // 2 x half[128][72] = 2x18432 B
#define FOFF_V   62720    // 2 x half[64][136] = 2x17408 B

__global__ void __launch_bounds__(128)
attn_flash(const float* __restrict__ Eb)
{
    extern __shared__ char sm[];
    const uint32_t su = (uint32_t)__cvta_generic_to_shared(sm);
    __half* Qs  = (__half*)(sm + FOFF_Q);
    float*  QE  = (float*) (sm + FOFF_QE);
    float*  EBc = (float*) (sm + FOFF_EB);
    __half* Kb  = (__half*)(sm + FOFF_K);
    __half* Vb  = (__half*)(sm + FOFF_V);

    const int tid = threadIdx.x, warp = tid >> 5, lane = tid & 31;
    const int gid = lane >> 2, tig = lane & 3;
    const int grp = lane >> 3, lr = lane & 7;
    const uint32_t arow = (grp & 1) * 8 + lr, acol = (grp >> 1) * 8;
    const uint32_t brow = (grp >> 1) * 8 + lr, bcol = (grp & 1) * 8;
    const int bh = blockIdx.y, h = bh & 15, b = bh >> 4;
    const int m0 = blockIdx.x * 64;
    const int wr = warp * 16;

    const __half* Kg = g_kh + (size_t)bh * SEQ * HD;
    const __half* Vg = g_vt + (size_t)bh * HD * SEQ;

    #pragma unroll
    for (int i = 0; i < 4; i++) {
        int idx = i*128 + tid; int r = idx >> 3, c = (idx & 7) * 8;
        cpa16(Qs + r*72 + c, g_qh + (size_t)bh*SEQ*HD + (size_t)(m0 + r)*HD + c);
    }
    #pragma unroll
    for (int i = 0; i < 8; i++) {
        int idx = i*128 + tid; int r = idx >> 4, c = (idx & 15) * 4;
        cpa16(QE + r*64 + c, g_qe + ((size_t)bh*SEQ + m0 + r)*NREL + c);
    }
    if (tid < 64) EBc[tid] = Eb[tid*NH + h];
    #pragma unroll
    for (int i = 0; i < 8; i++) {
        int idx = i*128 + tid; int r = idx >> 3, c = (idx & 7) * 8;
        cpa16(Kb + r*72 + c, Kg + (size_t)r*HD + c);
    }
    #pragma unroll
    for (int i = 0; i < 8; i++) {
        int idx = i*128 + tid; int r = idx >> 4, c = (idx & 15) * 8;
        cpa16(Vb + r*136 + c, Vg + (size_t)r*SEQ + c);
    }
    CPA_COMMIT();
    #pragma unroll
    for (int i = 0; i < 8; i++) {
        int idx = i*128 + tid; int r = idx >> 3, c = (idx & 7) * 8;
        cpa16(Kb + 9216 + r*72 + c, Kg + (size_t)(128 + r)*HD + c);
    }
    #pragma unroll
    for (int i = 0; i < 8; i++) {
        int idx = i*128 + tid; int r = idx >> 4, c = (idx & 15) * 8;
        cpa16(Vb + 8704 + r*136 + c, Vg + (size_t)r*SEQ + 128 + c);
    }
    CPA_COMMIT();

    float m0r = -1e30f, m1r = -1e30f, l0 = 0.f, l1 = 0.f;
    float ctx[8][4] = {};

    for (int kt = 0; kt < 8; kt++) {
        if (kt < 7) CPA_WAIT1(); else CPA_WAIT0();
        __syncthreads();
        const uint32_t sK = su + FOFF_K + (kt & 1) * 18432;
        const uint32_t sV = su + FOFF_V + (kt & 1) * 17408;

        // ---- S = Q K^T (ldmatrix fragments) ----
        float sacc[16][4] = {};
        #pragma unroll
        for (int ks = 0; ks < 4; ks++) {
            const int kk = ks * 16;
            uint32_t af[4];
            ldm4(af, su + FOFF_Q + ((wr + arow)*72 + kk + acol)*2);
            #pragma unroll
            for (int p = 0; p < 8; p++) {
                uint32_t t4[4];
                ldm4(t4, sK + ((p*16 + brow)*72 + kk + bcol)*2);
                uint32_t b0[2] = {t4[0], t4[1]};
                uint32_t b1[2] = {t4[2], t4[3]};
                mma16(sacc[2*p    ], af, b0);
                mma16(sacc[2*p + 1], af, b1);
            }
        }

        // ---- rel gathers (u8 rid) + scale + tile max ----
        const int row0 = m0 + wr + gid, row1 = row0 + 8;
        const uint8_t* rp0 = g_rid8 + (size_t)row0*SEQ;
        const uint8_t* rp1 = g_rid8 + (size_t)row1*SEQ;
        const float* qe0 = QE + (wr + gid) * 64;
        const float* qe1 = qe0 + 8 * 64;
        float mx0 = -1e30f, mx1 = -1e30f;
        #pragma unroll
        for (int ni = 0; ni < 16; ni++) {
            int col = kt*128 + ni*8 + tig*2;
            uchar2 rd0 = *(const uchar2*)(rp0 + col);
            uchar2 rd1 = *(const uchar2*)(rp1 + col);
            sacc[ni][0] = (sacc[ni][0] + qe0[rd0.x] + EBc[rd0.x]) * 0.125f;
            sacc[ni][1] = (sacc[ni][1] + qe0[rd0.y] + EBc[rd0.y]) * 0.125f;
            sacc[ni][2] = (sacc[ni][2] + qe1[rd1.x] + EBc[rd1.x]) * 0.125f;
            sacc[ni][3] = (sacc[ni][3] + qe1[rd1.y] + EBc[rd1.y]) * 0.125f;
            mx0 = fmaxf(mx0, fmaxf(sacc[ni][0], sacc[ni][1]));
            mx1 = fmaxf(mx1, fmaxf(sacc[ni][2], sacc[ni][3]));
        }
        mx0 = fmaxf(mx0, __shfl_xor_sync(0xffffffffu, mx0, 1));
        mx0 = fmaxf(mx0, __shfl_xor_sync(0xffffffffu, mx0, 2));
        mx1 = fmaxf(mx1, __shfl_xor_sync(0xffffffffu, mx1, 1));
        mx1 = fmaxf(mx1, __shfl_xor_sync(0xffffffffu, mx1, 2));

        float nm0 = fmaxf(m0r, mx0), nm1 = fmaxf(m1r, mx1);
        float f0 = __expf(m0r - nm0), f1 = __expf(m1r - nm1);
        m0r = nm0; m1r = nm1;
        float s0 = 0.f, s1 = 0.f;
        #pragma unroll
        for (int ni = 0; ni < 16; ni++) {
            sacc[ni][0] = __expf(sacc[ni][0] - nm0); s0 += sacc[ni][0];
            sacc[ni][1] = __expf(sacc[ni][1] - nm0); s0 += sacc[ni][1];
            sacc[ni][2] = __expf(sacc[ni][2] - nm1); s1 += sacc[ni][2];
            sacc[ni][3] = __expf(sacc[ni][3] - nm1); s1 += sacc[ni][3];
        }
        s0 += __shfl_xor_sync(0xffffffffu, s0, 1);
        s0 += __shfl_xor_sync(0xffffffffu, s0, 2);
        s1 += __shfl_xor_sync(0xffffffffu, s1, 1);
        s1 += __shfl_xor_sync(0xffffffffu, s1, 2);
        l0 = l0 * f0 + s0;
        l1 = l1 * f1 + s1;
        #pragma unroll
        for (int nj = 0; nj < 8; nj++) {
            ctx[nj][0] *= f0; ctx[nj][1] *= f0;
            ctx[nj][2] *= f1; ctx[nj][3] *= f1;
        }

        // ---- ctx += P * V (ldmatrix V fragments) ----
        #pragma unroll
        for (int kc = 0; kc < 8; kc++) {
            uint32_t a[4];
            a[0] = pack2(sacc[2*kc    ][0], sacc[2*kc    ][1]);
            a[1] = pack2(sacc[2*kc    ][2], sacc[2*kc    ][3]);
            a[2] = pack2(sacc[2*kc + 1][0], sacc[2*kc + 1][1]);
            a[3] = pack2(sacc[2*kc + 1][2], sacc[2*kc + 1][3]);
            #pragma unroll
            for (int p = 0; p < 4; p++) {
                uint32_t t4[4];
                ldm4(t4, sV + ((p*16 + brow)*136 + kc*16 + bcol)*2);
                uint32_t b0[2] = {t4[0], t4[1]};
                uint32_t b1[2] = {t4[2], t4[3]};
                mma16(ctx[2*p    ], a, b0);
                mma16(ctx[2*p + 1], a, b1);
            }
        }

        __syncthreads();
        if (kt + 2 < 8) {
            const int nk = kt + 2, buf = kt & 1;
            #pragma unroll
            for (int i = 0; i < 8; i++) {
                int idx = i*128 + tid; int r = idx >> 3, c = (idx & 7) * 8;
                cpa16(Kb + buf*9216 + r*72 + c, Kg + (size_t)(nk*128 + r)*HD + c);
            }
            #pragma unroll
            for (int i = 0; i < 8; i++) {
                int idx = i*128 + tid; int r = idx >> 4, c = (idx & 15) * 8;
                cpa16(Vb + buf*8704 + r*136 + c, Vg + (size_t)r*SEQ + nk*128 + c);
            }
            CPA_COMMIT();
        }
    }

    const float i0 = __fdividef(1.0f, l0), i1 = __fdividef(1.0f, l1);
    const int tok0 = b*SEQ + m0 + wr + gid, tok1 = tok0 + 8;
    #pragma unroll
    for (int nj = 0; nj < 8; nj++) {
        int c = h*HD + nj*8 + tig*2;
        *(__half2*)&g_ctxh[(size_t)tok0*DM + c] =
            __floats2half2_rn(ctx[nj][0]*i0, ctx[nj][1]*i0);
        *(__half2*)&g_ctxh[(size_t)tok1*DM + c] =
            __floats2half2_rn(ctx[nj][2]*i1, ctx[nj][3]*i1);
    }
}

// ---------------- small kernels ---------------------------------------------
__global__ void __launch_bounds__(256)
rid8_kernel(const int* __restrict__ rid)
{
    size_t i = (size_t)blockIdx.x * 1024 + threadIdx.x * 4;
    int4 v = *(const int4*)(rid + i);
    uchar4 o;
    o.x = (uint8_t)v.x; o.y = (uint8_t)v.y; o.z = (uint8_t)v.z; o.w = (uint8_t)v.w;
    *(uchar4*)(g_rid8 + i) = o;
}

__global__ void __launch_bounds__(256)
wtrans4_kernel(const float* __restrict__ Wq, const float* __restrict__ Wk,
               const float* __restrict__ Wv, const float* __restrict__ Wo)
{
    const float* S = (blockIdx.z == 0) ? Wq : (blockIdx.z == 1) ? Wk
                   : (blockIdx.z == 2) ? Wv : Wo;
    __half* D = g_wT + (size_t)blockIdx.z * DM * DM;
    __shared__ float t[32][33];
    const int k0 = blockIdx.y * 32, n0 = blockIdx.x * 32;
    const int tx = threadIdx.x & 31, ty = threadIdx.x >> 5;
    #pragma unroll
    for (int i = 0; i < 32; i += 8)
        t[ty + i][tx] = S[(size_t)(k0 + ty + i) * DM + n0 + tx];
    __syncthreads();
    #pragma unroll
    for (int i = 0; i < 32; i += 8)
        D[(size_t)(n0 + ty + i) * DM + k0 + tx] = __float2half(t[tx][ty + i]);
}

__global__ void __launch_bounds__(256)
wtrans_kernel(const float* __restrict__ S, __half* __restrict__ D, int K, int N)
{
    __shared__ float t[32][33];
    const int k0 = blockIdx.y * 32, n0 = blockIdx.x * 32;
    const int tx = threadIdx.x & 31, ty = threadIdx.x >> 5;
    #pragma unroll
    for (int i = 0; i < 32; i += 8)
        t[ty + i][tx] = S[(size_t)(k0 + ty + i) * N + n0 + tx];
    __syncthreads();
    #pragma unroll
    for (int i = 0; i < 32; i += 8)
        D[(size_t)(n0 + ty + i) * K + k0 + tx] = __float2half(t[tx][ty + i]);
}

template<int HOUT>
__global__ void __launch_bounds__(256)
ln_kernel(const float* __restrict__ X, const float* __restrict__ g,
          const float* __restrict__ bb, float* __restrict__ Y, __half* __restrict__ Yh)
{
    __shared__ float red[16];
    const int tid = threadIdx.x;
    const size_t off = (size_t)blockIdx.x << 10;
    float4 v = ((const float4*)(X + off))[tid];

    float s  = v.x + v.y + v.z + v.w;
    float s2 = v.x*v.x + v.y*v.y + v.z*v.z + v.w*v.w;
    s = warpSum(s); s2 = warpSum(s2);
    if ((tid & 31) == 0) { red[tid >> 5] = s; red[8 + (tid >> 5)] = s2; }
    __syncthreads();
    float S = 0.f, S2 = 0.f;
    #pragma unroll
    for (int i = 0; i < 8; i++) { S += red[i]; S2 += red[8 + i]; }
    float mu  = S * (1.0f / 1024.0f);
    float var = S2 * (1.0f / 1024.0f) - mu * mu;
    float rs  = rsqrtf(var + 1e-6f);

    float4 gv = ((const float4*)g)[tid];
    float4 bv = ((const float4*)bb)[tid];
    float4 o;
    o.x = (v.x - mu) * rs * gv.x + bv.x;
    o.y = (v.y - mu) * rs * gv.y + bv.y;
    o.z = (v.z - mu) * rs * gv.z + bv.z;
    o.w = (v.w - mu) * rs * gv.w + bv.w;
    ((float4*)(Y + off))[tid] = o;
    if (HOUT) {
        __half2* ph = (__half2*)(Yh + off);
        ph[tid*2+0] = __floats2half2_rn(o.x, o.y);
        ph[tid*2+1] = __floats2half2_rn(o.z, o.w);
    }
}

__global__ void __launch_bounds__(256)
f2h_kernel(const float* __restrict__ S, __half* __restrict__ D)
{
    size_t i = (size_t)blockIdx.x * 1024 + threadIdx.x * 4;
    float4 v = *(const float4*)(S + i);
    ((__half2*)(D + i))[0] = __floats2half2_rn(v.x, v.y);
    ((__half2*)(D + i))[1] = __floats2half2_rn(v.z, v.w);
}

// ---------------- launch -----------------------------------------------------
extern "C" void kernel_launch(void* const* d_in, const int* in_sizes, int n_in,
                              void* d_out, int out_size)
{
    const float* x   = (const float*)d_in[0];
    const int*   rid = (const int*)  d_in[1];
    const float* Wq  = (const float*)d_in[2];
    const float* bq  = (const float*)d_in[3];
    const float* Wk  = (const float*)d_in[4];
    const float* bk  = (const float*)d_in[5];
    const float* Wv  = (const float*)d_in[6];
    const float* bv  = (const float*)d_in[7];
    const float* Wo  = (const float*)d_in[8];
    const float* bo  = (const float*)d_in[9];
    const float* Ek  = (const float*)d_in[10];
    const float* Eb  = (const float*)d_in[11];
    const float* g1  = (const float*)d_in[12];
    const float* b1  = (const float*)d_in[13];
    const float* g2  = (const float*)d_in[14];
    const float* b2  = (const float*)d_in[15];
    const float* W1  = (const float*)d_in[16];
    const float* bf1 = (const float*)d_in[17];
    const float* W2  = (const float*)d_in[18];
    const float* bf2 = (const float*)d_in[19];
    float* out = (float*)d_out;

    __half *p_wT, *p_xh, *p_ctxh, *p_ffinh, *p_h1h;
    float  *p_t, *p_ffin;
    cudaGetSymbolAddress((void**)&p_wT,    g_wT);
    cudaGetSymbolAddress((void**)&p_xh,    g_xh);
    cudaGetSymbolAddress((void**)&p_ctxh,  g_ctxh);
    cudaGetSymbolAddress((void**)&p_ffinh, g_ffinh);
    cudaGetSymbolAddress((void**)&p_h1h,   g_h1h);
    cudaGetSymbolAddress((void**)&p_t,     g_t);
    cudaGetSymbolAddress((void**)&p_ffin,  g_ffin);

    __half* WoT = p_wT + (size_t)3*DM*DM;
    __half* W1T = p_wT + (size_t)4*DM*DM;            // [FFN][DM]
    __half* W2T = p_wT + (size_t)4*DM*DM + DM*FFN_D; // [DM][FFN]

    static int smem_set = 0;
    if (!smem_set) {
        cudaFuncSetAttribute(attn_flash, cudaFuncAttributeMaxDynamicSharedMemorySize, FA_SMEM);
        cudaFuncSetAttribute(proj_h,     cudaFuncAttributeMaxDynamicSharedMemorySize, G_SMEM);
        cudaFuncSetAttribute(hgemm<2>,   cudaFuncAttributeMaxDynamicSharedMemorySize, G_SMEM);
        cudaFuncSetAttribute(hgemm<3>,   cudaFuncAttributeMaxDynamicSharedMemorySize, G_SMEM);
        smem_set = 1;
    }

    const dim3 blk(256);

    // 0. operand conversion
    rid8_kernel<<<SEQ*SEQ/1024, blk>>>(rid);
    wtrans4_kernel<<<dim3(DM/32, DM/32, 4), blk>>>(Wq, Wk, Wv, Wo);
    wtrans_kernel<<<dim3(FFN_D/32, DM/32),  blk>>>(W1, W1T, DM, FFN_D);
    wtrans_kernel<<<dim3(DM/32,  FFN_D/32), blk>>>(W2, W2T, FFN_D, DM);
    f2h_kernel<<<ROWS*DM/1024, blk>>>(x, p_xh);

    // 1. QKV projections
    proj_h<<<dim3(DM/128, ROWS/128, 3), blk, G_SMEM>>>(p_xh, bq, bk, bv);

    // 2. qE = Q @ Ek^T
    qe_kernel<<<BHN * SEQ / 64, blk>>>(Ek);

    // 3-5. flash attention
    attn_flash<<<dim3(SEQ/64, BHN), dim3(128), FA_SMEM>>>(Eb);

    // 6. t = x + ctx @ Wo + bo
    hgemm<3><<<dim3(DM/128, ROWS/128), blk, G_SMEM>>>(p_ctxh, WoT, bo, x, p_t, DM, DM);

    // 7. ff_in = LN1(t)
    ln_kernel<1><<<ROWS, blk>>>(p_t, g1, b1, p_ffin, p_ffinh);

    // 8. h1 = relu(ff_in @ W1 + bf1) -> half
    hgemm<2><<<dim3(FFN_D/128, ROWS/128), blk, G_SMEM>>>(p_ffinh, W1T, bf1, nullptr, p_h1h, DM, FFN_D);

    // 9. t = ff_in + h1 @ W2 + bf2
    hgemm<3><<<dim3(DM/128, ROWS/128), blk, G_SMEM>>>(p_h1h, W2T, bf2, p_ffin, p_t, FFN_D, DM);

    // 10. out = LN2(t)
    ln_kernel<0><<<ROWS, blk>>>(p_t, g2, b2, out, nullptr);
}

// round 17
// speedup vs baseline: 4.9495x; 1.0480x over previous
#include <cuda_runtime.h>
#include <cuda_fp16.h>
#include <cstdint>

#define SEQ    1024
#define DM     1024
#define NH     16
#define HD     64
#define BATCH  4
#define FFN_D  4096
#define NREL   64
#define BHN    (BATCH*NH)      // 64
#define ROWS   (BATCH*SEQ)     // 4096

// ---------------- scratch (device globals; no runtime allocation) ----------
__device__ __half  g_qh  [BHN*SEQ*HD];       // 8 MB  [bh][s][d]
__device__ __half  g_kh  [BHN*SEQ*HD];       // 8 MB  [bh][s][d]
__device__ __half  g_vt  [BHN*HD*SEQ];       // 8 MB  [bh][d][s]
__device__ float   g_qe  [BHN*SEQ*NREL];     // 16 MB
__device__ __half  g_ctxh[ROWS*DM];          // 8 MB
__device__ float   g_t   [ROWS*DM];          // 16 MB
__device__ float   g_ffin[ROWS*DM];          // 16 MB
__device__ __half  g_ffinh[ROWS*DM];         // 8 MB
__device__ __half  g_h1h [ROWS*FFN_D];       // 32 MB
__device__ __half  g_wT  [4*DM*DM + 2*DM*FFN_D];  // 24 MB
__device__ __half  g_xh  [ROWS*DM];          // half copy of input x
__device__ uint8_t g_rid8[SEQ*SEQ];          // 1 MB  u8 copy of relative_ids

// ---------------- helpers ---------------------------------------------------
__device__ __forceinline__ float warpSum(float v) {
    #pragma unroll
    for (int o = 16; o; o >>= 1) v += __shfl_xor_sync(0xffffffffu, v, o);
    return v;
}
__device__ __forceinline__ void cpa16(void* dst, const void* src) {
    uint32_t d = (uint32_t)__cvta_generic_to_shared(dst);
    asm volatile("cp.async.cg.shared.global [%0], [%1], 16;\n" :: "r"(d), "l"(src));
}
#define CPA_COMMIT() asm volatile("cp.async.commit_group;\n" ::: "memory")
#define CPA_WAIT0()  asm volatile("cp.async.wait_group 0;\n" ::: "memory")
#define CPA_WAIT1()  asm volatile("cp.async.wait_group 1;\n" ::: "memory")

__device__ __forceinline__ void mma16(float* d, const uint32_t* a, const uint32_t* b) {
    asm volatile(
        "mma.sync.aligned.m16n8k16.row.col.f32.f16.f16.f32 "
        "{%0,%1,%2,%3}, {%4,%5,%6,%7}, {%8,%9}, {%0,%1,%2,%3};\n"
        : "+f"(d[0]), "+f"(d[1]), "+f"(d[2]), "+f"(d[3])
        : "r"(a[0]), "r"(a[1]), "r"(a[2]), "r"(a[3]), "r"(b[0]), "r"(b[1]));
}
__device__ __forceinline__ void ldm4(uint32_t* r, uint32_t addr) {
    asm volatile("ldmatrix.sync.aligned.m8n8.x4.shared.b16 {%0,%1,%2,%3}, [%4];"
        : "=r"(r[0]), "=r"(r[1]), "=r"(r[2]), "=r"(r[3]) : "r"(addr));
}
__device__ __forceinline__ uint32_t pack2(float a, float b) {
    __half2 h = __floats2half2_rn(a, b);
    return *(uint32_t*)&h;
}

// ================= 3-stage BK=64 ldmatrix TN GEMM core =======================
// Tile 128x128, BK=64, 8 warps (2M x 4N), warp tile 64x32.
// Stage: A[128][72]h then B[128][72]h -> 36864 B, 3 stages (110.6 KB).
// Row stride 72 halves = 144 B: ldmatrix 8-row phase hits banks {4r} -> CF.
#define G_STG   36864
#define G_SMEM  (3*G_STG)

__device__ __forceinline__ void ld_stage(char* smp, int st, const __half* Ag,
                                         const __half* Bg, int K, int k0, int tid)
{
    char* A = smp + st * G_STG;
    char* B = A + 18432;
    #pragma unroll
    for (int i = 0; i < 4; i++) {
        int idx = i * 256 + tid;
        int r = idx >> 3, c = (idx & 7) * 8;
        cpa16(A + (r*72 + c)*2, Ag + (size_t)r * K + k0 + c);
        cpa16(B + (r*72 + c)*2, Bg + (size_t)r * K + k0 + c);
    }
    CPA_COMMIT();
}

// compute one BK=64 stage (4 x k16) via ldmatrix fragments
__device__ __forceinline__ void ldm_step64(uint32_t su, int st, int wm, int wn,
                                           int lane, float (&acc)[4][4][4])
{
    const int grp = lane >> 3, lr = lane & 7;
    const uint32_t arow = (grp & 1) * 8 + lr, acol = (grp >> 1) * 8;
    const uint32_t brow = (grp >> 1) * 8 + lr, bcol = (grp & 1) * 8;
    const uint32_t sA = su + st * G_STG;
    const uint32_t sB = sA + 18432;

    #pragma unroll
    for (int ks = 0; ks < 4; ks++) {
        const int kk = ks * 16;
        uint32_t af[4][4], bf[4][2];
        #pragma unroll
        for (int mi = 0; mi < 4; mi++)
            ldm4(af[mi], sA + ((wm + mi*16 + arow)*72 + kk + acol)*2);
        #pragma unroll
        for (int p = 0; p < 2; p++) {
            uint32_t t4[4];
            ldm4(t4, sB + ((wn + p*16 + brow)*72 + kk + bcol)*2);
            bf[2*p  ][0] = t4[0]; bf[2*p  ][1] = t4[1];
            bf[2*p+1][0] = t4[2]; bf[2*p+1][1] = t4[3];
        }
        #pragma unroll
        for (int mi = 0; mi < 4; mi++)
            #pragma unroll
            for (int ni = 0; ni < 4; ni++)
                mma16(acc[mi][ni], af[mi], bf[ni]);
    }
}

__device__ __forceinline__ void mainloop64(char* smp, uint32_t su,
                                           const __half* Ag, const __half* Bg,
                                           int K, int wm, int wn, int lane, int tid,
                                           float (&acc)[4][4][4])
{
    const int nt = K >> 6;
    ld_stage(smp, 0, Ag, Bg, K, 0, tid);
    ld_stage(smp, 1, Ag, Bg, K, 64, tid);
    int cs = 0, ls = 2;
    for (int t = 0; t < nt; t++) {
        if (t + 1 < nt) CPA_WAIT1(); else CPA_WAIT0();
        __syncthreads();
        if (t + 2 < nt) {
            ld_stage(smp, ls, Ag, Bg, K, (t + 2) << 6, tid);
            ls = (ls == 2) ? 0 : ls + 1;
        }
        ldm_step64(su, cs, wm, wn, lane, acc);
        cs = (cs == 2) ? 0 : cs + 1;
    }
}

// ---------------- QKV projection (z-fused) -----------------------------------
__global__ void __launch_bounds__(256, 2)
proj_h(const __half* __restrict__ xh,
       const float* __restrict__ bq, const float* __restrict__ bk, const float* __restrict__ bv)
{
    extern __shared__ char smp[];
    const uint32_t su = (uint32_t)__cvta_generic_to_shared(smp);
    const int tid = threadIdx.x, warp = tid >> 5, lane = tid & 31;
    const int wm = (warp >> 2) * 64, wn = (warp & 3) * 32;
    const int gid = lane >> 2, tig = lane & 3;
    const int z = blockIdx.z;
    const int m0 = blockIdx.y * 128, n0 = blockIdx.x * 128;
    const __half* Ag = xh + (size_t)m0 * DM;
    const __half* Bg = g_wT + (size_t)z * DM * DM + (size_t)n0 * DM;
    const float* bias = (z == 0) ? bq : (z == 1) ? bk : bv;

    float acc[4][4][4] = {};
    mainloop64(smp, su, Ag, Bg, DM, wm, wn, lane, tid, acc);

    #pragma unroll
    for (int mi = 0; mi < 4; mi++) {
        int r0 = m0 + wm + mi * 16 + gid;
        #pragma unroll
        for (int ni = 0; ni < 4; ni++) {
            int c = n0 + wn + ni * 8 + tig * 2;
            int h = c >> 6, d = c & 63;
            float b0 = bias[c], b1 = bias[c + 1];
            #pragma unroll
            for (int rr = 0; rr < 2; rr++) {
                int row = r0 + rr * 8;
                int b = row >> 10, s = row & 1023;
                float v0 = acc[mi][ni][rr*2+0] + b0;
                float v1 = acc[mi][ni][rr*2+1] + b1;
                if (z < 2) {
                    __half* O = (z == 0) ? g_qh : g_kh;
                    *(__half2*)&O[((size_t)(b*NH + h) * SEQ + s) * HD + d] =
                        __floats2half2_rn(v0, v1);
                } else {
                    size_t vb = (size_t)(b*NH + h) * HD;
                    g_vt[(vb + d    ) * SEQ + s] = __float2half(v0);
                    g_vt[(vb + d + 1) * SEQ + s] = __float2half(v1);
                }
            }
        }
    }
}

// ---------------- generic half TN GEMM + epilogues ---------------------------
template<int EPI>
__global__ void __launch_bounds__(256, 2)
hgemm(const __half* __restrict__ A, const __half* __restrict__ Bt,
      const float* __restrict__ bias, const float* __restrict__ R,
      void* __restrict__ Cout, int K, int N)
{
    extern __shared__ char smp[];
    const uint32_t su = (uint32_t)__cvta_generic_to_shared(smp);
    const int tid = threadIdx.x, warp = tid >> 5, lane = tid & 31;
    const int wm = (warp >> 2) * 64, wn = (warp & 3) * 32;
    const int gid = lane >> 2, tig = lane & 3;
    const int m0 = blockIdx.y * 128, n0 = blockIdx.x * 128;

    float acc[4][4][4] = {};
    mainloop64(smp, su, A + (size_t)m0 * K, Bt + (size_t)n0 * K, K, wm, wn, lane, tid, acc);

    #pragma unroll
    for (int mi = 0; mi < 4; mi++) {
        int r0 = m0 + wm + mi * 16 + gid;
        #pragma unroll
        for (int ni = 0; ni < 4; ni++) {
            int c = n0 + wn + ni * 8 + tig * 2;
            float b0 = bias[c], b1 = bias[c + 1];
            float v00 = acc[mi][ni][0] + b0, v01 = acc[mi][ni][1] + b1;
            float v10 = acc[mi][ni][2] + b0, v11 = acc[mi][ni][3] + b1;
            if (EPI == 2) {
                v00 = fmaxf(v00, 0.f); v01 = fmaxf(v01, 0.f);
                v10 = fmaxf(v10, 0.f); v11 = fmaxf(v11, 0.f);
                __half* C = (__half*)Cout;
                *(__half2*)(C + (size_t)r0 * N + c)       = __floats2half2_rn(v00, v01);
                *(__half2*)(C + (size_t)(r0 + 8) * N + c) = __floats2half2_rn(v10, v11);
            } else {
                float2 ra = *(const float2*)(R + (size_t)r0 * N + c);
                float2 rb = *(const float2*)(R + (size_t)(r0 + 8) * N + c);
                float* C = (float*)Cout;
                *(float2*)(C + (size_t)r0 * N + c)       = make_float2(v00 + ra.x, v01 + ra.y);
                *(float2*)(C + (size_t)(r0 + 8) * N + c) = make_float2(v10 + rb.x, v11 + rb.y);
            }
        }
    }
}

// ---------------- qE = Q @ Ek^T  ---------------------------------------------
__global__ void __launch_bounds__(256)
qe_kernel(const float* __restrict__ Ek)
{
    __shared__ float sQ [64][65];
    __shared__ float sEk[64][65];
    const int tid = threadIdx.x;
    const size_t row0 = (size_t)blockIdx.x * 64;

    for (int i = tid; i < 64*64; i += 256) {
        sQ [i >> 6][i & 63] = __half2float(g_qh[row0 * 64 + i]);
        sEk[i >> 6][i & 63] = Ek[i];
    }
    __syncthreads();

    const int r  = tid >> 2;
    const int nb = (tid & 3) * 16;
    float acc[16] = {};
    #pragma unroll
    for (int d = 0; d < 64; d++) {
        float qv = sQ[r][d];
        #pragma unroll
        for (int j = 0; j < 16; j++)
            acc[j] = fmaf(qv, sEk[nb + j][d], acc[j]);
    }
    #pragma unroll
    for (int j = 0; j < 16; j++)
        g_qe[(row0 + r) * 64 + nb + j] = acc[j];
}

// ================= flash attention (online softmax, ldmatrix frags) ==========
#define FA_SMEM 97536
#define FOFF_Q   0        // half [64][72]   9216 B
#define FOFF_QE  9216     // f32  [64][64]  16384 B
#define FOFF_EB  25600    // f32  [64]        256 B
#define FOFF_K   25856    // 2 x half[128][72] = 2x18432 B
#define FOFF_V   62720    // 2 x half[64][136] = 2x17408 B

__global__ void __launch_bounds__(128)
attn_flash(const float* __restrict__ Eb)
{
    extern __shared__ char sm[];
    const uint32_t su = (uint32_t)__cvta_generic_to_shared(sm);
    __half* Qs  = (__half*)(sm + FOFF_Q);
    float*  QE  = (float*) (sm + FOFF_QE);
    float*  EBc = (float*) (sm + FOFF_EB);
    __half* Kb  = (__half*)(sm + FOFF_K);
    __half* Vb  = (__half*)(sm + FOFF_V);

    const int tid = threadIdx.x, warp = tid >> 5, lane = tid & 31;
    const int gid = lane >> 2, tig = lane & 3;
    const int grp = lane >> 3, lr = lane & 7;
    const uint32_t arow = (grp & 1) * 8 + lr, acol = (grp >> 1) * 8;
    const uint32_t brow = (grp >> 1) * 8 + lr, bcol = (grp & 1) * 8;
    const int bh = blockIdx.y, h = bh & 15, b = bh >> 4;
    const int m0 = blockIdx.x * 64;
    const int wr = warp * 16;

    const __half* Kg = g_kh + (size_t)bh * SEQ * HD;
    const __half* Vg = g_vt + (size_t)bh * HD * SEQ;

    #pragma unroll
    for (int i = 0; i < 4; i++) {
        int idx = i*128 + tid; int r = idx >> 3, c = (idx & 7) * 8;
        cpa16(Qs + r*72 + c, g_qh + (size_t)bh*SEQ*HD + (size_t)(m0 + r)*HD + c);
    }
    #pragma unroll
    for (int i = 0; i < 8; i++) {
        int idx = i*128 + tid; int r = idx >> 4, c = (idx & 15) * 4;
        cpa16(QE + r*64 + c, g_qe + ((size_t)bh*SEQ + m0 + r)*NREL + c);
    }
    if (tid < 64) EBc[tid] = Eb[tid*NH + h];
    #pragma unroll
    for (int i = 0; i < 8; i++) {
        int idx = i*128 + tid; int r = idx >> 3, c = (idx & 7) * 8;
        cpa16(Kb + r*72 + c, Kg + (size_t)r*HD + c);
    }
    #pragma unroll
    for (int i = 0; i < 8; i++) {
        int idx = i*128 + tid; int r = idx >> 4, c = (idx & 15) * 8;
        cpa16(Vb + r*136 + c, Vg + (size_t)r*SEQ + c);
    }
    CPA_COMMIT();
    #pragma unroll
    for (int i = 0; i < 8; i++) {
        int idx = i*128 + tid; int r = idx >> 3, c = (idx & 7) * 8;
        cpa16(Kb + 9216 + r*72 + c, Kg + (size_t)(128 + r)*HD + c);
    }
    #pragma unroll
    for (int i = 0; i < 8; i++) {
        int idx = i*128 + tid; int r = idx >> 4, c = (idx & 15) * 8;
        cpa16(Vb + 8704 + r*136 + c, Vg + (size_t)r*SEQ + 128 + c);
    }
    CPA_COMMIT();

    float m0r = -1e30f, m1r = -1e30f, l0 = 0.f, l1 = 0.f;
    float ctx[8][4] = {};

    for (int kt = 0; kt < 8; kt++) {
        if (kt < 7) CPA_WAIT1(); else CPA_WAIT0();
        __syncthreads();
        const uint32_t sK = su + FOFF_K + (kt & 1) * 18432;
        const uint32_t sV = su + FOFF_V + (kt & 1) * 17408;

        float sacc[16][4] = {};
        #pragma unroll
        for (int ks = 0; ks < 4; ks++) {
            const int kk = ks * 16;
            uint32_t af[4];
            ldm4(af, su + FOFF_Q + ((wr + arow)*72 + kk + acol)*2);
            #pragma unroll
            for (int p = 0; p < 8; p++) {
                uint32_t t4[4];
                ldm4(t4, sK + ((p*16 + brow)*72 + kk + bcol)*2);
                uint32_t b0[2] = {t4[0], t4[1]};
                uint32_t b1[2] = {t4[2], t4[3]};
                mma16(sacc[2*p    ], af, b0);
                mma16(sacc[2*p + 1], af, b1);
            }
        }

        const int row0 = m0 + wr + gid, row1 = row0 + 8;
        const uint8_t* rp0 = g_rid8 + (size_t)row0*SEQ;
        const uint8_t* rp1 = g_rid8 + (size_t)row1*SEQ;
        const float* qe0 = QE + (wr + gid) * 64;
        const float* qe1 = qe0 + 8 * 64;
        float mx0 = -1e30f, mx1 = -1e30f;
        #pragma unroll
        for (int ni = 0; ni < 16; ni++) {
            int col = kt*128 + ni*8 + tig*2;
            uchar2 rd0 = *(const uchar2*)(rp0 + col);
            uchar2 rd1 = *(const uchar2*)(rp1 + col);
            sacc[ni][0] = (sacc[ni][0] + qe0[rd0.x] + EBc[rd0.x]) * 0.125f;
            sacc[ni][1] = (sacc[ni][1] + qe0[rd0.y] + EBc[rd0.y]) * 0.125f;
            sacc[ni][2] = (sacc[ni][2] + qe1[rd1.x] + EBc[rd1.x]) * 0.125f;
            sacc[ni][3] = (sacc[ni][3] + qe1[rd1.y] + EBc[rd1.y]) * 0.125f;
            mx0 = fmaxf(mx0, fmaxf(sacc[ni][0], sacc[ni][1]));
            mx1 = fmaxf(mx1, fmaxf(sacc[ni][2], sacc[ni][3]));
        }
        mx0 = fmaxf(mx0, __shfl_xor_sync(0xffffffffu, mx0, 1));
        mx0 = fmaxf(mx0, __shfl_xor_sync(0xffffffffu, mx0, 2));
        mx1 = fmaxf(mx1, __shfl_xor_sync(0xffffffffu, mx1, 1));
        mx1 = fmaxf(mx1, __shfl_xor_sync(0xffffffffu, mx1, 2));

        float nm0 = fmaxf(m0r, mx0), nm1 = fmaxf(m1r, mx1);
        float f0 = __expf(m0r - nm0), f1 = __expf(m1r - nm1);
        m0r = nm0; m1r = nm1;
        float s0 = 0.f, s1 = 0.f;
        #pragma unroll
        for (int ni = 0; ni < 16; ni++) {
            sacc[ni][0] = __expf(sacc[ni][0] - nm0); s0 += sacc[ni][0];
            sacc[ni][1] = __expf(sacc[ni][1] - nm0); s0 += sacc[ni][1];
            sacc[ni][2] = __expf(sacc[ni][2] - nm1); s1 += sacc[ni][2];
            sacc[ni][3] = __expf(sacc[ni][3] - nm1); s1 += sacc[ni][3];
        }
        s0 += __shfl_xor_sync(0xffffffffu, s0, 1);
        s0 += __shfl_xor_sync(0xffffffffu, s0, 2);
        s1 += __shfl_xor_sync(0xffffffffu, s1, 1);
        s1 += __shfl_xor_sync(0xffffffffu, s1, 2);
        l0 = l0 * f0 + s0;
        l1 = l1 * f1 + s1;
        #pragma unroll
        for (int nj = 0; nj < 8; nj++) {
            ctx[nj][0] *= f0; ctx[nj][1] *= f0;
            ctx[nj][2] *= f1; ctx[nj][3] *= f1;
        }

        #pragma unroll
        for (int kc = 0; kc < 8; kc++) {
            uint32_t a[4];
            a[0] = pack2(sacc[2*kc    ][0], sacc[2*kc    ][1]);
            a[1] = pack2(sacc[2*kc    ][2], sacc[2*kc    ][3]);
            a[2] = pack2(sacc[2*kc + 1][0], sacc[2*kc + 1][1]);
            a[3] = pack2(sacc[2*kc + 1][2], sacc[2*kc + 1][3]);
            #pragma unroll
            for (int p = 0; p < 4; p++) {
                uint32_t t4[4];
                ldm4(t4, sV + ((p*16 + brow)*136 + kc*16 + bcol)*2);
                uint32_t b0[2] = {t4[0], t4[1]};
                uint32_t b1[2] = {t4[2], t4[3]};
                mma16(ctx[2*p    ], a, b0);
                mma16(ctx[2*p + 1], a, b1);
            }
        }

        __syncthreads();
        if (kt + 2 < 8) {
            const int nk = kt + 2, buf = kt & 1;
            #pragma unroll
            for (int i = 0; i < 8; i++) {
                int idx = i*128 + tid; int r = idx >> 3, c = (idx & 7) * 8;
                cpa16(Kb + buf*9216 + r*72 + c, Kg + (size_t)(nk*128 + r)*HD + c);
            }
            #pragma unroll
            for (int i = 0; i < 8; i++) {
                int idx = i*128 + tid; int r = idx >> 4, c = (idx & 15) * 8;
                cpa16(Vb + buf*8704 + r*136 + c, Vg + (size_t)r*SEQ + nk*128 + c);
            }
            CPA_COMMIT();
        }
    }

    const float i0 = __fdividef(1.0f, l0), i1 = __fdividef(1.0f, l1);
    const int tok0 = b*SEQ + m0 + wr + gid, tok1 = tok0 + 8;
    #pragma unroll
    for (int nj = 0; nj < 8; nj++) {
        int c = h*HD + nj*8 + tig*2;
        *(__half2*)&g_ctxh[(size_t)tok0*DM + c] =
            __floats2half2_rn(ctx[nj][0]*i0, ctx[nj][1]*i0);
        *(__half2*)&g_ctxh[(size_t)tok1*DM + c] =
            __floats2half2_rn(ctx[nj][2]*i1, ctx[nj][3]*i1);
    }
}

// ---------------- small kernels ---------------------------------------------
__global__ void __launch_bounds__(256)
rid8_kernel(const int* __restrict__ rid)
{
    size_t i = (size_t)blockIdx.x * 1024 + threadIdx.x * 4;
    int4 v = *(const int4*)(rid + i);
    uchar4 o;
    o.x = (uint8_t)v.x; o.y = (uint8_t)v.y; o.z = (uint8_t)v.z; o.w = (uint8_t)v.w;
    *(uchar4*)(g_rid8 + i) = o;
}

__global__ void __launch_bounds__(256)
wtrans4_kernel(const float* __restrict__ Wq, const float* __restrict__ Wk,
               const float* __restrict__ Wv, const float* __restrict__ Wo)
{
    const float* S = (blockIdx.z == 0) ? Wq : (blockIdx.z == 1) ? Wk
                   : (blockIdx.z == 2) ? Wv : Wo;
    __half* D = g_wT + (size_t)blockIdx.z * DM * DM;
    __shared__ float t[32][33];
    const int k0 = blockIdx.y * 32, n0 = blockIdx.x * 32;
    const int tx = threadIdx.x & 31, ty = threadIdx.x >> 5;
    #pragma unroll
    for (int i = 0; i < 32; i += 8)
        t[ty + i][tx] = S[(size_t)(k0 + ty + i) * DM + n0 + tx];
    __syncthreads();
    #pragma unroll
    for (int i = 0; i < 32; i += 8)
        D[(size_t)(n0 + ty + i) * DM + k0 + tx] = __float2half(t[tx][ty + i]);
}

__global__ void __launch_bounds__(256)
wtrans_kernel(const float* __restrict__ S, __half* __restrict__ D, int K, int N)
{
    __shared__ float t[32][33];
    const int k0 = blockIdx.y * 32, n0 = blockIdx.x * 32;
    const int tx = threadIdx.x & 31, ty = threadIdx.x >> 5;
    #pragma unroll
    for (int i = 0; i < 32; i += 8)
        t[ty + i][tx] = S[(size_t)(k0 + ty + i) * N + n0 + tx];
    __syncthreads();
    #pragma unroll
    for (int i = 0; i < 32; i += 8)
        D[(size_t)(n0 + ty + i) * K + k0 + tx] = __float2half(t[tx][ty + i]);
}

template<int HOUT>
__global__ void __launch_bounds__(256)
ln_kernel(const float* __restrict__ X, const float* __restrict__ g,
          const float* __restrict__ bb, float* __restrict__ Y, __half* __restrict__ Yh)
{
    __shared__ float red[16];
    const int tid = threadIdx.x;
    const size_t off = (size_t)blockIdx.x << 10;
    float4 v = ((const float4*)(X + off))[tid];

    float s  = v.x + v.y + v.z + v.w;
    float s2 = v.x*v.x + v.y*v.y + v.z*v.z + v.w*v.w;
    s = warpSum(s); s2 = warpSum(s2);
    if ((tid & 31) == 0) { red[tid >> 5] = s; red[8 + (tid >> 5)] = s2; }
    __syncthreads();
    float S = 0.f, S2 = 0.f;
    #pragma unroll
    for (int i = 0; i < 8; i++) { S += red[i]; S2 += red[8 + i]; }
    float mu  = S * (1.0f / 1024.0f);
    float var = S2 * (1.0f / 1024.0f) - mu * mu;
    float rs  = rsqrtf(var + 1e-6f);

    float4 gv = ((const float4*)g)[tid];
    float4 bv = ((const float4*)bb)[tid];
    float4 o;
    o.x = (v.x - mu) * rs * gv.x + bv.x;
    o.y = (v.y - mu) * rs * gv.y + bv.y;
    o.z = (v.z - mu) * rs * gv.z + bv.z;
    o.w = (v.w - mu) * rs * gv.w + bv.w;
    ((float4*)(Y + off))[tid] = o;
    if (HOUT) {
        __half2* ph = (__half2*)(Yh + off);
        ph[tid*2+0] = __floats2half2_rn(o.x, o.y);
        ph[tid*2+1] = __floats2half2_rn(o.z, o.w);
    }
}

__global__ void __launch_bounds__(256)
f2h_kernel(const float* __restrict__ S, __half* __restrict__ D)
{
    size_t i = (size_t)blockIdx.x * 1024 + threadIdx.x * 4;
    float4 v = *(const float4*)(S + i);
    ((__half2*)(D + i))[0] = __floats2half2_rn(v.x, v.y);
    ((__half2*)(D + i))[1] = __floats2half2_rn(v.z, v.w);
}

// ---------------- launch -----------------------------------------------------
extern "C" void kernel_launch(void* const* d_in, const int* in_sizes, int n_in,
                              void* d_out, int out_size)
{
    const float* x   = (const float*)d_in[0];
    const int*   rid = (const int*)  d_in[1];
    const float* Wq  = (const float*)d_in[2];
    const float* bq  = (const float*)d_in[3];
    const float* Wk  = (const float*)d_in[4];
    const float* bk  = (const float*)d_in[5];
    const float* Wv  = (const float*)d_in[6];
    const float* bv  = (const float*)d_in[7];
    const float* Wo  = (const float*)d_in[8];
    const float* bo  = (const float*)d_in[9];
    const float* Ek  = (const float*)d_in[10];
    const float* Eb  = (const float*)d_in[11];
    const float* g1  = (const float*)d_in[12];
    const float* b1  = (const float*)d_in[13];
    const float* g2  = (const float*)d_in[14];
    const float* b2  = (const float*)d_in[15];
    const float* W1  = (const float*)d_in[16];
    const float* bf1 = (const float*)d_in[17];
    const float* W2  = (const float*)d_in[18];
    const float* bf2 = (const float*)d_in[19];
    float* out = (float*)d_out;

    __half *p_wT, *p_xh, *p_ctxh, *p_ffinh, *p_h1h;
    float  *p_t, *p_ffin;
    cudaGetSymbolAddress((void**)&p_wT,    g_wT);
    cudaGetSymbolAddress((void**)&p_xh,    g_xh);
    cudaGetSymbolAddress((void**)&p_ctxh,  g_ctxh);
    cudaGetSymbolAddress((void**)&p_ffinh, g_ffinh);
    cudaGetSymbolAddress((void**)&p_h1h,   g_h1h);
    cudaGetSymbolAddress((void**)&p_t,     g_t);
    cudaGetSymbolAddress((void**)&p_ffin,  g_ffin);

    __half* WoT = p_wT + (size_t)3*DM*DM;
    __half* W1T = p_wT + (size_t)4*DM*DM;            // [FFN][DM]
    __half* W2T = p_wT + (size_t)4*DM*DM + DM*FFN_D; // [DM][FFN]

    static int smem_set = 0;
    if (!smem_set) {
        cudaFuncSetAttribute(attn_flash, cudaFuncAttributeMaxDynamicSharedMemorySize, FA_SMEM);
        cudaFuncSetAttribute(proj_h,     cudaFuncAttributeMaxDynamicSharedMemorySize, G_SMEM);
        cudaFuncSetAttribute(hgemm<2>,   cudaFuncAttributeMaxDynamicSharedMemorySize, G_SMEM);
        cudaFuncSetAttribute(hgemm<3>,   cudaFuncAttributeMaxDynamicSharedMemorySize, G_SMEM);
        smem_set = 1;
    }

    const dim3 blk(256);

    // 0. operand conversion
    rid8_kernel<<<SEQ*SEQ/1024, blk>>>(rid);
    wtrans4_kernel<<<dim3(DM/32, DM/32, 4), blk>>>(Wq, Wk, Wv, Wo);
    wtrans_kernel<<<dim3(FFN_D/32, DM/32),  blk>>>(W1, W1T, DM, FFN_D);
    wtrans_kernel<<<dim3(DM/32,  FFN_D/32), blk>>>(W2, W2T, FFN_D, DM);
    f2h_kernel<<<ROWS*DM/1024, blk>>>(x, p_xh);

    // 1. QKV projections
    proj_h<<<dim3(DM/128, ROWS/128, 3), blk, G_SMEM>>>(p_xh, bq, bk, bv);

    // 2. qE = Q @ Ek^T
    qe_kernel<<<BHN * SEQ / 64, blk>>>(Ek);

    // 3-5. flash attention
    attn_flash<<<dim3(SEQ/64, BHN), dim3(128), FA_SMEM>>>(Eb);

    // 6. t = x + ctx @ Wo + bo
    hgemm<3><<<dim3(DM/128, ROWS/128), blk, G_SMEM>>>(p_ctxh, WoT, bo, x, p_t, DM, DM);

    // 7. ff_in = LN1(t)
    ln_kernel<1><<<ROWS, blk>>>(p_t, g1, b1, p_ffin, p_ffinh);

    // 8. h1 = relu(ff_in @ W1 + bf1) -> half
    hgemm<2><<<dim3(FFN_D/128, ROWS/128), blk, G_SMEM>>>(p_ffinh, W1T, bf1, nullptr, p_h1h, DM, FFN_D);

    // 9. t = ff_in + h1 @ W2 + bf2
    hgemm<3><<<dim3(DM/128, ROWS/128), blk, G_SMEM>>>(p_h1h, W2T, bf2, p_ffin, p_t, FFN_D, DM);

    // 10. out = LN2(t)
    ln_kernel<0><<<ROWS, blk>>>(p_t, g2, b2, out, nullptr);
}